// round 1
// baseline (speedup 1.0000x reference)
#include <cuda_runtime.h>
#include <cuda_bf16.h>
#include <math.h>

// Problem constants (fixed shapes from reference)
#define BATCH 2
#define SEQ   2048
#define DIM   1024
#define HEADS 16
#define HD    64
#define WIN   64
#define MTOT  (BATCH*SEQ)          // 4096 rows

// Scratch (device globals; allocation-free contract)
__device__ float g_q[MTOT * DIM];
__device__ float g_k[MTOT * DIM];
__device__ float g_v[MTOT * DIM];
__device__ float g_att[MTOT * DIM];
__device__ float g_kmean[BATCH * HEADS * HD];

// ---------------------------------------------------------------------------
// SGEMM: C[M,N] = A[M,K] @ B[N,K]^T   (both row-major, K contiguous)
// BM=128, BN=64, BK=16, 256 threads, 8x4 register tile per thread.
// ---------------------------------------------------------------------------
#define BM 128
#define BN 64
#define BK 16

__device__ __forceinline__ void gemm_body(const float* __restrict__ A,
                                          const float* __restrict__ Bm,
                                          float* __restrict__ C,
                                          int M, int N, int K) {
    __shared__ float As[BK][BM];
    __shared__ float Bs[BK][BN];
    const int tid = threadIdx.x;
    const int tx = tid & 15;        // N direction (4 cols each)
    const int ty = tid >> 4;        // M direction (8 rows each)
    const int rowA = blockIdx.y * BM;
    const int colC = blockIdx.x * BN;

    float acc[8][4];
#pragma unroll
    for (int i = 0; i < 8; i++)
#pragma unroll
        for (int j = 0; j < 4; j++) acc[i][j] = 0.f;

    for (int k0 = 0; k0 < K; k0 += BK) {
        // Load A tile: 128x16 floats = 512 float4, 2 per thread
#pragma unroll
        for (int it = 0; it < 2; it++) {
            int idx = tid + 256 * it;
            int r  = idx >> 2;
            int c4 = (idx & 3) * 4;
            float4 a = *(const float4*)(A + (size_t)(rowA + r) * K + k0 + c4);
            As[c4 + 0][r] = a.x; As[c4 + 1][r] = a.y;
            As[c4 + 2][r] = a.z; As[c4 + 3][r] = a.w;
        }
        // Load B tile: 64x16 floats = 256 float4, 1 per thread
        {
            int r  = tid >> 2;
            int c4 = (tid & 3) * 4;
            float4 b = *(const float4*)(Bm + (size_t)(colC + r) * K + k0 + c4);
            Bs[c4 + 0][r] = b.x; Bs[c4 + 1][r] = b.y;
            Bs[c4 + 2][r] = b.z; Bs[c4 + 3][r] = b.w;
        }
        __syncthreads();
#pragma unroll
        for (int k = 0; k < BK; k++) {
            float ra[8], rb[4];
#pragma unroll
            for (int i = 0; i < 8; i++) ra[i] = As[k][ty * 8 + i];
#pragma unroll
            for (int j = 0; j < 4; j++) rb[j] = Bs[k][tx * 4 + j];
#pragma unroll
            for (int i = 0; i < 8; i++)
#pragma unroll
                for (int j = 0; j < 4; j++)
                    acc[i][j] = fmaf(ra[i], rb[j], acc[i][j]);
        }
        __syncthreads();
    }
#pragma unroll
    for (int i = 0; i < 8; i++) {
        float4 o = make_float4(acc[i][0], acc[i][1], acc[i][2], acc[i][3]);
        *(float4*)(C + (size_t)(rowA + ty * 8 + i) * N + colC + tx * 4) = o;
    }
}

// QKV projections in one launch (grid.z selects the weight/output)
__global__ void __launch_bounds__(256)
qkv_gemm_kernel(const float* __restrict__ x,
                const float* __restrict__ Wq,
                const float* __restrict__ Wk,
                const float* __restrict__ Wv) {
    const float* W = (blockIdx.z == 0) ? Wq : (blockIdx.z == 1) ? Wk : Wv;
    float* C = (blockIdx.z == 0) ? g_q : (blockIdx.z == 1) ? g_k : g_v;
    gemm_body(x, W, C, MTOT, DIM, DIM);
}

__global__ void __launch_bounds__(256)
out_gemm_kernel(const float* __restrict__ Wo, float* __restrict__ out) {
    gemm_body(g_att, Wo, out, MTOT, DIM, DIM);
}

// ---------------------------------------------------------------------------
// k_mean[b,h,d] = mean_l k[b,h,l,d]   (exploits linearity of score mean)
// ---------------------------------------------------------------------------
__global__ void kmean_kernel() {
    int bh = blockIdx.x;              // 0..B*H-1
    int b = bh / HEADS, h = bh % HEADS;
    int d = threadIdx.x;              // 64 threads
    const float* base = g_k + (size_t)b * SEQ * DIM + h * HD + d;
    float s = 0.f;
    for (int l = 0; l < SEQ; l++) s += base[(size_t)l * DIM];
    g_kmean[bh * HD + d] = s * (1.f / (float)SEQ);
}

// ---------------------------------------------------------------------------
// Fused windowed attention with Reynolds rules.
// Grid: (SEQ/64 tiles, B*H). 256 threads = 8 warps; warp w handles 8 queries.
// smem: K tile 128x64, V tile 128x64, Q tile 64x64, kmean 64, sbuf 8x64.
// ---------------------------------------------------------------------------
#define ATTN_SMEM ((128*64 + 128*64 + 64*64 + 64 + 8*64) * 4)

__global__ void __launch_bounds__(256)
attn_kernel(const float* __restrict__ gsep,
            const float* __restrict__ galign,
            const float* __restrict__ gcoh) {
    extern __shared__ float sm[];
    float* Ks   = sm;                 // 128*64
    float* Vs   = Ks + 128 * 64;      // 128*64
    float* Qs   = Vs + 128 * 64;      // 64*64
    float* km   = Qs + 64 * 64;       // 64
    float* sbuf = km + 64;            // 8*64

    const int t  = blockIdx.x;                 // query tile
    const int bh = blockIdx.y;
    const int b  = bh / HEADS, h = bh % HEADS;
    const int tid = threadIdx.x, lane = tid & 31, w = tid >> 5;
    const int base = t * 64 - 64;              // first (possibly negative) kv row

    const float* Kg = g_k + (size_t)b * SEQ * DIM + h * HD;
    const float* Vg = g_v + (size_t)b * SEQ * DIM + h * HD;
    const float* Qg = g_q + (size_t)b * SEQ * DIM + h * HD;

    // Stage K,V: 128 rows x 64 floats each = 2048 float4 per tensor
#pragma unroll
    for (int it = 0; it < 8; it++) {
        int idx = tid + 256 * it;
        int r = idx >> 4;
        int c4 = (idx & 15) * 4;
        int j = base + r;
        float4 kv = make_float4(0.f, 0.f, 0.f, 0.f);
        float4 vv = make_float4(0.f, 0.f, 0.f, 0.f);
        if (j >= 0) {
            kv = *(const float4*)(Kg + (size_t)j * DIM + c4);
            vv = *(const float4*)(Vg + (size_t)j * DIM + c4);
        }
        *(float4*)(Ks + r * 64 + c4) = kv;
        *(float4*)(Vs + r * 64 + c4) = vv;
    }
    // Stage Q: 64 rows
#pragma unroll
    for (int it = 0; it < 4; it++) {
        int idx = tid + 256 * it;
        int r = idx >> 4;
        int c4 = (idx & 15) * 4;
        *(float4*)(Qs + r * 64 + c4) =
            *(const float4*)(Qg + (size_t)(t * 64 + r) * DIM + c4);
    }
    if (tid < 64) km[tid] = g_kmean[bh * HD + tid];
    __syncthreads();

    const float sep = *gsep, alg = *galign, coh = *gcoh;

#pragma unroll 1
    for (int qq = 0; qq < 8; qq++) {
        const int qi = w * 8 + qq;         // local query
        const int i  = t * 64 + qi;        // global query
        const float q0 = Qs[qi * 64 + lane];
        const float q1 = Qs[qi * 64 + 32 + lane];

        // score mean over full kv dim == q . k_mean / scale (linearity)
        float pm = q0 * km[lane] + q1 * km[lane + 32];
#pragma unroll
        for (int o = 16; o; o >>= 1) pm += __shfl_xor_sync(~0u, pm, o);
        const float mi = pm * 0.125f;

        const int jlo = (i - 63 > 0) ? (i - 63) : 0;
        const int cnt = i - jlo + 1;       // 1..64 valid kv
        const int r0  = jlo - base;        // smem row of first valid kv

        float mx = -1e30f;
        for (int n = 0; n < cnt; n++) {
            const int r = r0 + n;
            float s = q0 * Ks[r * 64 + lane] + q1 * Ks[r * 64 + 32 + lane];
#pragma unroll
            for (int o = 16; o; o >>= 1) s += __shfl_xor_sync(~0u, s, o);
            s *= 0.125f;
            const float sim = 1.f / (1.f + expf(-s));
            const float s2 = s + alg * s - sep * sim * sim - coh * fabsf(s - mi);
            mx = fmaxf(mx, s2);
            if (lane == (n & 31)) sbuf[w * 64 + n] = s2;   // all lanes hold s2
        }

        float denom = 0.f, o0 = 0.f, o1 = 0.f;
        for (int n = 0; n < cnt; n++) {
            const int r = r0 + n;
            const float e = expf(sbuf[w * 64 + n] - mx);
            denom += e;
            o0 = fmaf(e, Vs[r * 64 + lane], o0);
            o1 = fmaf(e, Vs[r * 64 + 32 + lane], o1);
        }
        const float inv = 1.f / denom;
        float* outp = g_att + ((size_t)b * SEQ + i) * DIM + h * HD;
        outp[lane]      = o0 * inv;
        outp[lane + 32] = o1 * inv;
    }
}

// ---------------------------------------------------------------------------
extern "C" void kernel_launch(void* const* d_in, const int* in_sizes, int n_in,
                              void* d_out, int out_size) {
    const float* x     = (const float*)d_in[0];
    const float* Wq    = (const float*)d_in[1];
    const float* Wk    = (const float*)d_in[2];
    const float* Wv    = (const float*)d_in[3];
    const float* Wo    = (const float*)d_in[4];
    const float* gsep  = (const float*)d_in[5];
    const float* galn  = (const float*)d_in[6];
    const float* gcoh  = (const float*)d_in[7];
    float* out = (float*)d_out;

    cudaFuncSetAttribute(attn_kernel,
                         cudaFuncAttributeMaxDynamicSharedMemorySize, ATTN_SMEM);

    dim3 gqkv(DIM / BN, MTOT / BM, 3);
    qkv_gemm_kernel<<<gqkv, 256>>>(x, Wq, Wk, Wv);

    kmean_kernel<<<BATCH * HEADS, HD>>>();

    dim3 gatt(SEQ / 64, BATCH * HEADS);
    attn_kernel<<<gatt, 256, ATTN_SMEM>>>(gsep, galn, gcoh);

    dim3 gout(DIM / BN, MTOT / BM);
    out_gemm_kernel<<<gout, 256>>>(Wo, out);
}

// round 4
// speedup vs baseline: 1.5719x; 1.5719x over previous
#include <cuda_runtime.h>
#include <cuda_bf16.h>
#include <math.h>
#include <stdint.h>

// Problem constants
#define BATCH 2
#define SEQ   2048
#define DIM   1024
#define HEADS 16
#define HD    64
#define MTOT  (BATCH*SEQ)      // 4096
#define GK3   (3*DIM)          // 3-term split K: 3072

// GEMM tiling
#define TM 128
#define TN 128
#define BK 32                  // bf16 elems per chunk
#define NCHUNK (GK3/BK)        // 96
#define STAGES 3
#define RS (BK+8)              // smem row stride in bf16 (80 B, conflict-free)
#define STAGE_ELEMS (2*128*RS)
#define GEMM_SMEM (STAGES*STAGE_ELEMS*2)   // 61440 B

// Scratch (device globals; allocation-free contract)
__device__ __align__(256) float g_q[MTOT*DIM];
__device__ __align__(256) float g_k[MTOT*DIM];
__device__ __align__(256) float g_v[MTOT*DIM];
__device__ __align__(256) float g_kmean[BATCH*HEADS*HD];
// A-side (activations): [hi | lo | hi];  B-side (weights): [hi | hi | lo]
__device__ __align__(256) __nv_bfloat16 g_x3[(size_t)MTOT*GK3];
__device__ __align__(256) __nv_bfloat16 g_att3[(size_t)MTOT*GK3];
__device__ __align__(256) __nv_bfloat16 g_wq3[(size_t)DIM*GK3];
__device__ __align__(256) __nv_bfloat16 g_wk3[(size_t)DIM*GK3];
__device__ __align__(256) __nv_bfloat16 g_wv3[(size_t)DIM*GK3];
__device__ __align__(256) __nv_bfloat16 g_wo3[(size_t)DIM*GK3];

// ---------------------------------------------------------------------------
// Non-arch-variant PTX helpers (compute_103-safe)
// ---------------------------------------------------------------------------
__device__ __forceinline__ uint32_t smem_u32(const void* p) {
    uint32_t a;
    asm("{ .reg .u64 t; cvta.to.shared.u64 t, %1; cvt.u32.u64 %0, t; }"
        : "=r"(a) : "l"(p));
    return a;
}
__device__ __forceinline__ void cp16(uint32_t dst, const void* src) {
    asm volatile("cp.async.cg.shared.global [%0], [%1], 16;"
                 :: "r"(dst), "l"(src));
}
#define CP_COMMIT() asm volatile("cp.async.commit_group;" ::: "memory")
#define CP_WAIT1()  asm volatile("cp.async.wait_group 1;" ::: "memory")

__device__ __forceinline__ void mma_bf16(float* c, const uint32_t* a,
                                         const uint32_t* b) {
    asm volatile(
        "mma.sync.aligned.m16n8k16.row.col.f32.bf16.bf16.f32 "
        "{%0,%1,%2,%3}, {%4,%5,%6,%7}, {%8,%9}, {%0,%1,%2,%3};"
        : "+f"(c[0]), "+f"(c[1]), "+f"(c[2]), "+f"(c[3])
        : "r"(a[0]), "r"(a[1]), "r"(a[2]), "r"(a[3]), "r"(b[0]), "r"(b[1]));
}

// ---------------------------------------------------------------------------
// 3-term split conversion. A-side: [hi|lo|hi], B-side: [hi|hi|lo].
// ---------------------------------------------------------------------------
__global__ __launch_bounds__(256)
void convert_kernel(const float* __restrict__ x,  const float* __restrict__ wq,
                    const float* __restrict__ wk, const float* __restrict__ wv,
                    const float* __restrict__ wo) {
    int rid = blockIdx.x;
    const float* src; __nv_bfloat16* dst; int row; int aside;
    if      (rid < 4096) { src = x;  dst = g_x3;  row = rid;        aside = 1; }
    else if (rid < 5120) { src = wq; dst = g_wq3; row = rid - 4096; aside = 0; }
    else if (rid < 6144) { src = wk; dst = g_wk3; row = rid - 5120; aside = 0; }
    else if (rid < 7168) { src = wv; dst = g_wv3; row = rid - 6144; aside = 0; }
    else                 { src = wo; dst = g_wo3; row = rid - 7168; aside = 0; }
    int c = threadIdx.x * 4;
    float4 f = *(const float4*)(src + (size_t)row * DIM + c);
    float fv[4] = {f.x, f.y, f.z, f.w};
    union { __nv_bfloat16 b[4]; uint2 u; } H, L;
#pragma unroll
    for (int i = 0; i < 4; i++) {
        __nv_bfloat16 h = __float2bfloat16(fv[i]);
        H.b[i] = h;
        L.b[i] = __float2bfloat16(fv[i] - __bfloat162float(h));
    }
    __nv_bfloat16* r0 = dst + (size_t)row * GK3 + c;
    if (aside) {   // [hi | lo | hi]
        *(uint2*)(r0)            = H.u;
        *(uint2*)(r0 + DIM)      = L.u;
        *(uint2*)(r0 + 2*DIM)    = H.u;
    } else {       // [hi | hi | lo]
        *(uint2*)(r0)            = H.u;
        *(uint2*)(r0 + DIM)      = H.u;
        *(uint2*)(r0 + 2*DIM)    = L.u;
    }
}

// ---------------------------------------------------------------------------
// HMMA GEMM: C[4096,1024] = A3[4096,3072]bf16 @ B3[1024,3072]bf16^T (fp32 acc)
// CTA 128x128, BK=32, 3-stage cp.async. 8 warps (2x4), warp tile 64x32.
// ---------------------------------------------------------------------------
__device__ __forceinline__ void load_stage(uint32_t stg,
                                           const __nv_bfloat16* __restrict__ Ag,
                                           const __nv_bfloat16* __restrict__ Bg,
                                           int chunk, int tid) {
    const __nv_bfloat16* Ac = Ag + chunk * BK;
    const __nv_bfloat16* Bc = Bg + chunk * BK;
#pragma unroll
    for (int i = 0; i < 2; i++) {
        int seg = tid + 256 * i;
        int r = seg >> 2, cs = seg & 3;
        cp16(stg + r * (RS*2) + cs * 16,
             (const char*)(Ac + (size_t)r * GK3) + cs * 16);
    }
#pragma unroll
    for (int i = 0; i < 2; i++) {
        int seg = tid + 256 * i;
        int r = seg >> 2, cs = seg & 3;
        cp16(stg + 128*(RS*2) + r * (RS*2) + cs * 16,
             (const char*)(Bc + (size_t)r * GK3) + cs * 16);
    }
}

__device__ __forceinline__ void mma_gemm(const __nv_bfloat16* __restrict__ A3,
                                         const __nv_bfloat16* __restrict__ B3,
                                         float* __restrict__ C) {
    extern __shared__ __align__(128) __nv_bfloat16 smem[];
    const uint32_t sb = smem_u32(smem);
    const int tid = threadIdx.x;
    const int lane = tid & 31, w = tid >> 5;
    const int wm = w >> 2, wn = w & 3;          // 2 x 4 warp grid
    const int g = lane >> 2, tg = lane & 3;
    const int rowC = blockIdx.y * TM;
    const int colC = blockIdx.x * TN;
    const __nv_bfloat16* Ag = A3 + (size_t)rowC * GK3;
    const __nv_bfloat16* Bg = B3 + (size_t)colC * GK3;

    float acc[4][4][4];
#pragma unroll
    for (int mt = 0; mt < 4; mt++)
#pragma unroll
        for (int nt = 0; nt < 4; nt++)
#pragma unroll
            for (int i = 0; i < 4; i++) acc[mt][nt][i] = 0.f;

#pragma unroll
    for (int s = 0; s < STAGES - 1; s++) {
        load_stage(sb + s * (STAGE_ELEMS*2), Ag, Bg, s, tid);
        CP_COMMIT();
    }

    for (int c = 0; c < NCHUNK; c++) {
        CP_WAIT1();
        __syncthreads();
        const int st = c % STAGES;
        const __nv_bfloat16* As = smem + st * STAGE_ELEMS;
        const __nv_bfloat16* Bs = As + 128 * RS;
#pragma unroll
        for (int ks = 0; ks < 2; ks++) {
            const int k0 = ks * 16 + tg * 2;
            uint32_t a[4][4], b[4][2];
#pragma unroll
            for (int mt = 0; mt < 4; mt++) {
                const int r = wm * 64 + mt * 16 + g;
                a[mt][0] = *(const uint32_t*)&As[r * RS + k0];
                a[mt][1] = *(const uint32_t*)&As[(r + 8) * RS + k0];
                a[mt][2] = *(const uint32_t*)&As[r * RS + k0 + 8];
                a[mt][3] = *(const uint32_t*)&As[(r + 8) * RS + k0 + 8];
            }
#pragma unroll
            for (int nt = 0; nt < 4; nt++) {
                const int n = wn * 32 + nt * 8 + g;
                b[nt][0] = *(const uint32_t*)&Bs[n * RS + k0];
                b[nt][1] = *(const uint32_t*)&Bs[n * RS + k0 + 8];
            }
#pragma unroll
            for (int mt = 0; mt < 4; mt++)
#pragma unroll
                for (int nt = 0; nt < 4; nt++)
                    mma_bf16(acc[mt][nt], a[mt], b[nt]);
        }
        __syncthreads();
        if (c + STAGES - 1 < NCHUNK)
            load_stage(sb + ((c + STAGES - 1) % STAGES) * (STAGE_ELEMS*2),
                       Ag, Bg, c + STAGES - 1, tid);
        CP_COMMIT();
    }

    // Epilogue: direct fp32 stores
#pragma unroll
    for (int mt = 0; mt < 4; mt++) {
        const int row = rowC + wm * 64 + mt * 16 + g;
#pragma unroll
        for (int nt = 0; nt < 4; nt++) {
            const int col = colC + wn * 32 + nt * 8 + tg * 2;
            *(float2*)(C + (size_t)row * DIM + col) =
                make_float2(acc[mt][nt][0], acc[mt][nt][1]);
            *(float2*)(C + (size_t)(row + 8) * DIM + col) =
                make_float2(acc[mt][nt][2], acc[mt][nt][3]);
        }
    }
}

__global__ __launch_bounds__(256)
void qkv_mma_kernel() {
    const __nv_bfloat16* W = (blockIdx.z == 0) ? g_wq3
                           : (blockIdx.z == 1) ? g_wk3 : g_wv3;
    float* C = (blockIdx.z == 0) ? g_q : (blockIdx.z == 1) ? g_k : g_v;
    mma_gemm(g_x3, W, C);
}

__global__ __launch_bounds__(256)
void out_mma_kernel(float* __restrict__ out) {
    mma_gemm(g_att3, g_wo3, out);
}

// ---------------------------------------------------------------------------
// k_mean[b,h,d] = mean_l k[b,h,l,d]  (score-mean linearity)
// ---------------------------------------------------------------------------
__global__ __launch_bounds__(256)
void kmean_kernel() {
    __shared__ float red[256];
    const int bh = blockIdx.x;
    const int b = bh >> 4, h = bh & 15;
    const int d = threadIdx.x & 63, p = threadIdx.x >> 6;
    const float* base = g_k + (size_t)b * SEQ * DIM + h * HD + d;
    float s = 0.f;
    for (int l = p; l < SEQ; l += 4) s += base[(size_t)l * DIM];
    red[threadIdx.x] = s;
    __syncthreads();
    if (threadIdx.x < 64) {
        float t = red[d] + red[64 + d] + red[128 + d] + red[192 + d];
        g_kmean[bh * HD + d] = t * (1.f / (float)SEQ);
    }
}

// ---------------------------------------------------------------------------
// Fused windowed attention with Reynolds rules. Output in A-side 3-term split.
// ---------------------------------------------------------------------------
#define ATTN_SMEM ((128*64 + 128*64 + 64*64 + 64 + 8*64) * 4)

__global__ void __launch_bounds__(256)
attn_kernel(const float* __restrict__ gsep,
            const float* __restrict__ galign,
            const float* __restrict__ gcoh) {
    extern __shared__ float sm[];
    float* Ks   = sm;                 // 128*64
    float* Vs   = Ks + 128 * 64;      // 128*64
    float* Qs   = Vs + 128 * 64;      // 64*64
    float* km   = Qs + 64 * 64;       // 64
    float* sbuf = km + 64;            // 8*64

    const int t  = blockIdx.x;
    const int bh = blockIdx.y;
    const int b  = bh / HEADS, h = bh % HEADS;
    const int tid = threadIdx.x, lane = tid & 31, w = tid >> 5;
    const int base = t * 64 - 64;

    const float* Kg = g_k + (size_t)b * SEQ * DIM + h * HD;
    const float* Vg = g_v + (size_t)b * SEQ * DIM + h * HD;
    const float* Qg = g_q + (size_t)b * SEQ * DIM + h * HD;

#pragma unroll
    for (int it = 0; it < 8; it++) {
        int idx = tid + 256 * it;
        int r = idx >> 4;
        int c4 = (idx & 15) * 4;
        int j = base + r;
        float4 kv = make_float4(0.f, 0.f, 0.f, 0.f);
        float4 vv = make_float4(0.f, 0.f, 0.f, 0.f);
        if (j >= 0) {
            kv = *(const float4*)(Kg + (size_t)j * DIM + c4);
            vv = *(const float4*)(Vg + (size_t)j * DIM + c4);
        }
        *(float4*)(Ks + r * 64 + c4) = kv;
        *(float4*)(Vs + r * 64 + c4) = vv;
    }
#pragma unroll
    for (int it = 0; it < 4; it++) {
        int idx = tid + 256 * it;
        int r = idx >> 4;
        int c4 = (idx & 15) * 4;
        *(float4*)(Qs + r * 64 + c4) =
            *(const float4*)(Qg + (size_t)(t * 64 + r) * DIM + c4);
    }
    if (tid < 64) km[tid] = g_kmean[bh * HD + tid];
    __syncthreads();

    const float sep = *gsep, alg = *galign, coh = *gcoh;

#pragma unroll 1
    for (int qq = 0; qq < 8; qq++) {
        const int qi = w * 8 + qq;
        const int i  = t * 64 + qi;
        const float q0 = Qs[qi * 64 + lane];
        const float q1 = Qs[qi * 64 + 32 + lane];

        float pm = q0 * km[lane] + q1 * km[lane + 32];
#pragma unroll
        for (int o = 16; o; o >>= 1) pm += __shfl_xor_sync(~0u, pm, o);
        const float mi = pm * 0.125f;

        const int jlo = (i - 63 > 0) ? (i - 63) : 0;
        const int cnt = i - jlo + 1;
        const int r0  = jlo - base;

        float mx = -1e30f;
        for (int n = 0; n < cnt; n++) {
            const int r = r0 + n;
            float s = q0 * Ks[r * 64 + lane] + q1 * Ks[r * 64 + 32 + lane];
#pragma unroll
            for (int o = 16; o; o >>= 1) s += __shfl_xor_sync(~0u, s, o);
            s *= 0.125f;
            const float sim = 1.f / (1.f + expf(-s));
            const float s2 = s + alg * s - sep * sim * sim - coh * fabsf(s - mi);
            mx = fmaxf(mx, s2);
            if (lane == (n & 31)) sbuf[w * 64 + n] = s2;
        }

        float denom = 0.f, o0 = 0.f, o1 = 0.f;
        for (int n = 0; n < cnt; n++) {
            const int r = r0 + n;
            const float e = expf(sbuf[w * 64 + n] - mx);
            denom += e;
            o0 = fmaf(e, Vs[r * 64 + lane], o0);
            o1 = fmaf(e, Vs[r * 64 + 32 + lane], o1);
        }
        const float inv = 1.f / denom;
        const float o0v = o0 * inv, o1v = o1 * inv;
        __nv_bfloat16 h0 = __float2bfloat16(o0v);
        __nv_bfloat16 l0 = __float2bfloat16(o0v - __bfloat162float(h0));
        __nv_bfloat16 h1 = __float2bfloat16(o1v);
        __nv_bfloat16 l1 = __float2bfloat16(o1v - __bfloat162float(h1));
        const size_t rb = ((size_t)b * SEQ + i) * GK3 + h * HD;
        // A-side: [hi | lo | hi]
        g_att3[rb + lane]              = h0;
        g_att3[rb + lane + 32]         = h1;
        g_att3[rb + DIM + lane]        = l0;
        g_att3[rb + DIM + lane + 32]   = l1;
        g_att3[rb + 2*DIM + lane]      = h0;
        g_att3[rb + 2*DIM + lane + 32] = h1;
    }
}

// ---------------------------------------------------------------------------
extern "C" void kernel_launch(void* const* d_in, const int* in_sizes, int n_in,
                              void* d_out, int out_size) {
    const float* x    = (const float*)d_in[0];
    const float* Wq   = (const float*)d_in[1];
    const float* Wk   = (const float*)d_in[2];
    const float* Wv   = (const float*)d_in[3];
    const float* Wo   = (const float*)d_in[4];
    const float* gsep = (const float*)d_in[5];
    const float* galn = (const float*)d_in[6];
    const float* gcoh = (const float*)d_in[7];
    float* out = (float*)d_out;

    cudaFuncSetAttribute(qkv_mma_kernel,
                         cudaFuncAttributeMaxDynamicSharedMemorySize, GEMM_SMEM);
    cudaFuncSetAttribute(out_mma_kernel,
                         cudaFuncAttributeMaxDynamicSharedMemorySize, GEMM_SMEM);
    cudaFuncSetAttribute(attn_kernel,
                         cudaFuncAttributeMaxDynamicSharedMemorySize, ATTN_SMEM);

    convert_kernel<<<8192, 256>>>(x, Wq, Wk, Wv, Wo);

    dim3 gqkv(DIM / TN, MTOT / TM, 3);
    qkv_mma_kernel<<<gqkv, 256, GEMM_SMEM>>>();

    kmean_kernel<<<BATCH * HEADS, 256>>>();

    dim3 gatt(SEQ / 64, BATCH * HEADS);
    attn_kernel<<<gatt, 256, ATTN_SMEM>>>(gsep, galn, gcoh);

    dim3 gout(DIM / TN, MTOT / TM);
    out_mma_kernel<<<gout, 256, GEMM_SMEM>>>(out);
}

// round 5
// speedup vs baseline: 2.5209x; 1.6037x over previous
#include <cuda_runtime.h>
#include <cuda_bf16.h>
#include <math.h>
#include <stdint.h>

// Problem constants
#define BATCH 2
#define SEQ   2048
#define DIM   1024
#define HEADS 16
#define HD    64
#define MTOT  (BATCH*SEQ)      // 4096
#define GK3   (3*DIM)          // 3-term split K: 3072

// GEMM tiling
#define TM 128
#define TN 128
#define BK 32
#define NCHUNK (GK3/BK)        // 96
#define STAGES 3
#define RS (BK+8)
#define STAGE_ELEMS (2*128*RS)
#define GEMM_SMEM (STAGES*STAGE_ELEMS*2)   // 61440 B

// Scratch (device globals; allocation-free contract)
__device__ __align__(256) float g_q[MTOT*DIM];
__device__ __align__(256) float g_k[MTOT*DIM];
__device__ __align__(256) float g_v[MTOT*DIM];
__device__ __align__(256) float g_kmean[BATCH*HEADS*HD];
// A-side (activations): [hi | lo | hi];  B-side (weights): [hi | hi | lo]
__device__ __align__(256) __nv_bfloat16 g_x3[(size_t)MTOT*GK3];
__device__ __align__(256) __nv_bfloat16 g_att3[(size_t)MTOT*GK3];
__device__ __align__(256) __nv_bfloat16 g_wq3[(size_t)DIM*GK3];
__device__ __align__(256) __nv_bfloat16 g_wk3[(size_t)DIM*GK3];
__device__ __align__(256) __nv_bfloat16 g_wv3[(size_t)DIM*GK3];
__device__ __align__(256) __nv_bfloat16 g_wo3[(size_t)DIM*GK3];

// ---------------------------------------------------------------------------
// Non-arch-variant PTX helpers (compute_103-safe)
// ---------------------------------------------------------------------------
__device__ __forceinline__ uint32_t smem_u32(const void* p) {
    uint32_t a;
    asm("{ .reg .u64 t; cvta.to.shared.u64 t, %1; cvt.u32.u64 %0, t; }"
        : "=r"(a) : "l"(p));
    return a;
}
__device__ __forceinline__ void cp16(uint32_t dst, const void* src) {
    asm volatile("cp.async.cg.shared.global [%0], [%1], 16;"
                 :: "r"(dst), "l"(src));
}
#define CP_COMMIT() asm volatile("cp.async.commit_group;" ::: "memory")
#define CP_WAIT1()  asm volatile("cp.async.wait_group 1;" ::: "memory")

__device__ __forceinline__ void mma_bf16(float* c, const uint32_t* a,
                                         const uint32_t* b) {
    asm volatile(
        "mma.sync.aligned.m16n8k16.row.col.f32.bf16.bf16.f32 "
        "{%0,%1,%2,%3}, {%4,%5,%6,%7}, {%8,%9}, {%0,%1,%2,%3};"
        : "+f"(c[0]), "+f"(c[1]), "+f"(c[2]), "+f"(c[3])
        : "r"(a[0]), "r"(a[1]), "r"(a[2]), "r"(a[3]), "r"(b[0]), "r"(b[1]));
}

// ---------------------------------------------------------------------------
// 3-term split conversion. A-side: [hi|lo|hi], B-side: [hi|hi|lo].
// ---------------------------------------------------------------------------
__global__ __launch_bounds__(256)
void convert_kernel(const float* __restrict__ x,  const float* __restrict__ wq,
                    const float* __restrict__ wk, const float* __restrict__ wv,
                    const float* __restrict__ wo) {
    int rid = blockIdx.x;
    const float* src; __nv_bfloat16* dst; int row; int aside;
    if      (rid < 4096) { src = x;  dst = g_x3;  row = rid;        aside = 1; }
    else if (rid < 5120) { src = wq; dst = g_wq3; row = rid - 4096; aside = 0; }
    else if (rid < 6144) { src = wk; dst = g_wk3; row = rid - 5120; aside = 0; }
    else if (rid < 7168) { src = wv; dst = g_wv3; row = rid - 6144; aside = 0; }
    else                 { src = wo; dst = g_wo3; row = rid - 7168; aside = 0; }
    int c = threadIdx.x * 4;
    float4 f = *(const float4*)(src + (size_t)row * DIM + c);
    float fv[4] = {f.x, f.y, f.z, f.w};
    union { __nv_bfloat16 b[4]; uint2 u; } H, L;
#pragma unroll
    for (int i = 0; i < 4; i++) {
        __nv_bfloat16 h = __float2bfloat16(fv[i]);
        H.b[i] = h;
        L.b[i] = __float2bfloat16(fv[i] - __bfloat162float(h));
    }
    __nv_bfloat16* r0 = dst + (size_t)row * GK3 + c;
    if (aside) {   // [hi | lo | hi]
        *(uint2*)(r0)            = H.u;
        *(uint2*)(r0 + DIM)      = L.u;
        *(uint2*)(r0 + 2*DIM)    = H.u;
    } else {       // [hi | hi | lo]
        *(uint2*)(r0)            = H.u;
        *(uint2*)(r0 + DIM)      = H.u;
        *(uint2*)(r0 + 2*DIM)    = L.u;
    }
}

// ---------------------------------------------------------------------------
// HMMA GEMM: C[4096,1024] = A3[4096,3072]bf16 @ B3[1024,3072]bf16^T (fp32 acc)
// ---------------------------------------------------------------------------
__device__ __forceinline__ void load_stage(uint32_t stg,
                                           const __nv_bfloat16* __restrict__ Ag,
                                           const __nv_bfloat16* __restrict__ Bg,
                                           int chunk, int tid) {
    const __nv_bfloat16* Ac = Ag + chunk * BK;
    const __nv_bfloat16* Bc = Bg + chunk * BK;
#pragma unroll
    for (int i = 0; i < 2; i++) {
        int seg = tid + 256 * i;
        int r = seg >> 2, cs = seg & 3;
        cp16(stg + r * (RS*2) + cs * 16,
             (const char*)(Ac + (size_t)r * GK3) + cs * 16);
    }
#pragma unroll
    for (int i = 0; i < 2; i++) {
        int seg = tid + 256 * i;
        int r = seg >> 2, cs = seg & 3;
        cp16(stg + 128*(RS*2) + r * (RS*2) + cs * 16,
             (const char*)(Bc + (size_t)r * GK3) + cs * 16);
    }
}

__device__ __forceinline__ void mma_gemm(const __nv_bfloat16* __restrict__ A3,
                                         const __nv_bfloat16* __restrict__ B3,
                                         float* __restrict__ C) {
    extern __shared__ __align__(128) __nv_bfloat16 smem[];
    const uint32_t sb = smem_u32(smem);
    const int tid = threadIdx.x;
    const int lane = tid & 31, w = tid >> 5;
    const int wm = w >> 2, wn = w & 3;
    const int g = lane >> 2, tg = lane & 3;
    const int rowC = blockIdx.y * TM;
    const int colC = blockIdx.x * TN;
    const __nv_bfloat16* Ag = A3 + (size_t)rowC * GK3;
    const __nv_bfloat16* Bg = B3 + (size_t)colC * GK3;

    float acc[4][4][4];
#pragma unroll
    for (int mt = 0; mt < 4; mt++)
#pragma unroll
        for (int nt = 0; nt < 4; nt++)
#pragma unroll
            for (int i = 0; i < 4; i++) acc[mt][nt][i] = 0.f;

#pragma unroll
    for (int s = 0; s < STAGES - 1; s++) {
        load_stage(sb + s * (STAGE_ELEMS*2), Ag, Bg, s, tid);
        CP_COMMIT();
    }

    for (int c = 0; c < NCHUNK; c++) {
        CP_WAIT1();
        __syncthreads();
        const int st = c % STAGES;
        const __nv_bfloat16* As = smem + st * STAGE_ELEMS;
        const __nv_bfloat16* Bs = As + 128 * RS;
#pragma unroll
        for (int ks = 0; ks < 2; ks++) {
            const int k0 = ks * 16 + tg * 2;
            uint32_t a[4][4], b[4][2];
#pragma unroll
            for (int mt = 0; mt < 4; mt++) {
                const int r = wm * 64 + mt * 16 + g;
                a[mt][0] = *(const uint32_t*)&As[r * RS + k0];
                a[mt][1] = *(const uint32_t*)&As[(r + 8) * RS + k0];
                a[mt][2] = *(const uint32_t*)&As[r * RS + k0 + 8];
                a[mt][3] = *(const uint32_t*)&As[(r + 8) * RS + k0 + 8];
            }
#pragma unroll
            for (int nt = 0; nt < 4; nt++) {
                const int n = wn * 32 + nt * 8 + g;
                b[nt][0] = *(const uint32_t*)&Bs[n * RS + k0];
                b[nt][1] = *(const uint32_t*)&Bs[n * RS + k0 + 8];
            }
#pragma unroll
            for (int mt = 0; mt < 4; mt++)
#pragma unroll
                for (int nt = 0; nt < 4; nt++)
                    mma_bf16(acc[mt][nt], a[mt], b[nt]);
        }
        __syncthreads();
        if (c + STAGES - 1 < NCHUNK)
            load_stage(sb + ((c + STAGES - 1) % STAGES) * (STAGE_ELEMS*2),
                       Ag, Bg, c + STAGES - 1, tid);
        CP_COMMIT();
    }

#pragma unroll
    for (int mt = 0; mt < 4; mt++) {
        const int row = rowC + wm * 64 + mt * 16 + g;
#pragma unroll
        for (int nt = 0; nt < 4; nt++) {
            const int col = colC + wn * 32 + nt * 8 + tg * 2;
            *(float2*)(C + (size_t)row * DIM + col) =
                make_float2(acc[mt][nt][0], acc[mt][nt][1]);
            *(float2*)(C + (size_t)(row + 8) * DIM + col) =
                make_float2(acc[mt][nt][2], acc[mt][nt][3]);
        }
    }
}

__global__ __launch_bounds__(256)
void qkv_mma_kernel() {
    const __nv_bfloat16* W = (blockIdx.z == 0) ? g_wq3
                           : (blockIdx.z == 1) ? g_wk3 : g_wv3;
    float* C = (blockIdx.z == 0) ? g_q : (blockIdx.z == 1) ? g_k : g_v;
    mma_gemm(g_x3, W, C);
}

__global__ __launch_bounds__(256)
void out_mma_kernel(float* __restrict__ out) {
    mma_gemm(g_att3, g_wo3, out);
}

// ---------------------------------------------------------------------------
// k_mean[b,h,d] = mean_l k[b,h,l,d]
// ---------------------------------------------------------------------------
__global__ __launch_bounds__(256)
void kmean_kernel() {
    __shared__ float red[256];
    const int bh = blockIdx.x;
    const int b = bh >> 4, h = bh & 15;
    const int d = threadIdx.x & 63, p = threadIdx.x >> 6;
    const float* base = g_k + (size_t)b * SEQ * DIM + h * HD + d;
    float s = 0.f;
    for (int l = p; l < SEQ; l += 4) s += base[(size_t)l * DIM];
    red[threadIdx.x] = s;
    __syncthreads();
    if (threadIdx.x < 64) {
        float t = red[d] + red[64 + d] + red[128 + d] + red[192 + d];
        g_kmean[bh * HD + d] = t * (1.f / (float)SEQ);
    }
}

// ---------------------------------------------------------------------------
// Fused windowed attention, register-GEMM formulation.
// 256 threads as 16x16 grid. Score: each thread 4q x 8n. PV: 4q x 4d.
// ---------------------------------------------------------------------------
#define AQ_S 68    // Q row stride (floats)
#define AK_S 132   // Kt row stride
#define AV_S 68    // V row stride
#define AP_S 132   // P row stride
#define ATTN_SMEM ((64*AQ_S + 64*AK_S + 128*AV_S + 64*AP_S + 64) * 4)

__global__ void __launch_bounds__(256)
attn_kernel(const float* __restrict__ gsep,
            const float* __restrict__ galign,
            const float* __restrict__ gcoh) {
    extern __shared__ float sm[];
    float* Qs = sm;                    // [64][AQ_S]  q-major
    float* Kt = Qs + 64 * AQ_S;        // [64][AK_S]  d-major (transposed)
    float* Vs = Kt + 64 * AK_S;        // [128][AV_S] n-major
    float* Ps = Vs + 128 * AV_S;       // [64][AP_S]  q-major, pre-normalized
    float* km = Ps + 64 * AP_S;        // [64]

    const int t  = blockIdx.x;
    const int bh = blockIdx.y;
    const int b  = bh >> 4, h = bh & 15;
    const int tid = threadIdx.x;
    const int tx = tid & 15, ty = tid >> 4;
    const int base = t * 64 - 64;

    const float* Kg = g_k + (size_t)b * SEQ * DIM + h * HD;
    const float* Vg = g_v + (size_t)b * SEQ * DIM + h * HD;
    const float* Qg = g_q + (size_t)b * SEQ * DIM + h * HD;

    // Q: coalesced float4 loads, conflict-free STS.128
#pragma unroll
    for (int it = 0; it < 1; it++) {
        int idx = tid;                          // 64 rows x 4 f4-cols = 256
        int r = idx >> 2, c4 = (idx & 3) * 4 * 4; // 16 floats per f4 group? no:
    }
    // (64 rows x 16 floats = 64x4 float4 = 256 float4; one per thread)
    {
        int r = tid >> 2, c4 = (tid & 3) * 4;   // wait: 64 floats/row = 16 f4
    }
    // proper: 64 rows x 16 float4 = 1024 f4, 4 per thread
#pragma unroll
    for (int it = 0; it < 4; it++) {
        int idx = tid + 256 * it;
        int r = idx >> 4, c4 = (idx & 15) * 4;
        *(float4*)(Qs + r * AQ_S + c4) =
            *(const float4*)(Qg + (size_t)(t * 64 + r) * DIM + c4);
    }
    // V: 128 rows x 16 f4 = 2048, 8 per thread, conflict-free
#pragma unroll
    for (int it = 0; it < 8; it++) {
        int idx = tid + 256 * it;
        int r = idx >> 4, c4 = (idx & 15) * 4;
        int j = base + r;
        float4 vv = make_float4(0.f, 0.f, 0.f, 0.f);
        if (j >= 0) vv = *(const float4*)(Vg + (size_t)j * DIM + c4);
        *(float4*)(Vs + r * AV_S + c4) = vv;
    }
    // K transposed: lane reads one row's 16B (uncoalesced gmem, L2-resident);
    // STS.32 with consecutive r per lane -> conflict-free
#pragma unroll
    for (int it = 0; it < 8; it++) {
        int idx = tid + 256 * it;
        int r = idx & 127, d0 = (idx >> 7) * 4;
        int j = base + r;
        float4 kv = make_float4(0.f, 0.f, 0.f, 0.f);
        if (j >= 0) kv = *(const float4*)(Kg + (size_t)j * DIM + d0);
        Kt[(d0 + 0) * AK_S + r] = kv.x;
        Kt[(d0 + 1) * AK_S + r] = kv.y;
        Kt[(d0 + 2) * AK_S + r] = kv.z;
        Kt[(d0 + 3) * AK_S + r] = kv.w;
    }
    if (tid < 64) km[tid] = g_kmean[bh * HD + tid];
    __syncthreads();

    // ---- Score GEMM: S[4q][8n] per thread, plus pm = q . kmean ----
    float acc[4][8];
    float pm[4] = {0.f, 0.f, 0.f, 0.f};
#pragma unroll
    for (int qj = 0; qj < 4; qj++)
#pragma unroll
        for (int nj = 0; nj < 8; nj++) acc[qj][nj] = 0.f;

#pragma unroll 4
    for (int d = 0; d < 64; d++) {
        float4 k0 = *(const float4*)(Kt + d * AK_S + tx * 8);
        float4 k1 = *(const float4*)(Kt + d * AK_S + tx * 8 + 4);
        const float kvs[8] = {k0.x, k0.y, k0.z, k0.w, k1.x, k1.y, k1.z, k1.w};
        const float kmd = km[d];
#pragma unroll
        for (int qj = 0; qj < 4; qj++) {
            const float qv = Qs[(ty * 4 + qj) * AQ_S + d];
            pm[qj] = fmaf(qv, kmd, pm[qj]);
#pragma unroll
            for (int nj = 0; nj < 8; nj++)
                acc[qj][nj] = fmaf(qv, kvs[nj], acc[qj][nj]);
        }
    }

    // ---- Reynolds + mask + softmax (row reductions across tx half-warp) ----
    const float sep = *gsep, alg = *galign, coh = *gcoh;
#pragma unroll
    for (int qj = 0; qj < 4; qj++) {
        const int qi = ty * 4 + qj;
        const float mi = pm[qj] * 0.125f;
        float s2[8];
        float mx = -1e30f;
#pragma unroll
        for (int nj = 0; nj < 8; nj++) {
            const int n = tx * 8 + nj;
            const float s = acc[qj][nj] * 0.125f;
            const float sim = 1.f / (1.f + __expf(-s));
            const float v = s + alg * s - sep * sim * sim - coh * fabsf(s - mi);
            const bool ok = (n >= qi + 1) && (n <= qi + 64) && (base + n >= 0);
            s2[nj] = ok ? v : -1e30f;
            mx = fmaxf(mx, s2[nj]);
        }
#pragma unroll
        for (int o = 1; o < 16; o <<= 1)
            mx = fmaxf(mx, __shfl_xor_sync(0xffffffffu, mx, o));
        float e[8];
        float sum = 0.f;
#pragma unroll
        for (int nj = 0; nj < 8; nj++) {
            e[nj] = (s2[nj] > -1e29f) ? __expf(s2[nj] - mx) : 0.f;
            sum += e[nj];
        }
#pragma unroll
        for (int o = 1; o < 16; o <<= 1)
            sum += __shfl_xor_sync(0xffffffffu, sum, o);
        const float inv = 1.f / sum;
        *(float4*)(Ps + qi * AP_S + tx * 8) =
            make_float4(e[0]*inv, e[1]*inv, e[2]*inv, e[3]*inv);
        *(float4*)(Ps + qi * AP_S + tx * 8 + 4) =
            make_float4(e[4]*inv, e[5]*inv, e[6]*inv, e[7]*inv);
    }
    __syncthreads();

    // ---- PV GEMM: O[4q][4d] per thread ----
    float o[4][4];
#pragma unroll
    for (int qj = 0; qj < 4; qj++)
#pragma unroll
        for (int dj = 0; dj < 4; dj++) o[qj][dj] = 0.f;

#pragma unroll 4
    for (int n = 0; n < 128; n++) {
        float4 vv = *(const float4*)(Vs + n * AV_S + tx * 4);
        const float vs[4] = {vv.x, vv.y, vv.z, vv.w};
#pragma unroll
        for (int qj = 0; qj < 4; qj++) {
            const float p = Ps[(ty * 4 + qj) * AP_S + n];
#pragma unroll
            for (int dj = 0; dj < 4; dj++)
                o[qj][dj] = fmaf(p, vs[dj], o[qj][dj]);
        }
    }

    // ---- Epilogue: write A-side 3-term split [hi | lo | hi] ----
#pragma unroll
    for (int qj = 0; qj < 4; qj++) {
        const int i = t * 64 + ty * 4 + qj;
        const size_t rb = ((size_t)b * SEQ + i) * GK3 + h * HD + tx * 4;
        union { __nv_bfloat16 v[4]; uint2 u; } Hh, Ll;
#pragma unroll
        for (int dj = 0; dj < 4; dj++) {
            __nv_bfloat16 hb = __float2bfloat16(o[qj][dj]);
            Hh.v[dj] = hb;
            Ll.v[dj] = __float2bfloat16(o[qj][dj] - __bfloat162float(hb));
        }
        *(uint2*)(g_att3 + rb)           = Hh.u;
        *(uint2*)(g_att3 + rb + DIM)     = Ll.u;
        *(uint2*)(g_att3 + rb + 2*DIM)   = Hh.u;
    }
}

// ---------------------------------------------------------------------------
extern "C" void kernel_launch(void* const* d_in, const int* in_sizes, int n_in,
                              void* d_out, int out_size) {
    const float* x    = (const float*)d_in[0];
    const float* Wq   = (const float*)d_in[1];
    const float* Wk   = (const float*)d_in[2];
    const float* Wv   = (const float*)d_in[3];
    const float* Wo   = (const float*)d_in[4];
    const float* gsep = (const float*)d_in[5];
    const float* galn = (const float*)d_in[6];
    const float* gcoh = (const float*)d_in[7];
    float* out = (float*)d_out;

    cudaFuncSetAttribute(qkv_mma_kernel,
                         cudaFuncAttributeMaxDynamicSharedMemorySize, GEMM_SMEM);
    cudaFuncSetAttribute(out_mma_kernel,
                         cudaFuncAttributeMaxDynamicSharedMemorySize, GEMM_SMEM);
    cudaFuncSetAttribute(attn_kernel,
                         cudaFuncAttributeMaxDynamicSharedMemorySize, ATTN_SMEM);

    convert_kernel<<<8192, 256>>>(x, Wq, Wk, Wv, Wo);

    dim3 gqkv(DIM / TN, MTOT / TM, 3);
    qkv_mma_kernel<<<gqkv, 256, GEMM_SMEM>>>();

    kmean_kernel<<<BATCH * HEADS, 256>>>();

    dim3 gatt(SEQ / 64, BATCH * HEADS);
    attn_kernel<<<gatt, 256, ATTN_SMEM>>>(gsep, galn, gcoh);

    dim3 gout(DIM / TN, MTOT / TM);
    out_mma_kernel<<<gout, 256, GEMM_SMEM>>>(out);
}

// round 6
// speedup vs baseline: 2.8620x; 1.1353x over previous
#include <cuda_runtime.h>
#include <cuda_bf16.h>
#include <math.h>
#include <stdint.h>

// Problem constants
#define BATCH 2
#define SEQ   2048
#define DIM   1024
#define HEADS 16
#define HD    64
#define MTOT  (BATCH*SEQ)      // 4096
#define GK3   (3*DIM)          // 3-term split K: 3072

// GEMM tiling
#define TM 128
#define TN 128
#define BK 32
#define NCHUNK (GK3/BK)        // 96
#define STAGES 4
#define RS (BK+8)              // 40 elems = 80 B row stride (conflict-free)
#define STAGE_ELEMS (2*128*RS) // 10240 elems
#define STAGE_BYTES (STAGE_ELEMS*2)        // 20480
#define GEMM_SMEM (STAGES*STAGE_BYTES)     // 81920 B -> 2 CTAs/SM

// Scratch (device globals; allocation-free contract)
__device__ __align__(256) float g_q[MTOT*DIM];
__device__ __align__(256) float g_k[MTOT*DIM];
__device__ __align__(256) float g_v[MTOT*DIM];
__device__ __align__(256) float g_kmean[BATCH*HEADS*HD];
// A-side (activations): [hi | lo | hi];  B-side (weights): [hi | hi | lo]
__device__ __align__(256) __nv_bfloat16 g_x3[(size_t)MTOT*GK3];
__device__ __align__(256) __nv_bfloat16 g_att3[(size_t)MTOT*GK3];
__device__ __align__(256) __nv_bfloat16 g_wq3[(size_t)DIM*GK3];
__device__ __align__(256) __nv_bfloat16 g_wk3[(size_t)DIM*GK3];
__device__ __align__(256) __nv_bfloat16 g_wv3[(size_t)DIM*GK3];
__device__ __align__(256) __nv_bfloat16 g_wo3[(size_t)DIM*GK3];

// ---------------------------------------------------------------------------
// Non-arch-variant PTX helpers (compute_103-safe)
// ---------------------------------------------------------------------------
__device__ __forceinline__ uint32_t smem_u32(const void* p) {
    uint32_t a;
    asm("{ .reg .u64 t; cvta.to.shared.u64 t, %1; cvt.u32.u64 %0, t; }"
        : "=r"(a) : "l"(p));
    return a;
}
__device__ __forceinline__ void cp16(uint32_t dst, const void* src) {
    asm volatile("cp.async.cg.shared.global [%0], [%1], 16;"
                 :: "r"(dst), "l"(src));
}
#define CP_COMMIT() asm volatile("cp.async.commit_group;" ::: "memory")
#define CP_WAIT2()  asm volatile("cp.async.wait_group 2;" ::: "memory")

__device__ __forceinline__ void ldsm4(uint32_t* d, uint32_t addr) {
    asm volatile("ldmatrix.sync.aligned.m8n8.x4.shared.b16 {%0,%1,%2,%3}, [%4];"
                 : "=r"(d[0]), "=r"(d[1]), "=r"(d[2]), "=r"(d[3]) : "r"(addr));
}

__device__ __forceinline__ void mma_bf16(float* c, const uint32_t* a,
                                         const uint32_t* b) {
    asm volatile(
        "mma.sync.aligned.m16n8k16.row.col.f32.bf16.bf16.f32 "
        "{%0,%1,%2,%3}, {%4,%5,%6,%7}, {%8,%9}, {%0,%1,%2,%3};"
        : "+f"(c[0]), "+f"(c[1]), "+f"(c[2]), "+f"(c[3])
        : "r"(a[0]), "r"(a[1]), "r"(a[2]), "r"(a[3]), "r"(b[0]), "r"(b[1]));
}

// ---------------------------------------------------------------------------
// 3-term split conversion. A-side: [hi|lo|hi], B-side: [hi|hi|lo].
// ---------------------------------------------------------------------------
__global__ __launch_bounds__(256)
void convert_kernel(const float* __restrict__ x,  const float* __restrict__ wq,
                    const float* __restrict__ wk, const float* __restrict__ wv,
                    const float* __restrict__ wo) {
    int rid = blockIdx.x;
    const float* src; __nv_bfloat16* dst; int row; int aside;
    if      (rid < 4096) { src = x;  dst = g_x3;  row = rid;        aside = 1; }
    else if (rid < 5120) { src = wq; dst = g_wq3; row = rid - 4096; aside = 0; }
    else if (rid < 6144) { src = wk; dst = g_wk3; row = rid - 5120; aside = 0; }
    else if (rid < 7168) { src = wv; dst = g_wv3; row = rid - 6144; aside = 0; }
    else                 { src = wo; dst = g_wo3; row = rid - 7168; aside = 0; }
    int c = threadIdx.x * 4;
    float4 f = *(const float4*)(src + (size_t)row * DIM + c);
    float fv[4] = {f.x, f.y, f.z, f.w};
    union { __nv_bfloat16 b[4]; uint2 u; } H, L;
#pragma unroll
    for (int i = 0; i < 4; i++) {
        __nv_bfloat16 h = __float2bfloat16(fv[i]);
        H.b[i] = h;
        L.b[i] = __float2bfloat16(fv[i] - __bfloat162float(h));
    }
    __nv_bfloat16* r0 = dst + (size_t)row * GK3 + c;
    if (aside) {   // [hi | lo | hi]
        *(uint2*)(r0)            = H.u;
        *(uint2*)(r0 + DIM)      = L.u;
        *(uint2*)(r0 + 2*DIM)    = H.u;
    } else {       // [hi | hi | lo]
        *(uint2*)(r0)            = H.u;
        *(uint2*)(r0 + DIM)      = H.u;
        *(uint2*)(r0 + 2*DIM)    = L.u;
    }
}

// ---------------------------------------------------------------------------
// HMMA GEMM: C[4096,1024] = A3[4096,3072]bf16 @ B3[1024,3072]bf16^T (fp32 acc)
// CTA 128x128, BK=32, 4-stage cp.async, single sync/chunk, ldmatrix frags.
// 8 warps (2x4), warp tile 64x32.
// ---------------------------------------------------------------------------
__device__ __forceinline__ void load_stage(uint32_t stg,
                                           const __nv_bfloat16* __restrict__ Ag,
                                           const __nv_bfloat16* __restrict__ Bg,
                                           int chunk, int tid) {
    const __nv_bfloat16* Ac = Ag + chunk * BK;
    const __nv_bfloat16* Bc = Bg + chunk * BK;
#pragma unroll
    for (int i = 0; i < 2; i++) {
        int seg = tid + 256 * i;
        int r = seg >> 2, cs = seg & 3;
        cp16(stg + r * (RS*2) + cs * 16,
             (const char*)(Ac + (size_t)r * GK3) + cs * 16);
    }
#pragma unroll
    for (int i = 0; i < 2; i++) {
        int seg = tid + 256 * i;
        int r = seg >> 2, cs = seg & 3;
        cp16(stg + 128*(RS*2) + r * (RS*2) + cs * 16,
             (const char*)(Bc + (size_t)r * GK3) + cs * 16);
    }
}

__device__ __forceinline__ void mma_gemm(const __nv_bfloat16* __restrict__ A3,
                                         const __nv_bfloat16* __restrict__ B3,
                                         float* __restrict__ C) {
    extern __shared__ __align__(128) __nv_bfloat16 smem[];
    const uint32_t sb = smem_u32(smem);
    const int tid = threadIdx.x;
    const int lane = tid & 31, w = tid >> 5;
    const int wm = w >> 2, wn = w & 3;        // 2 x 4 warp grid
    const int g = lane >> 2, tg = lane & 3;   // epilogue mapping
    const int rowC = blockIdx.y * TM;
    const int colC = blockIdx.x * TN;
    const __nv_bfloat16* Ag = A3 + (size_t)rowC * GK3;
    const __nv_bfloat16* Bg = B3 + (size_t)colC * GK3;

    // ldmatrix per-lane byte offsets within a stage
    // A sub-tiles: lanes 0-15 rows 0-15 @k0, lanes 16-31 rows 0-15 @k0+8
    const int arow = wm * 64 + (lane & 15);
    const int acol = (lane >> 4) * 8;
    uint32_t a_rel[4];
#pragma unroll
    for (int mt = 0; mt < 4; mt++)
        a_rel[mt] = (uint32_t)(((arow + mt * 16) * RS + acol) * 2);
    // B sub-tiles: lanes 0-7 n0..7@k0, 8-15 n0..7@k0+8, 16-23 n8..15@k0, 24-31 n8..15@k0+8
    const int brow = wn * 32 + (lane & 7) + ((lane >> 4) << 3);
    const int bcol = ((lane >> 3) & 1) * 8;
    uint32_t b_rel[2];
#pragma unroll
    for (int p = 0; p < 2; p++)
        b_rel[p] = (uint32_t)(((128 + brow + p * 16) * RS + bcol) * 2);

    float acc[4][4][4];
#pragma unroll
    for (int mt = 0; mt < 4; mt++)
#pragma unroll
        for (int nt = 0; nt < 4; nt++)
#pragma unroll
            for (int i = 0; i < 4; i++) acc[mt][nt][i] = 0.f;

#pragma unroll
    for (int s = 0; s < STAGES - 1; s++) {
        load_stage(sb + s * STAGE_BYTES, Ag, Bg, s, tid);
        CP_COMMIT();
    }

    for (int c = 0; c < NCHUNK; c++) {
        CP_WAIT2();
        __syncthreads();
        const uint32_t stg = sb + (uint32_t)(c & 3) * STAGE_BYTES;

        // Prefetch next stage early (overwrites stage read in chunk c-1,
        // ordered by the barrier above).
        if (c + (STAGES - 1) < NCHUNK)
            load_stage(sb + (uint32_t)((c + STAGES - 1) & 3) * STAGE_BYTES,
                       Ag, Bg, c + STAGES - 1, tid);
        CP_COMMIT();

#pragma unroll
        for (int ks = 0; ks < 2; ks++) {
            const uint32_t ko = (uint32_t)(ks * 16 * 2);
            uint32_t a[4][4], b[2][4];
#pragma unroll
            for (int mt = 0; mt < 4; mt++) ldsm4(a[mt], stg + a_rel[mt] + ko);
#pragma unroll
            for (int p = 0; p < 2; p++)    ldsm4(b[p],  stg + b_rel[p] + ko);
#pragma unroll
            for (int mt = 0; mt < 4; mt++)
#pragma unroll
                for (int nt = 0; nt < 4; nt++)
                    mma_bf16(acc[mt][nt], a[mt], &b[nt >> 1][(nt & 1) * 2]);
        }
    }

    // Epilogue: direct fp32 stores
#pragma unroll
    for (int mt = 0; mt < 4; mt++) {
        const int row = rowC + wm * 64 + mt * 16 + g;
#pragma unroll
        for (int nt = 0; nt < 4; nt++) {
            const int col = colC + wn * 32 + nt * 8 + tg * 2;
            *(float2*)(C + (size_t)row * DIM + col) =
                make_float2(acc[mt][nt][0], acc[mt][nt][1]);
            *(float2*)(C + (size_t)(row + 8) * DIM + col) =
                make_float2(acc[mt][nt][2], acc[mt][nt][3]);
        }
    }
}

__global__ __launch_bounds__(256, 2)
void qkv_mma_kernel() {
    const __nv_bfloat16* W = (blockIdx.z == 0) ? g_wq3
                           : (blockIdx.z == 1) ? g_wk3 : g_wv3;
    float* C = (blockIdx.z == 0) ? g_q : (blockIdx.z == 1) ? g_k : g_v;
    mma_gemm(g_x3, W, C);
}

__global__ __launch_bounds__(256, 2)
void out_mma_kernel(float* __restrict__ out) {
    mma_gemm(g_att3, g_wo3, out);
}

// ---------------------------------------------------------------------------
// k_mean[b,h,d] = mean_l k[b,h,l,d]
// ---------------------------------------------------------------------------
__global__ __launch_bounds__(256)
void kmean_kernel() {
    __shared__ float red[256];
    const int bh = blockIdx.x;
    const int b = bh >> 4, h = bh & 15;
    const int d = threadIdx.x & 63, p = threadIdx.x >> 6;
    const float* base = g_k + (size_t)b * SEQ * DIM + h * HD + d;
    float s = 0.f;
    for (int l = p; l < SEQ; l += 4) s += base[(size_t)l * DIM];
    red[threadIdx.x] = s;
    __syncthreads();
    if (threadIdx.x < 64) {
        float t = red[d] + red[64 + d] + red[128 + d] + red[192 + d];
        g_kmean[bh * HD + d] = t * (1.f / (float)SEQ);
    }
}

// ---------------------------------------------------------------------------
// Fused windowed attention, register-GEMM formulation.
// 256 threads as 16x16 grid. Score: each thread 4q x 8n. PV: 4q x 4d.
// ---------------------------------------------------------------------------
#define AQ_S 68    // Q row stride (floats)
#define AK_S 132   // Kt row stride
#define AV_S 68    // V row stride
#define AP_S 132   // P row stride
#define ATTN_SMEM ((64*AQ_S + 64*AK_S + 128*AV_S + 64*AP_S + 64) * 4)

__global__ void __launch_bounds__(256)
attn_kernel(const float* __restrict__ gsep,
            const float* __restrict__ galign,
            const float* __restrict__ gcoh) {
    extern __shared__ float sm[];
    float* Qs = sm;                    // [64][AQ_S]  q-major
    float* Kt = Qs + 64 * AQ_S;        // [64][AK_S]  d-major (transposed)
    float* Vs = Kt + 64 * AK_S;        // [128][AV_S] n-major
    float* Ps = Vs + 128 * AV_S;       // [64][AP_S]  q-major, pre-normalized
    float* km = Ps + 64 * AP_S;        // [64]

    const int t  = blockIdx.x;
    const int bh = blockIdx.y;
    const int b  = bh >> 4, h = bh & 15;
    const int tid = threadIdx.x;
    const int tx = tid & 15, ty = tid >> 4;
    const int base = t * 64 - 64;

    const float* Kg = g_k + (size_t)b * SEQ * DIM + h * HD;
    const float* Vg = g_v + (size_t)b * SEQ * DIM + h * HD;
    const float* Qg = g_q + (size_t)b * SEQ * DIM + h * HD;

    // Q: 64 rows x 16 float4 = 1024 f4, 4 per thread
#pragma unroll
    for (int it = 0; it < 4; it++) {
        int idx = tid + 256 * it;
        int r = idx >> 4, c4 = (idx & 15) * 4;
        *(float4*)(Qs + r * AQ_S + c4) =
            *(const float4*)(Qg + (size_t)(t * 64 + r) * DIM + c4);
    }
    // V: 128 rows x 16 f4 = 2048, 8 per thread
#pragma unroll
    for (int it = 0; it < 8; it++) {
        int idx = tid + 256 * it;
        int r = idx >> 4, c4 = (idx & 15) * 4;
        int j = base + r;
        float4 vv = make_float4(0.f, 0.f, 0.f, 0.f);
        if (j >= 0) vv = *(const float4*)(Vg + (size_t)j * DIM + c4);
        *(float4*)(Vs + r * AV_S + c4) = vv;
    }
    // K transposed: lane reads one row's 16B; STS.32 conflict-free
#pragma unroll
    for (int it = 0; it < 8; it++) {
        int idx = tid + 256 * it;
        int r = idx & 127, d0 = (idx >> 7) * 4;
        int j = base + r;
        float4 kv = make_float4(0.f, 0.f, 0.f, 0.f);
        if (j >= 0) kv = *(const float4*)(Kg + (size_t)j * DIM + d0);
        Kt[(d0 + 0) * AK_S + r] = kv.x;
        Kt[(d0 + 1) * AK_S + r] = kv.y;
        Kt[(d0 + 2) * AK_S + r] = kv.z;
        Kt[(d0 + 3) * AK_S + r] = kv.w;
    }
    if (tid < 64) km[tid] = g_kmean[bh * HD + tid];
    __syncthreads();

    // ---- Score GEMM: S[4q][8n] per thread, plus pm = q . kmean ----
    float acc[4][8];
    float pm[4] = {0.f, 0.f, 0.f, 0.f};
#pragma unroll
    for (int qj = 0; qj < 4; qj++)
#pragma unroll
        for (int nj = 0; nj < 8; nj++) acc[qj][nj] = 0.f;

#pragma unroll 4
    for (int d = 0; d < 64; d++) {
        float4 k0 = *(const float4*)(Kt + d * AK_S + tx * 8);
        float4 k1 = *(const float4*)(Kt + d * AK_S + tx * 8 + 4);
        const float kvs[8] = {k0.x, k0.y, k0.z, k0.w, k1.x, k1.y, k1.z, k1.w};
        const float kmd = km[d];
#pragma unroll
        for (int qj = 0; qj < 4; qj++) {
            const float qv = Qs[(ty * 4 + qj) * AQ_S + d];
            pm[qj] = fmaf(qv, kmd, pm[qj]);
#pragma unroll
            for (int nj = 0; nj < 8; nj++)
                acc[qj][nj] = fmaf(qv, kvs[nj], acc[qj][nj]);
        }
    }

    // ---- Reynolds + mask + softmax (row reductions across tx half-warp) ----
    const float sep = *gsep, alg = *galign, coh = *gcoh;
#pragma unroll
    for (int qj = 0; qj < 4; qj++) {
        const int qi = ty * 4 + qj;
        const float mi = pm[qj] * 0.125f;
        float s2[8];
        float mx = -1e30f;
#pragma unroll
        for (int nj = 0; nj < 8; nj++) {
            const int n = tx * 8 + nj;
            const float s = acc[qj][nj] * 0.125f;
            const float sim = 1.f / (1.f + __expf(-s));
            const float v = s + alg * s - sep * sim * sim - coh * fabsf(s - mi);
            const bool ok = (n >= qi + 1) && (n <= qi + 64) && (base + n >= 0);
            s2[nj] = ok ? v : -1e30f;
            mx = fmaxf(mx, s2[nj]);
        }
#pragma unroll
        for (int o = 1; o < 16; o <<= 1)
            mx = fmaxf(mx, __shfl_xor_sync(0xffffffffu, mx, o));
        float e[8];
        float sum = 0.f;
#pragma unroll
        for (int nj = 0; nj < 8; nj++) {
            e[nj] = (s2[nj] > -1e29f) ? __expf(s2[nj] - mx) : 0.f;
            sum += e[nj];
        }
#pragma unroll
        for (int o = 1; o < 16; o <<= 1)
            sum += __shfl_xor_sync(0xffffffffu, sum, o);
        const float inv = 1.f / sum;
        *(float4*)(Ps + qi * AP_S + tx * 8) =
            make_float4(e[0]*inv, e[1]*inv, e[2]*inv, e[3]*inv);
        *(float4*)(Ps + qi * AP_S + tx * 8 + 4) =
            make_float4(e[4]*inv, e[5]*inv, e[6]*inv, e[7]*inv);
    }
    __syncthreads();

    // ---- PV GEMM: O[4q][4d] per thread ----
    float o[4][4];
#pragma unroll
    for (int qj = 0; qj < 4; qj++)
#pragma unroll
        for (int dj = 0; dj < 4; dj++) o[qj][dj] = 0.f;

#pragma unroll 4
    for (int n = 0; n < 128; n++) {
        float4 vv = *(const float4*)(Vs + n * AV_S + tx * 4);
        const float vs[4] = {vv.x, vv.y, vv.z, vv.w};
#pragma unroll
        for (int qj = 0; qj < 4; qj++) {
            const float p = Ps[(ty * 4 + qj) * AP_S + n];
#pragma unroll
            for (int dj = 0; dj < 4; dj++)
                o[qj][dj] = fmaf(p, vs[dj], o[qj][dj]);
        }
    }

    // ---- Epilogue: write A-side 3-term split [hi | lo | hi] ----
#pragma unroll
    for (int qj = 0; qj < 4; qj++) {
        const int i = t * 64 + ty * 4 + qj;
        const size_t rb = ((size_t)b * SEQ + i) * GK3 + h * HD + tx * 4;
        union { __nv_bfloat16 v[4]; uint2 u; } Hh, Ll;
#pragma unroll
        for (int dj = 0; dj < 4; dj++) {
            __nv_bfloat16 hb = __float2bfloat16(o[qj][dj]);
            Hh.v[dj] = hb;
            Ll.v[dj] = __float2bfloat16(o[qj][dj] - __bfloat162float(hb));
        }
        *(uint2*)(g_att3 + rb)           = Hh.u;
        *(uint2*)(g_att3 + rb + DIM)     = Ll.u;
        *(uint2*)(g_att3 + rb + 2*DIM)   = Hh.u;
    }
}

// ---------------------------------------------------------------------------
extern "C" void kernel_launch(void* const* d_in, const int* in_sizes, int n_in,
                              void* d_out, int out_size) {
    const float* x    = (const float*)d_in[0];
    const float* Wq   = (const float*)d_in[1];
    const float* Wk   = (const float*)d_in[2];
    const float* Wv   = (const float*)d_in[3];
    const float* Wo   = (const float*)d_in[4];
    const float* gsep = (const float*)d_in[5];
    const float* galn = (const float*)d_in[6];
    const float* gcoh = (const float*)d_in[7];
    float* out = (float*)d_out;

    cudaFuncSetAttribute(qkv_mma_kernel,
                         cudaFuncAttributeMaxDynamicSharedMemorySize, GEMM_SMEM);
    cudaFuncSetAttribute(out_mma_kernel,
                         cudaFuncAttributeMaxDynamicSharedMemorySize, GEMM_SMEM);
    cudaFuncSetAttribute(attn_kernel,
                         cudaFuncAttributeMaxDynamicSharedMemorySize, ATTN_SMEM);

    convert_kernel<<<8192, 256>>>(x, Wq, Wk, Wv, Wo);

    dim3 gqkv(DIM / TN, MTOT / TM, 3);
    qkv_mma_kernel<<<gqkv, 256, GEMM_SMEM>>>();

    kmean_kernel<<<BATCH * HEADS, 256>>>();

    dim3 gatt(SEQ / 64, BATCH * HEADS);
    attn_kernel<<<gatt, 256, ATTN_SMEM>>>(gsep, galn, gcoh);

    dim3 gout(DIM / TN, MTOT / TM);
    out_mma_kernel<<<gout, 256, GEMM_SMEM>>>(out);
}

// round 8
// speedup vs baseline: 2.9250x; 1.0220x over previous
#include <cuda_runtime.h>
#include <cuda_bf16.h>
#include <math.h>
#include <stdint.h>

// Problem constants
#define BATCH 2
#define SEQ   2048
#define DIM   1024
#define HEADS 16
#define HD    64
#define MTOT  (BATCH*SEQ)      // 4096
#define GK2   (2*DIM)          // [hi | lo] storage: 2048

// GEMM tiling (3-term split via chunk remap: 96 logical chunks over 64 stored)
#define TM 128
#define TN 128
#define BK 32
#define NCHUNK 96              // logical chunks (hi*hi, lo*hi, hi*lo)
#define STAGES 4
#define RS (BK+8)              // 40 elems = 80 B row stride (conflict-free)
#define STAGE_ELEMS (2*128*RS)
#define STAGE_BYTES (STAGE_ELEMS*2)        // 20480
#define GEMM_SMEM (STAGES*STAGE_BYTES)     // 81920 B -> 2 CTAs/SM

// Scratch (device globals; allocation-free contract)
__device__ __align__(256) float g_q[MTOT*DIM];
__device__ __align__(256) float g_k[MTOT*DIM];
__device__ __align__(256) float g_v[MTOT*DIM];
__device__ __align__(256) float g_kmean[BATCH*HEADS*HD];
// Both sides stored [hi | lo] (K=2048); GEMM remaps logical chunk -> segment.
__device__ __align__(256) __nv_bfloat16 g_x2[(size_t)MTOT*GK2];
__device__ __align__(256) __nv_bfloat16 g_att2[(size_t)MTOT*GK2];
__device__ __align__(256) __nv_bfloat16 g_wq2[(size_t)DIM*GK2];
__device__ __align__(256) __nv_bfloat16 g_wk2[(size_t)DIM*GK2];
__device__ __align__(256) __nv_bfloat16 g_wv2[(size_t)DIM*GK2];
__device__ __align__(256) __nv_bfloat16 g_wo2[(size_t)DIM*GK2];

// ---------------------------------------------------------------------------
// Non-arch-variant PTX helpers (compute_103-safe)
// ---------------------------------------------------------------------------
__device__ __forceinline__ uint32_t smem_u32(const void* p) {
    uint32_t a;
    asm("{ .reg .u64 t; cvta.to.shared.u64 t, %1; cvt.u32.u64 %0, t; }"
        : "=r"(a) : "l"(p));
    return a;
}
__device__ __forceinline__ void cp16(uint32_t dst, const void* src) {
    asm volatile("cp.async.cg.shared.global [%0], [%1], 16;"
                 :: "r"(dst), "l"(src));
}
#define CP_COMMIT() asm volatile("cp.async.commit_group;" ::: "memory")
#define CP_WAIT2()  asm volatile("cp.async.wait_group 2;" ::: "memory")

__device__ __forceinline__ void ldsm4(uint32_t* d, uint32_t addr) {
    asm volatile("ldmatrix.sync.aligned.m8n8.x4.shared.b16 {%0,%1,%2,%3}, [%4];"
                 : "=r"(d[0]), "=r"(d[1]), "=r"(d[2]), "=r"(d[3]) : "r"(addr));
}

__device__ __forceinline__ void mma_bf16(float* c, const uint32_t* a,
                                         const uint32_t* b) {
    asm volatile(
        "mma.sync.aligned.m16n8k16.row.col.f32.bf16.bf16.f32 "
        "{%0,%1,%2,%3}, {%4,%5,%6,%7}, {%8,%9}, {%0,%1,%2,%3};"
        : "+f"(c[0]), "+f"(c[1]), "+f"(c[2]), "+f"(c[3])
        : "r"(a[0]), "r"(a[1]), "r"(a[2]), "r"(a[3]), "r"(b[0]), "r"(b[1]));
}

// ---------------------------------------------------------------------------
// Split conversion: f = hi(bf16) + lo(bf16); store [hi | lo].
// ---------------------------------------------------------------------------
__global__ __launch_bounds__(256)
void convert_kernel(const float* __restrict__ x,  const float* __restrict__ wq,
                    const float* __restrict__ wk, const float* __restrict__ wv,
                    const float* __restrict__ wo) {
    int rid = blockIdx.x;
    const float* src; __nv_bfloat16* dst; int row;
    if      (rid < 4096) { src = x;  dst = g_x2;  row = rid;        }
    else if (rid < 5120) { src = wq; dst = g_wq2; row = rid - 4096; }
    else if (rid < 6144) { src = wk; dst = g_wk2; row = rid - 5120; }
    else if (rid < 7168) { src = wv; dst = g_wv2; row = rid - 6144; }
    else                 { src = wo; dst = g_wo2; row = rid - 7168; }
    int c = threadIdx.x * 4;
    float4 f = *(const float4*)(src + (size_t)row * DIM + c);
    float fv[4] = {f.x, f.y, f.z, f.w};
    union { __nv_bfloat16 b[4]; uint2 u; } H, L;
#pragma unroll
    for (int i = 0; i < 4; i++) {
        __nv_bfloat16 h = __float2bfloat16(fv[i]);
        H.b[i] = h;
        L.b[i] = __float2bfloat16(fv[i] - __bfloat162float(h));
    }
    __nv_bfloat16* r0 = dst + (size_t)row * GK2 + c;
    *(uint2*)(r0)       = H.u;
    *(uint2*)(r0 + DIM) = L.u;
}

// ---------------------------------------------------------------------------
// HMMA GEMM with logical->physical chunk remap implementing the 3-term split:
//   c in [0,32):  A hi * B hi
//   c in [32,64): A lo * B hi
//   c in [64,96): A hi * B lo
// ---------------------------------------------------------------------------
__device__ __forceinline__ void load_stage(uint32_t stg,
                                           const __nv_bfloat16* __restrict__ Ag,
                                           const __nv_bfloat16* __restrict__ Bg,
                                           int chunk, int tid) {
    const int a_src = (chunk < 64) ? chunk : chunk - 64;   // hi, lo, hi
    const int b_src = (chunk < 32) ? chunk : chunk - 32;   // hi, hi, lo
    const __nv_bfloat16* Ac = Ag + a_src * BK;
    const __nv_bfloat16* Bc = Bg + b_src * BK;
#pragma unroll
    for (int i = 0; i < 2; i++) {
        int seg = tid + 256 * i;
        int r = seg >> 2, cs = seg & 3;
        cp16(stg + r * (RS*2) + cs * 16,
             (const char*)(Ac + (size_t)r * GK2) + cs * 16);
    }
#pragma unroll
    for (int i = 0; i < 2; i++) {
        int seg = tid + 256 * i;
        int r = seg >> 2, cs = seg & 3;
        cp16(stg + 128*(RS*2) + r * (RS*2) + cs * 16,
             (const char*)(Bc + (size_t)r * GK2) + cs * 16);
    }
}

__device__ __forceinline__ void mma_gemm(const __nv_bfloat16* __restrict__ A2,
                                         const __nv_bfloat16* __restrict__ B2,
                                         float* __restrict__ C) {
    extern __shared__ __align__(128) __nv_bfloat16 smem[];
    const uint32_t sb = smem_u32(smem);
    const int tid = threadIdx.x;
    const int lane = tid & 31, w = tid >> 5;
    const int wm = w >> 2, wn = w & 3;        // 2 x 4 warp grid
    const int g = lane >> 2, tg = lane & 3;   // epilogue mapping
    const int rowC = blockIdx.y * TM;
    const int colC = blockIdx.x * TN;
    const __nv_bfloat16* Ag = A2 + (size_t)rowC * GK2;
    const __nv_bfloat16* Bg = B2 + (size_t)colC * GK2;

    const int arow = wm * 64 + (lane & 15);
    const int acol = (lane >> 4) * 8;
    uint32_t a_rel[4];
#pragma unroll
    for (int mt = 0; mt < 4; mt++)
        a_rel[mt] = (uint32_t)(((arow + mt * 16) * RS + acol) * 2);
    const int brow = wn * 32 + (lane & 7) + ((lane >> 4) << 3);
    const int bcol = ((lane >> 3) & 1) * 8;
    uint32_t b_rel[2];
#pragma unroll
    for (int p = 0; p < 2; p++)
        b_rel[p] = (uint32_t)(((128 + brow + p * 16) * RS + bcol) * 2);

    float acc[4][4][4];
#pragma unroll
    for (int mt = 0; mt < 4; mt++)
#pragma unroll
        for (int nt = 0; nt < 4; nt++)
#pragma unroll
            for (int i = 0; i < 4; i++) acc[mt][nt][i] = 0.f;

#pragma unroll
    for (int s = 0; s < STAGES - 1; s++) {
        load_stage(sb + s * STAGE_BYTES, Ag, Bg, s, tid);
        CP_COMMIT();
    }

    for (int c = 0; c < NCHUNK; c++) {
        CP_WAIT2();
        __syncthreads();
        const uint32_t stg = sb + (uint32_t)(c & 3) * STAGE_BYTES;

        if (c + (STAGES - 1) < NCHUNK)
            load_stage(sb + (uint32_t)((c + STAGES - 1) & 3) * STAGE_BYTES,
                       Ag, Bg, c + STAGES - 1, tid);
        CP_COMMIT();

#pragma unroll
        for (int ks = 0; ks < 2; ks++) {
            const uint32_t ko = (uint32_t)(ks * 16 * 2);
            uint32_t a[4][4], b[2][4];
#pragma unroll
            for (int mt = 0; mt < 4; mt++) ldsm4(a[mt], stg + a_rel[mt] + ko);
#pragma unroll
            for (int p = 0; p < 2; p++)    ldsm4(b[p],  stg + b_rel[p] + ko);
#pragma unroll
            for (int mt = 0; mt < 4; mt++)
#pragma unroll
                for (int nt = 0; nt < 4; nt++)
                    mma_bf16(acc[mt][nt], a[mt], &b[nt >> 1][(nt & 1) * 2]);
        }
    }

    // Epilogue: direct fp32 stores
#pragma unroll
    for (int mt = 0; mt < 4; mt++) {
        const int row = rowC + wm * 64 + mt * 16 + g;
#pragma unroll
        for (int nt = 0; nt < 4; nt++) {
            const int col = colC + wn * 32 + nt * 8 + tg * 2;
            *(float2*)(C + (size_t)row * DIM + col) =
                make_float2(acc[mt][nt][0], acc[mt][nt][1]);
            *(float2*)(C + (size_t)(row + 8) * DIM + col) =
                make_float2(acc[mt][nt][2], acc[mt][nt][3]);
        }
    }
}

__global__ __launch_bounds__(256, 2)
void qkv_mma_kernel() {
    const __nv_bfloat16* W = (blockIdx.z == 0) ? g_wq2
                           : (blockIdx.z == 1) ? g_wk2 : g_wv2;
    float* C = (blockIdx.z == 0) ? g_q : (blockIdx.z == 1) ? g_k : g_v;
    mma_gemm(g_x2, W, C);
}

__global__ __launch_bounds__(256, 2)
void out_mma_kernel(float* __restrict__ out) {
    mma_gemm(g_att2, g_wo2, out);
}

// ---------------------------------------------------------------------------
// k_mean[b,h,d] = mean_l k[b,h,l,d]
// ---------------------------------------------------------------------------
__global__ __launch_bounds__(256)
void kmean_kernel() {
    __shared__ float red[256];
    const int bh = blockIdx.x;
    const int b = bh >> 4, h = bh & 15;
    const int d = threadIdx.x & 63, p = threadIdx.x >> 6;
    const float* base = g_k + (size_t)b * SEQ * DIM + h * HD + d;
    float s = 0.f;
    for (int l = p; l < SEQ; l += 4) s += base[(size_t)l * DIM];
    red[threadIdx.x] = s;
    __syncthreads();
    if (threadIdx.x < 64) {
        float t = red[d] + red[64 + d] + red[128 + d] + red[192 + d];
        g_kmean[bh * HD + d] = t * (1.f / (float)SEQ);
    }
}

// ---------------------------------------------------------------------------
// Fused windowed attention, register-GEMM formulation (proven R6 layout).
// 256 threads as 16x16 grid. Score: each thread 4q x 8n. PV: 4q x 4d.
// ---------------------------------------------------------------------------
#define AQ_S 68    // Q row stride (floats)
#define AK_S 132   // Kt row stride
#define AV_S 68    // V row stride
#define AP_S 132   // P row stride
#define ATTN_SMEM ((64*AQ_S + 64*AK_S + 128*AV_S + 64*AP_S + 64) * 4)

__global__ void __launch_bounds__(256)
attn_kernel(const float* __restrict__ gsep,
            const float* __restrict__ galign,
            const float* __restrict__ gcoh) {
    extern __shared__ float sm[];
    float* Qs = sm;                    // [64][AQ_S]  q-major
    float* Kt = Qs + 64 * AQ_S;        // [64][AK_S]  d-major (transposed)
    float* Vs = Kt + 64 * AK_S;        // [128][AV_S] n-major
    float* Ps = Vs + 128 * AV_S;       // [64][AP_S]  q-major, pre-normalized
    float* km = Ps + 64 * AP_S;        // [64]

    const int t  = blockIdx.x;
    const int bh = blockIdx.y;
    const int b  = bh >> 4, h = bh & 15;
    const int tid = threadIdx.x;
    const int tx = tid & 15, ty = tid >> 4;
    const int base = t * 64 - 64;

    const float* Kg = g_k + (size_t)b * SEQ * DIM + h * HD;
    const float* Vg = g_v + (size_t)b * SEQ * DIM + h * HD;
    const float* Qg = g_q + (size_t)b * SEQ * DIM + h * HD;

    // Q: 64 rows x 16 float4 = 1024 f4, 4 per thread
#pragma unroll
    for (int it = 0; it < 4; it++) {
        int idx = tid + 256 * it;
        int r = idx >> 4, c4 = (idx & 15) * 4;
        *(float4*)(Qs + r * AQ_S + c4) =
            *(const float4*)(Qg + (size_t)(t * 64 + r) * DIM + c4);
    }
    // V: 128 rows x 16 f4 = 2048, 8 per thread
#pragma unroll
    for (int it = 0; it < 8; it++) {
        int idx = tid + 256 * it;
        int r = idx >> 4, c4 = (idx & 15) * 4;
        int j = base + r;
        float4 vv = make_float4(0.f, 0.f, 0.f, 0.f);
        if (j >= 0) vv = *(const float4*)(Vg + (size_t)j * DIM + c4);
        *(float4*)(Vs + r * AV_S + c4) = vv;
    }
    // K transposed: lane reads one row's 16B; STS.32 conflict-free
#pragma unroll
    for (int it = 0; it < 8; it++) {
        int idx = tid + 256 * it;
        int r = idx & 127, d0 = (idx >> 7) * 4;
        int j = base + r;
        float4 kv = make_float4(0.f, 0.f, 0.f, 0.f);
        if (j >= 0) kv = *(const float4*)(Kg + (size_t)j * DIM + d0);
        Kt[(d0 + 0) * AK_S + r] = kv.x;
        Kt[(d0 + 1) * AK_S + r] = kv.y;
        Kt[(d0 + 2) * AK_S + r] = kv.z;
        Kt[(d0 + 3) * AK_S + r] = kv.w;
    }
    if (tid < 64) km[tid] = g_kmean[bh * HD + tid];
    __syncthreads();

    // ---- Score GEMM: S[4q][8n] per thread, plus pm = q . kmean ----
    float acc[4][8];
    float pm[4] = {0.f, 0.f, 0.f, 0.f};
#pragma unroll
    for (int qj = 0; qj < 4; qj++)
#pragma unroll
        for (int nj = 0; nj < 8; nj++) acc[qj][nj] = 0.f;

#pragma unroll 4
    for (int d = 0; d < 64; d++) {
        float4 k0 = *(const float4*)(Kt + d * AK_S + tx * 8);
        float4 k1 = *(const float4*)(Kt + d * AK_S + tx * 8 + 4);
        const float kvs[8] = {k0.x, k0.y, k0.z, k0.w, k1.x, k1.y, k1.z, k1.w};
        const float kmd = km[d];
#pragma unroll
        for (int qj = 0; qj < 4; qj++) {
            const float qv = Qs[(ty * 4 + qj) * AQ_S + d];
            pm[qj] = fmaf(qv, kmd, pm[qj]);
#pragma unroll
            for (int nj = 0; nj < 8; nj++)
                acc[qj][nj] = fmaf(qv, kvs[nj], acc[qj][nj]);
        }
    }

    // ---- Reynolds + mask + softmax (row reductions across tx half-warp) ----
    const float sep = *gsep, alg = *galign, coh = *gcoh;
#pragma unroll
    for (int qj = 0; qj < 4; qj++) {
        const int qi = ty * 4 + qj;
        const float mi = pm[qj] * 0.125f;
        float s2[8];
        float mx = -1e30f;
#pragma unroll
        for (int nj = 0; nj < 8; nj++) {
            const int n = tx * 8 + nj;
            const float s = acc[qj][nj] * 0.125f;
            const float sim = 1.f / (1.f + __expf(-s));
            const float v = s + alg * s - sep * sim * sim - coh * fabsf(s - mi);
            const bool ok = (n >= qi + 1) && (n <= qi + 64) && (base + n >= 0);
            s2[nj] = ok ? v : -1e30f;
            mx = fmaxf(mx, s2[nj]);
        }
#pragma unroll
        for (int o = 1; o < 16; o <<= 1)
            mx = fmaxf(mx, __shfl_xor_sync(0xffffffffu, mx, o));
        float e[8];
        float sum = 0.f;
#pragma unroll
        for (int nj = 0; nj < 8; nj++) {
            e[nj] = (s2[nj] > -1e29f) ? __expf(s2[nj] - mx) : 0.f;
            sum += e[nj];
        }
#pragma unroll
        for (int o = 1; o < 16; o <<= 1)
            sum += __shfl_xor_sync(0xffffffffu, sum, o);
        const float inv = 1.f / sum;
        *(float4*)(Ps + qi * AP_S + tx * 8) =
            make_float4(e[0]*inv, e[1]*inv, e[2]*inv, e[3]*inv);
        *(float4*)(Ps + qi * AP_S + tx * 8 + 4) =
            make_float4(e[4]*inv, e[5]*inv, e[6]*inv, e[7]*inv);
    }
    __syncthreads();

    // ---- PV GEMM: O[4q][4d] per thread ----
    float o[4][4];
#pragma unroll
    for (int qj = 0; qj < 4; qj++)
#pragma unroll
        for (int dj = 0; dj < 4; dj++) o[qj][dj] = 0.f;

#pragma unroll 4
    for (int n = 0; n < 128; n++) {
        float4 vv = *(const float4*)(Vs + n * AV_S + tx * 4);
        const float vs[4] = {vv.x, vv.y, vv.z, vv.w};
#pragma unroll
        for (int qj = 0; qj < 4; qj++) {
            const float p = Ps[(ty * 4 + qj) * AP_S + n];
#pragma unroll
            for (int dj = 0; dj < 4; dj++)
                o[qj][dj] = fmaf(p, vs[dj], o[qj][dj]);
        }
    }

    // ---- Epilogue: write [hi | lo] split ----
#pragma unroll
    for (int qj = 0; qj < 4; qj++) {
        const int i = t * 64 + ty * 4 + qj;
        const size_t rb = ((size_t)b * SEQ + i) * GK2 + h * HD + tx * 4;
        union { __nv_bfloat16 v[4]; uint2 u; } Hh, Ll;
#pragma unroll
        for (int dj = 0; dj < 4; dj++) {
            __nv_bfloat16 hb = __float2bfloat16(o[qj][dj]);
            Hh.v[dj] = hb;
            Ll.v[dj] = __float2bfloat16(o[qj][dj] - __bfloat162float(hb));
        }
        *(uint2*)(g_att2 + rb)       = Hh.u;
        *(uint2*)(g_att2 + rb + DIM) = Ll.u;
    }
}

// ---------------------------------------------------------------------------
extern "C" void kernel_launch(void* const* d_in, const int* in_sizes, int n_in,
                              void* d_out, int out_size) {
    const float* x    = (const float*)d_in[0];
    const float* Wq   = (const float*)d_in[1];
    const float* Wk   = (const float*)d_in[2];
    const float* Wv   = (const float*)d_in[3];
    const float* Wo   = (const float*)d_in[4];
    const float* gsep = (const float*)d_in[5];
    const float* galn = (const float*)d_in[6];
    const float* gcoh = (const float*)d_in[7];
    float* out = (float*)d_out;

    cudaFuncSetAttribute(qkv_mma_kernel,
                         cudaFuncAttributeMaxDynamicSharedMemorySize, GEMM_SMEM);
    cudaFuncSetAttribute(out_mma_kernel,
                         cudaFuncAttributeMaxDynamicSharedMemorySize, GEMM_SMEM);
    cudaFuncSetAttribute(attn_kernel,
                         cudaFuncAttributeMaxDynamicSharedMemorySize, ATTN_SMEM);

    convert_kernel<<<8192, 256>>>(x, Wq, Wk, Wv, Wo);

    dim3 gqkv(DIM / TN, MTOT / TM, 3);
    qkv_mma_kernel<<<gqkv, 256, GEMM_SMEM>>>();

    kmean_kernel<<<BATCH * HEADS, 256>>>();

    dim3 gatt(SEQ / 64, BATCH * HEADS);
    attn_kernel<<<gatt, 256, ATTN_SMEM>>>(gsep, galn, gcoh);

    dim3 gout(DIM / TN, MTOT / TM);
    out_mma_kernel<<<gout, 256, GEMM_SMEM>>>(out);
}

// round 9
// speedup vs baseline: 3.7539x; 1.2834x over previous
#include <cuda_runtime.h>
#include <cuda_fp16.h>
#include <math.h>
#include <stdint.h>

// Problem constants
#define BATCH 2
#define SEQ   2048
#define DIM   1024
#define HEADS 16
#define HD    64
#define MTOT  (BATCH*SEQ)      // 4096
#define GK2   (2*DIM)          // activation [hi | lo] storage: 2048

// GEMM tiling: 2-term fp16 split. Logical K = 2048 (A: hi then lo segments,
// B: the single fp16 weight tile reused for both segments).
#define TM 128
#define TN 128
#define BK 32
#define NCHUNK 64              // 64 logical chunks: c<32 hi*W, c>=32 lo*W
#define STAGES 4
#define RS (BK+8)              // 40 elems = 80 B row stride (conflict-free)
#define STAGE_ELEMS (2*128*RS)
#define STAGE_BYTES (STAGE_ELEMS*2)        // 20480
#define GEMM_SMEM (STAGES*STAGE_BYTES)     // 81920 B -> 2 CTAs/SM

// Scratch (device globals; allocation-free contract)
__device__ __align__(256) float g_q[MTOT*DIM];
__device__ __align__(256) float g_k[MTOT*DIM];
__device__ __align__(256) float g_v[MTOT*DIM];
__device__ __align__(256) float g_kmean[BATCH*HEADS*HD];
// Activations: fp16 [hi | lo] (K=2048). Weights: single fp16 (K=1024).
__device__ __align__(256) __half g_x2[(size_t)MTOT*GK2];
__device__ __align__(256) __half g_att2[(size_t)MTOT*GK2];
__device__ __align__(256) __half g_wq1[(size_t)DIM*DIM];
__device__ __align__(256) __half g_wk1[(size_t)DIM*DIM];
__device__ __align__(256) __half g_wv1[(size_t)DIM*DIM];
__device__ __align__(256) __half g_wo1[(size_t)DIM*DIM];

// ---------------------------------------------------------------------------
// Non-arch-variant PTX helpers (compute_103-safe)
// ---------------------------------------------------------------------------
__device__ __forceinline__ uint32_t smem_u32(const void* p) {
    uint32_t a;
    asm("{ .reg .u64 t; cvta.to.shared.u64 t, %1; cvt.u32.u64 %0, t; }"
        : "=r"(a) : "l"(p));
    return a;
}
__device__ __forceinline__ void cp16(uint32_t dst, const void* src) {
    asm volatile("cp.async.cg.shared.global [%0], [%1], 16;"
                 :: "r"(dst), "l"(src));
}
#define CP_COMMIT() asm volatile("cp.async.commit_group;" ::: "memory")
#define CP_WAIT2()  asm volatile("cp.async.wait_group 2;" ::: "memory")

__device__ __forceinline__ void ldsm4(uint32_t* d, uint32_t addr) {
    asm volatile("ldmatrix.sync.aligned.m8n8.x4.shared.b16 {%0,%1,%2,%3}, [%4];"
                 : "=r"(d[0]), "=r"(d[1]), "=r"(d[2]), "=r"(d[3]) : "r"(addr));
}

__device__ __forceinline__ void mma_f16(float* c, const uint32_t* a,
                                        const uint32_t* b) {
    asm volatile(
        "mma.sync.aligned.m16n8k16.row.col.f32.f16.f16.f32 "
        "{%0,%1,%2,%3}, {%4,%5,%6,%7}, {%8,%9}, {%0,%1,%2,%3};"
        : "+f"(c[0]), "+f"(c[1]), "+f"(c[2]), "+f"(c[3])
        : "r"(a[0]), "r"(a[1]), "r"(a[2]), "r"(a[3]), "r"(b[0]), "r"(b[1]));
}

// ---------------------------------------------------------------------------
// Conversion. Activations: f = hi + lo, store [hi | lo]. Weights: hi only.
// ---------------------------------------------------------------------------
__global__ __launch_bounds__(256)
void convert_kernel(const float* __restrict__ x,  const float* __restrict__ wq,
                    const float* __restrict__ wk, const float* __restrict__ wv,
                    const float* __restrict__ wo) {
    int rid = blockIdx.x;
    const float* src; __half* dst; int row; int split;
    if      (rid < 4096) { src = x;  dst = g_x2;  row = rid;        split = 1; }
    else if (rid < 5120) { src = wq; dst = g_wq1; row = rid - 4096; split = 0; }
    else if (rid < 6144) { src = wk; dst = g_wk1; row = rid - 5120; split = 0; }
    else if (rid < 7168) { src = wv; dst = g_wv1; row = rid - 6144; split = 0; }
    else                 { src = wo; dst = g_wo1; row = rid - 7168; split = 0; }
    int c = threadIdx.x * 4;
    float4 f = *(const float4*)(src + (size_t)row * DIM + c);
    float fv[4] = {f.x, f.y, f.z, f.w};
    union { __half b[4]; uint2 u; } H, L;
#pragma unroll
    for (int i = 0; i < 4; i++) {
        __half h = __float2half(fv[i]);
        H.b[i] = h;
        L.b[i] = __float2half(fv[i] - __half2float(h));
    }
    if (split) {
        __half* r0 = dst + (size_t)row * GK2 + c;
        *(uint2*)(r0)       = H.u;
        *(uint2*)(r0 + DIM) = L.u;
    } else {
        *(uint2*)(dst + (size_t)row * DIM + c) = H.u;
    }
}

// ---------------------------------------------------------------------------
// HMMA GEMM, fp16 2-term split:
//   c in [0,32):  A hi * W      c in [32,64): A lo * W
// A stride GK2 (2048), B stride DIM (1024).
// ---------------------------------------------------------------------------
__device__ __forceinline__ void load_stage(uint32_t stg,
                                           const __half* __restrict__ Ag,
                                           const __half* __restrict__ Bg,
                                           int chunk, int tid) {
    const __half* Ac = Ag + chunk * BK;                 // hi then lo segments
    const __half* Bc = Bg + (chunk & 31) * BK;          // weight reused
#pragma unroll
    for (int i = 0; i < 2; i++) {
        int seg = tid + 256 * i;
        int r = seg >> 2, cs = seg & 3;
        cp16(stg + r * (RS*2) + cs * 16,
             (const char*)(Ac + (size_t)r * GK2) + cs * 16);
    }
#pragma unroll
    for (int i = 0; i < 2; i++) {
        int seg = tid + 256 * i;
        int r = seg >> 2, cs = seg & 3;
        cp16(stg + 128*(RS*2) + r * (RS*2) + cs * 16,
             (const char*)(Bc + (size_t)r * DIM) + cs * 16);
    }
}

__device__ __forceinline__ void mma_gemm(const __half* __restrict__ A2,
                                         const __half* __restrict__ B1,
                                         float* __restrict__ C) {
    extern __shared__ __align__(128) __half smem[];
    const uint32_t sb = smem_u32(smem);
    const int tid = threadIdx.x;
    const int lane = tid & 31, w = tid >> 5;
    const int wm = w >> 2, wn = w & 3;        // 2 x 4 warp grid
    const int g = lane >> 2, tg = lane & 3;   // epilogue mapping
    const int rowC = blockIdx.y * TM;
    const int colC = blockIdx.x * TN;
    const __half* Ag = A2 + (size_t)rowC * GK2;
    const __half* Bg = B1 + (size_t)colC * DIM;

    const int arow = wm * 64 + (lane & 15);
    const int acol = (lane >> 4) * 8;
    uint32_t a_rel[4];
#pragma unroll
    for (int mt = 0; mt < 4; mt++)
        a_rel[mt] = (uint32_t)(((arow + mt * 16) * RS + acol) * 2);
    const int brow = wn * 32 + (lane & 7) + ((lane >> 4) << 3);
    const int bcol = ((lane >> 3) & 1) * 8;
    uint32_t b_rel[2];
#pragma unroll
    for (int p = 0; p < 2; p++)
        b_rel[p] = (uint32_t)(((128 + brow + p * 16) * RS + bcol) * 2);

    float acc[4][4][4];
#pragma unroll
    for (int mt = 0; mt < 4; mt++)
#pragma unroll
        for (int nt = 0; nt < 4; nt++)
#pragma unroll
            for (int i = 0; i < 4; i++) acc[mt][nt][i] = 0.f;

#pragma unroll
    for (int s = 0; s < STAGES - 1; s++) {
        load_stage(sb + s * STAGE_BYTES, Ag, Bg, s, tid);
        CP_COMMIT();
    }

    for (int c = 0; c < NCHUNK; c++) {
        CP_WAIT2();
        __syncthreads();
        const uint32_t stg = sb + (uint32_t)(c & 3) * STAGE_BYTES;

        if (c + (STAGES - 1) < NCHUNK)
            load_stage(sb + (uint32_t)((c + STAGES - 1) & 3) * STAGE_BYTES,
                       Ag, Bg, c + STAGES - 1, tid);
        CP_COMMIT();

#pragma unroll
        for (int ks = 0; ks < 2; ks++) {
            const uint32_t ko = (uint32_t)(ks * 16 * 2);
            uint32_t a[4][4], b[2][4];
#pragma unroll
            for (int mt = 0; mt < 4; mt++) ldsm4(a[mt], stg + a_rel[mt] + ko);
#pragma unroll
            for (int p = 0; p < 2; p++)    ldsm4(b[p],  stg + b_rel[p] + ko);
#pragma unroll
            for (int mt = 0; mt < 4; mt++)
#pragma unroll
                for (int nt = 0; nt < 4; nt++)
                    mma_f16(acc[mt][nt], a[mt], &b[nt >> 1][(nt & 1) * 2]);
        }
    }

    // Epilogue: direct fp32 stores
#pragma unroll
    for (int mt = 0; mt < 4; mt++) {
        const int row = rowC + wm * 64 + mt * 16 + g;
#pragma unroll
        for (int nt = 0; nt < 4; nt++) {
            const int col = colC + wn * 32 + nt * 8 + tg * 2;
            *(float2*)(C + (size_t)row * DIM + col) =
                make_float2(acc[mt][nt][0], acc[mt][nt][1]);
            *(float2*)(C + (size_t)(row + 8) * DIM + col) =
                make_float2(acc[mt][nt][2], acc[mt][nt][3]);
        }
    }
}

__global__ __launch_bounds__(256, 2)
void qkv_mma_kernel() {
    const __half* W = (blockIdx.z == 0) ? g_wq1
                    : (blockIdx.z == 1) ? g_wk1 : g_wv1;
    float* C = (blockIdx.z == 0) ? g_q : (blockIdx.z == 1) ? g_k : g_v;
    mma_gemm(g_x2, W, C);
}

__global__ __launch_bounds__(256, 2)
void out_mma_kernel(float* __restrict__ out) {
    mma_gemm(g_att2, g_wo1, out);
}

// ---------------------------------------------------------------------------
// k_mean[b,h,d] = mean_l k[b,h,l,d]
// ---------------------------------------------------------------------------
__global__ __launch_bounds__(256)
void kmean_kernel() {
    __shared__ float red[256];
    const int bh = blockIdx.x;
    const int b = bh >> 4, h = bh & 15;
    const int d = threadIdx.x & 63, p = threadIdx.x >> 6;
    const float* base = g_k + (size_t)b * SEQ * DIM + h * HD + d;
    float s = 0.f;
    for (int l = p; l < SEQ; l += 4) s += base[(size_t)l * DIM];
    red[threadIdx.x] = s;
    __syncthreads();
    if (threadIdx.x < 64) {
        float t = red[d] + red[64 + d] + red[128 + d] + red[192 + d];
        g_kmean[bh * HD + d] = t * (1.f / (float)SEQ);
    }
}

// ---------------------------------------------------------------------------
// Fused windowed attention, register-GEMM formulation (proven layout).
// 256 threads as 16x16 grid. Score: each thread 4q x 8n. PV: 4q x 4d.
// ---------------------------------------------------------------------------
#define AQ_S 68    // Q row stride (floats)
#define AK_S 132   // Kt row stride
#define AV_S 68    // V row stride
#define AP_S 132   // P row stride
#define ATTN_SMEM ((64*AQ_S + 64*AK_S + 128*AV_S + 64*AP_S + 64) * 4)

__global__ void __launch_bounds__(256)
attn_kernel(const float* __restrict__ gsep,
            const float* __restrict__ galign,
            const float* __restrict__ gcoh) {
    extern __shared__ float sm[];
    float* Qs = sm;                    // [64][AQ_S]  q-major
    float* Kt = Qs + 64 * AQ_S;        // [64][AK_S]  d-major (transposed)
    float* Vs = Kt + 64 * AK_S;        // [128][AV_S] n-major
    float* Ps = Vs + 128 * AV_S;       // [64][AP_S]  q-major, pre-normalized
    float* km = Ps + 64 * AP_S;        // [64]

    const int t  = blockIdx.x;
    const int bh = blockIdx.y;
    const int b  = bh >> 4, h = bh & 15;
    const int tid = threadIdx.x;
    const int tx = tid & 15, ty = tid >> 4;
    const int base = t * 64 - 64;

    const float* Kg = g_k + (size_t)b * SEQ * DIM + h * HD;
    const float* Vg = g_v + (size_t)b * SEQ * DIM + h * HD;
    const float* Qg = g_q + (size_t)b * SEQ * DIM + h * HD;

    // Q: 64 rows x 16 float4 = 1024 f4, 4 per thread
#pragma unroll
    for (int it = 0; it < 4; it++) {
        int idx = tid + 256 * it;
        int r = idx >> 4, c4 = (idx & 15) * 4;
        *(float4*)(Qs + r * AQ_S + c4) =
            *(const float4*)(Qg + (size_t)(t * 64 + r) * DIM + c4);
    }
    // V: 128 rows x 16 f4 = 2048, 8 per thread
#pragma unroll
    for (int it = 0; it < 8; it++) {
        int idx = tid + 256 * it;
        int r = idx >> 4, c4 = (idx & 15) * 4;
        int j = base + r;
        float4 vv = make_float4(0.f, 0.f, 0.f, 0.f);
        if (j >= 0) vv = *(const float4*)(Vg + (size_t)j * DIM + c4);
        *(float4*)(Vs + r * AV_S + c4) = vv;
    }
    // K transposed: lane reads one row's 16B; STS.32 conflict-free
#pragma unroll
    for (int it = 0; it < 8; it++) {
        int idx = tid + 256 * it;
        int r = idx & 127, d0 = (idx >> 7) * 4;
        int j = base + r;
        float4 kv = make_float4(0.f, 0.f, 0.f, 0.f);
        if (j >= 0) kv = *(const float4*)(Kg + (size_t)j * DIM + d0);
        Kt[(d0 + 0) * AK_S + r] = kv.x;
        Kt[(d0 + 1) * AK_S + r] = kv.y;
        Kt[(d0 + 2) * AK_S + r] = kv.z;
        Kt[(d0 + 3) * AK_S + r] = kv.w;
    }
    if (tid < 64) km[tid] = g_kmean[bh * HD + tid];
    __syncthreads();

    // ---- Score GEMM: S[4q][8n] per thread, plus pm = q . kmean ----
    float acc[4][8];
    float pm[4] = {0.f, 0.f, 0.f, 0.f};
#pragma unroll
    for (int qj = 0; qj < 4; qj++)
#pragma unroll
        for (int nj = 0; nj < 8; nj++) acc[qj][nj] = 0.f;

#pragma unroll 4
    for (int d = 0; d < 64; d++) {
        float4 k0 = *(const float4*)(Kt + d * AK_S + tx * 8);
        float4 k1 = *(const float4*)(Kt + d * AK_S + tx * 8 + 4);
        const float kvs[8] = {k0.x, k0.y, k0.z, k0.w, k1.x, k1.y, k1.z, k1.w};
        const float kmd = km[d];
#pragma unroll
        for (int qj = 0; qj < 4; qj++) {
            const float qv = Qs[(ty * 4 + qj) * AQ_S + d];
            pm[qj] = fmaf(qv, kmd, pm[qj]);
#pragma unroll
            for (int nj = 0; nj < 8; nj++)
                acc[qj][nj] = fmaf(qv, kvs[nj], acc[qj][nj]);
        }
    }

    // ---- Reynolds + mask + softmax (row reductions across tx half-warp) ----
    const float sep = *gsep, alg = *galign, coh = *gcoh;
#pragma unroll
    for (int qj = 0; qj < 4; qj++) {
        const int qi = ty * 4 + qj;
        const float mi = pm[qj] * 0.125f;
        float s2[8];
        float mx = -1e30f;
#pragma unroll
        for (int nj = 0; nj < 8; nj++) {
            const int n = tx * 8 + nj;
            const float s = acc[qj][nj] * 0.125f;
            const float sim = 1.f / (1.f + __expf(-s));
            const float v = s + alg * s - sep * sim * sim - coh * fabsf(s - mi);
            const bool ok = (n >= qi + 1) && (n <= qi + 64) && (base + n >= 0);
            s2[nj] = ok ? v : -1e30f;
            mx = fmaxf(mx, s2[nj]);
        }
#pragma unroll
        for (int o = 1; o < 16; o <<= 1)
            mx = fmaxf(mx, __shfl_xor_sync(0xffffffffu, mx, o));
        float e[8];
        float sum = 0.f;
#pragma unroll
        for (int nj = 0; nj < 8; nj++) {
            e[nj] = (s2[nj] > -1e29f) ? __expf(s2[nj] - mx) : 0.f;
            sum += e[nj];
        }
#pragma unroll
        for (int o = 1; o < 16; o <<= 1)
            sum += __shfl_xor_sync(0xffffffffu, sum, o);
        const float inv = 1.f / sum;
        *(float4*)(Ps + qi * AP_S + tx * 8) =
            make_float4(e[0]*inv, e[1]*inv, e[2]*inv, e[3]*inv);
        *(float4*)(Ps + qi * AP_S + tx * 8 + 4) =
            make_float4(e[4]*inv, e[5]*inv, e[6]*inv, e[7]*inv);
    }
    __syncthreads();

    // ---- PV GEMM: O[4q][4d] per thread ----
    float o[4][4];
#pragma unroll
    for (int qj = 0; qj < 4; qj++)
#pragma unroll
        for (int dj = 0; dj < 4; dj++) o[qj][dj] = 0.f;

#pragma unroll 4
    for (int n = 0; n < 128; n++) {
        float4 vv = *(const float4*)(Vs + n * AV_S + tx * 4);
        const float vs[4] = {vv.x, vv.y, vv.z, vv.w};
#pragma unroll
        for (int qj = 0; qj < 4; qj++) {
            const float p = Ps[(ty * 4 + qj) * AP_S + n];
#pragma unroll
            for (int dj = 0; dj < 4; dj++)
                o[qj][dj] = fmaf(p, vs[dj], o[qj][dj]);
        }
    }

    // ---- Epilogue: write fp16 [hi | lo] split ----
#pragma unroll
    for (int qj = 0; qj < 4; qj++) {
        const int i = t * 64 + ty * 4 + qj;
        const size_t rb = ((size_t)b * SEQ + i) * GK2 + h * HD + tx * 4;
        union { __half v[4]; uint2 u; } Hh, Ll;
#pragma unroll
        for (int dj = 0; dj < 4; dj++) {
            __half hb = __float2half(o[qj][dj]);
            Hh.v[dj] = hb;
            Ll.v[dj] = __float2half(o[qj][dj] - __half2float(hb));
        }
        *(uint2*)(g_att2 + rb)       = Hh.u;
        *(uint2*)(g_att2 + rb + DIM) = Ll.u;
    }
}

// ---------------------------------------------------------------------------
extern "C" void kernel_launch(void* const* d_in, const int* in_sizes, int n_in,
                              void* d_out, int out_size) {
    const float* x    = (const float*)d_in[0];
    const float* Wq   = (const float*)d_in[1];
    const float* Wk   = (const float*)d_in[2];
    const float* Wv   = (const float*)d_in[3];
    const float* Wo   = (const float*)d_in[4];
    const float* gsep = (const float*)d_in[5];
    const float* galn = (const float*)d_in[6];
    const float* gcoh = (const float*)d_in[7];
    float* out = (float*)d_out;

    cudaFuncSetAttribute(qkv_mma_kernel,
                         cudaFuncAttributeMaxDynamicSharedMemorySize, GEMM_SMEM);
    cudaFuncSetAttribute(out_mma_kernel,
                         cudaFuncAttributeMaxDynamicSharedMemorySize, GEMM_SMEM);
    cudaFuncSetAttribute(attn_kernel,
                         cudaFuncAttributeMaxDynamicSharedMemorySize, ATTN_SMEM);

    convert_kernel<<<8192, 256>>>(x, Wq, Wk, Wv, Wo);

    dim3 gqkv(DIM / TN, MTOT / TM, 3);
    qkv_mma_kernel<<<gqkv, 256, GEMM_SMEM>>>();

    kmean_kernel<<<BATCH * HEADS, 256>>>();

    dim3 gatt(SEQ / 64, BATCH * HEADS);
    attn_kernel<<<gatt, 256, ATTN_SMEM>>>(gsep, galn, gcoh);

    dim3 gout(DIM / TN, MTOT / TM);
    out_mma_kernel<<<gout, 256, GEMM_SMEM>>>(out);
}

// round 10
// speedup vs baseline: 3.9581x; 1.0544x over previous
#include <cuda_runtime.h>
#include <cuda_fp16.h>
#include <math.h>
#include <stdint.h>

// Problem constants
#define BATCH 2
#define SEQ   2048
#define DIM   1024
#define HEADS 16
#define HD    64
#define MTOT  (BATCH*SEQ)      // 4096
#define GK2   (2*DIM)          // activation [hi | lo] storage: 2048

// GEMM tiling: 2-term fp16 split. Logical K = 2048 (A: hi then lo segments,
// B: the single fp16 weight tile reused for both segments).
#define TM 128
#define TN 128
#define BK 32
#define NCHUNK 64              // 64 logical chunks: c<32 hi*W, c>=32 lo*W
#define STAGES 4
#define RS (BK+8)              // 40 elems = 80 B row stride (conflict-free)
#define STAGE_ELEMS (2*128*RS)
#define STAGE_BYTES (STAGE_ELEMS*2)        // 20480
#define GEMM_SMEM (STAGES*STAGE_BYTES)     // 81920 B -> 2 CTAs/SM

// Scratch (device globals; allocation-free contract)
__device__ __align__(256) float g_q[MTOT*DIM];
__device__ __align__(256) float g_k[MTOT*DIM];
__device__ __align__(256) float g_v[MTOT*DIM];
__device__ __align__(256) float g_kmean[BATCH*HEADS*HD];
// Activations: fp16 [hi | lo] (K=2048). Weights: single fp16 (K=1024).
__device__ __align__(256) __half g_x2[(size_t)MTOT*GK2];
__device__ __align__(256) __half g_att2[(size_t)MTOT*GK2];
__device__ __align__(256) __half g_wq1[(size_t)DIM*DIM];
__device__ __align__(256) __half g_wk1[(size_t)DIM*DIM];
__device__ __align__(256) __half g_wv1[(size_t)DIM*DIM];
__device__ __align__(256) __half g_wo1[(size_t)DIM*DIM];

// ---------------------------------------------------------------------------
// Non-arch-variant PTX helpers (compute_103-safe)
// ---------------------------------------------------------------------------
__device__ __forceinline__ uint32_t smem_u32(const void* p) {
    uint32_t a;
    asm("{ .reg .u64 t; cvta.to.shared.u64 t, %1; cvt.u32.u64 %0, t; }"
        : "=r"(a) : "l"(p));
    return a;
}
__device__ __forceinline__ void cp16(uint32_t dst, const void* src) {
    asm volatile("cp.async.cg.shared.global [%0], [%1], 16;"
                 :: "r"(dst), "l"(src));
}
#define CP_COMMIT() asm volatile("cp.async.commit_group;" ::: "memory")
#define CP_WAIT2()  asm volatile("cp.async.wait_group 2;" ::: "memory")

__device__ __forceinline__ void ldsm4(uint32_t* d, uint32_t addr) {
    asm volatile("ldmatrix.sync.aligned.m8n8.x4.shared.b16 {%0,%1,%2,%3}, [%4];"
                 : "=r"(d[0]), "=r"(d[1]), "=r"(d[2]), "=r"(d[3]) : "r"(addr));
}

__device__ __forceinline__ void mma_f16(float* c, const uint32_t* a,
                                        const uint32_t* b) {
    asm volatile(
        "mma.sync.aligned.m16n8k16.row.col.f32.f16.f16.f32 "
        "{%0,%1,%2,%3}, {%4,%5,%6,%7}, {%8,%9}, {%0,%1,%2,%3};"
        : "+f"(c[0]), "+f"(c[1]), "+f"(c[2]), "+f"(c[3])
        : "r"(a[0]), "r"(a[1]), "r"(a[2]), "r"(a[3]), "r"(b[0]), "r"(b[1]));
}

// ---------------------------------------------------------------------------
// Conversion. Activations: f = hi + lo, store [hi | lo]. Weights: hi only.
// ---------------------------------------------------------------------------
__global__ __launch_bounds__(256)
void convert_kernel(const float* __restrict__ x,  const float* __restrict__ wq,
                    const float* __restrict__ wk, const float* __restrict__ wv,
                    const float* __restrict__ wo) {
    int rid = blockIdx.x;
    const float* src; __half* dst; int row; int split;
    if      (rid < 4096) { src = x;  dst = g_x2;  row = rid;        split = 1; }
    else if (rid < 5120) { src = wq; dst = g_wq1; row = rid - 4096; split = 0; }
    else if (rid < 6144) { src = wk; dst = g_wk1; row = rid - 5120; split = 0; }
    else if (rid < 7168) { src = wv; dst = g_wv1; row = rid - 6144; split = 0; }
    else                 { src = wo; dst = g_wo1; row = rid - 7168; split = 0; }
    int c = threadIdx.x * 4;
    float4 f = *(const float4*)(src + (size_t)row * DIM + c);
    float fv[4] = {f.x, f.y, f.z, f.w};
    union { __half b[4]; uint2 u; } H, L;
#pragma unroll
    for (int i = 0; i < 4; i++) {
        __half h = __float2half(fv[i]);
        H.b[i] = h;
        L.b[i] = __float2half(fv[i] - __half2float(h));
    }
    if (split) {
        __half* r0 = dst + (size_t)row * GK2 + c;
        *(uint2*)(r0)       = H.u;
        *(uint2*)(r0 + DIM) = L.u;
    } else {
        *(uint2*)(dst + (size_t)row * DIM + c) = H.u;
    }
}

// ---------------------------------------------------------------------------
// HMMA GEMM, fp16 2-term split:
//   c in [0,32):  A hi * W      c in [32,64): A lo * W
// ---------------------------------------------------------------------------
__device__ __forceinline__ void load_stage(uint32_t stg,
                                           const __half* __restrict__ Ag,
                                           const __half* __restrict__ Bg,
                                           int chunk, int tid) {
    const __half* Ac = Ag + chunk * BK;                 // hi then lo segments
    const __half* Bc = Bg + (chunk & 31) * BK;          // weight reused
#pragma unroll
    for (int i = 0; i < 2; i++) {
        int seg = tid + 256 * i;
        int r = seg >> 2, cs = seg & 3;
        cp16(stg + r * (RS*2) + cs * 16,
             (const char*)(Ac + (size_t)r * GK2) + cs * 16);
    }
#pragma unroll
    for (int i = 0; i < 2; i++) {
        int seg = tid + 256 * i;
        int r = seg >> 2, cs = seg & 3;
        cp16(stg + 128*(RS*2) + r * (RS*2) + cs * 16,
             (const char*)(Bc + (size_t)r * DIM) + cs * 16);
    }
}

__device__ __forceinline__ void mma_gemm(const __half* __restrict__ A2,
                                         const __half* __restrict__ B1,
                                         float* __restrict__ C) {
    extern __shared__ __align__(128) __half smem[];
    const uint32_t sb = smem_u32(smem);
    const int tid = threadIdx.x;
    const int lane = tid & 31, w = tid >> 5;
    const int wm = w >> 2, wn = w & 3;        // 2 x 4 warp grid
    const int g = lane >> 2, tg = lane & 3;   // epilogue mapping
    const int rowC = blockIdx.y * TM;
    const int colC = blockIdx.x * TN;
    const __half* Ag = A2 + (size_t)rowC * GK2;
    const __half* Bg = B1 + (size_t)colC * DIM;

    const int arow = wm * 64 + (lane & 15);
    const int acol = (lane >> 4) * 8;
    uint32_t a_rel[4];
#pragma unroll
    for (int mt = 0; mt < 4; mt++)
        a_rel[mt] = (uint32_t)(((arow + mt * 16) * RS + acol) * 2);
    const int brow = wn * 32 + (lane & 7) + ((lane >> 4) << 3);
    const int bcol = ((lane >> 3) & 1) * 8;
    uint32_t b_rel[2];
#pragma unroll
    for (int p = 0; p < 2; p++)
        b_rel[p] = (uint32_t)(((128 + brow + p * 16) * RS + bcol) * 2);

    float acc[4][4][4];
#pragma unroll
    for (int mt = 0; mt < 4; mt++)
#pragma unroll
        for (int nt = 0; nt < 4; nt++)
#pragma unroll
            for (int i = 0; i < 4; i++) acc[mt][nt][i] = 0.f;

#pragma unroll
    for (int s = 0; s < STAGES - 1; s++) {
        load_stage(sb + s * STAGE_BYTES, Ag, Bg, s, tid);
        CP_COMMIT();
    }

    for (int c = 0; c < NCHUNK; c++) {
        CP_WAIT2();
        __syncthreads();
        const uint32_t stg = sb + (uint32_t)(c & 3) * STAGE_BYTES;

        if (c + (STAGES - 1) < NCHUNK)
            load_stage(sb + (uint32_t)((c + STAGES - 1) & 3) * STAGE_BYTES,
                       Ag, Bg, c + STAGES - 1, tid);
        CP_COMMIT();

#pragma unroll
        for (int ks = 0; ks < 2; ks++) {
            const uint32_t ko = (uint32_t)(ks * 16 * 2);
            uint32_t a[4][4], b[2][4];
#pragma unroll
            for (int mt = 0; mt < 4; mt++) ldsm4(a[mt], stg + a_rel[mt] + ko);
#pragma unroll
            for (int p = 0; p < 2; p++)    ldsm4(b[p],  stg + b_rel[p] + ko);
#pragma unroll
            for (int mt = 0; mt < 4; mt++)
#pragma unroll
                for (int nt = 0; nt < 4; nt++)
                    mma_f16(acc[mt][nt], a[mt], &b[nt >> 1][(nt & 1) * 2]);
        }
    }

    // Epilogue: direct fp32 stores
#pragma unroll
    for (int mt = 0; mt < 4; mt++) {
        const int row = rowC + wm * 64 + mt * 16 + g;
#pragma unroll
        for (int nt = 0; nt < 4; nt++) {
            const int col = colC + wn * 32 + nt * 8 + tg * 2;
            *(float2*)(C + (size_t)row * DIM + col) =
                make_float2(acc[mt][nt][0], acc[mt][nt][1]);
            *(float2*)(C + (size_t)(row + 8) * DIM + col) =
                make_float2(acc[mt][nt][2], acc[mt][nt][3]);
        }
    }
}

__global__ __launch_bounds__(256, 2)
void qkv_mma_kernel() {
    const __half* W = (blockIdx.z == 0) ? g_wq1
                    : (blockIdx.z == 1) ? g_wk1 : g_wv1;
    float* C = (blockIdx.z == 0) ? g_q : (blockIdx.z == 1) ? g_k : g_v;
    mma_gemm(g_x2, W, C);
}

__global__ __launch_bounds__(256, 2)
void out_mma_kernel(float* __restrict__ out) {
    mma_gemm(g_att2, g_wo1, out);
}

// ---------------------------------------------------------------------------
// k_mean[b,h,d] = mean_l k[b,h,l,d]
// ---------------------------------------------------------------------------
__global__ __launch_bounds__(256)
void kmean_kernel() {
    __shared__ float red[256];
    const int bh = blockIdx.x;
    const int b = bh >> 4, h = bh & 15;
    const int d = threadIdx.x & 63, p = threadIdx.x >> 6;
    const float* base = g_k + (size_t)b * SEQ * DIM + h * HD + d;
    float s = 0.f;
    for (int l = p; l < SEQ; l += 4) s += base[(size_t)l * DIM];
    red[threadIdx.x] = s;
    __syncthreads();
    if (threadIdx.x < 64) {
        float t = red[d] + red[64 + d] + red[128 + d] + red[192 + d];
        g_kmean[bh * HD + d] = t * (1.f / (float)SEQ);
    }
}

// ---------------------------------------------------------------------------
// Fused windowed attention, register-GEMM formulation.
// Tight strides + P aliased onto dead Kt region -> 82.2 KB -> 2 CTAs/SM.
// 256 threads as 16x16 grid. Score: each thread 4q x 8n. PV: 4q x 4d.
// ---------------------------------------------------------------------------
#define AQ_S 64    // Q row stride (floats)
#define AK_S 128   // Kt row stride; region reused for P after score phase
#define AV_S 64    // V row stride
#define ATTN_SMEM ((64*AQ_S + 64*AK_S + 128*AV_S + 64) * 4)   // 82176 B

__global__ void __launch_bounds__(256, 2)
attn_kernel(const float* __restrict__ gsep,
            const float* __restrict__ galign,
            const float* __restrict__ gcoh) {
    extern __shared__ float sm[];
    float* Qs = sm;                    // [64][AQ_S]  q-major
    float* Kt = Qs + 64 * AQ_S;        // [64][AK_S]  d-major; becomes P later
    float* Vs = Kt + 64 * AK_S;        // [128][AV_S] n-major
    float* km = Vs + 128 * AV_S;       // [64]

    const int t  = blockIdx.x;
    const int bh = blockIdx.y;
    const int b  = bh >> 4, h = bh & 15;
    const int tid = threadIdx.x;
    const int tx = tid & 15, ty = tid >> 4;
    const int base = t * 64 - 64;

    const float* Kg = g_k + (size_t)b * SEQ * DIM + h * HD;
    const float* Vg = g_v + (size_t)b * SEQ * DIM + h * HD;
    const float* Qg = g_q + (size_t)b * SEQ * DIM + h * HD;

    // Q: 64 rows x 16 float4 = 1024 f4, 4 per thread
#pragma unroll
    for (int it = 0; it < 4; it++) {
        int idx = tid + 256 * it;
        int r = idx >> 4, c4 = (idx & 15) * 4;
        *(float4*)(Qs + r * AQ_S + c4) =
            *(const float4*)(Qg + (size_t)(t * 64 + r) * DIM + c4);
    }
    // V: 128 rows x 16 f4 = 2048, 8 per thread
#pragma unroll
    for (int it = 0; it < 8; it++) {
        int idx = tid + 256 * it;
        int r = idx >> 4, c4 = (idx & 15) * 4;
        int j = base + r;
        float4 vv = make_float4(0.f, 0.f, 0.f, 0.f);
        if (j >= 0) vv = *(const float4*)(Vg + (size_t)j * DIM + c4);
        *(float4*)(Vs + r * AV_S + c4) = vv;
    }
    // K transposed: lane reads one row's 16B; STS.32 conflict-free
#pragma unroll
    for (int it = 0; it < 8; it++) {
        int idx = tid + 256 * it;
        int r = idx & 127, d0 = (idx >> 7) * 4;
        int j = base + r;
        float4 kv = make_float4(0.f, 0.f, 0.f, 0.f);
        if (j >= 0) kv = *(const float4*)(Kg + (size_t)j * DIM + d0);
        Kt[(d0 + 0) * AK_S + r] = kv.x;
        Kt[(d0 + 1) * AK_S + r] = kv.y;
        Kt[(d0 + 2) * AK_S + r] = kv.z;
        Kt[(d0 + 3) * AK_S + r] = kv.w;
    }
    if (tid < 64) km[tid] = g_kmean[bh * HD + tid];
    __syncthreads();

    // ---- Score GEMM: S[4q][8n] per thread, plus pm = q . kmean ----
    float acc[4][8];
    float pm[4] = {0.f, 0.f, 0.f, 0.f};
#pragma unroll
    for (int qj = 0; qj < 4; qj++)
#pragma unroll
        for (int nj = 0; nj < 8; nj++) acc[qj][nj] = 0.f;

#pragma unroll 4
    for (int d = 0; d < 64; d++) {
        float4 k0 = *(const float4*)(Kt + d * AK_S + tx * 8);
        float4 k1 = *(const float4*)(Kt + d * AK_S + tx * 8 + 4);
        const float kvs[8] = {k0.x, k0.y, k0.z, k0.w, k1.x, k1.y, k1.z, k1.w};
        const float kmd = km[d];
#pragma unroll
        for (int qj = 0; qj < 4; qj++) {
            const float qv = Qs[(ty * 4 + qj) * AQ_S + d];
            pm[qj] = fmaf(qv, kmd, pm[qj]);
#pragma unroll
            for (int nj = 0; nj < 8; nj++)
                acc[qj][nj] = fmaf(qv, kvs[nj], acc[qj][nj]);
        }
    }

    // ---- Reynolds + mask + softmax; normalized weights back into acc ----
    const float sep = *gsep, alg = *galign, coh = *gcoh;
#pragma unroll
    for (int qj = 0; qj < 4; qj++) {
        const int qi = ty * 4 + qj;
        const float mi = pm[qj] * 0.125f;
        float s2[8];
        float mx = -1e30f;
#pragma unroll
        for (int nj = 0; nj < 8; nj++) {
            const int n = tx * 8 + nj;
            const float s = acc[qj][nj] * 0.125f;
            const float sim = 1.f / (1.f + __expf(-s));
            const float v = s + alg * s - sep * sim * sim - coh * fabsf(s - mi);
            const bool ok = (n >= qi + 1) && (n <= qi + 64) && (base + n >= 0);
            s2[nj] = ok ? v : -1e30f;
            mx = fmaxf(mx, s2[nj]);
        }
#pragma unroll
        for (int o = 1; o < 16; o <<= 1)
            mx = fmaxf(mx, __shfl_xor_sync(0xffffffffu, mx, o));
        float sum = 0.f;
#pragma unroll
        for (int nj = 0; nj < 8; nj++) {
            acc[qj][nj] = (s2[nj] > -1e29f) ? __expf(s2[nj] - mx) : 0.f;
            sum += acc[qj][nj];
        }
#pragma unroll
        for (int o = 1; o < 16; o <<= 1)
            sum += __shfl_xor_sync(0xffffffffu, sum, o);
        const float inv = 1.f / sum;
#pragma unroll
        for (int nj = 0; nj < 8; nj++) acc[qj][nj] *= inv;
    }

    // ---- All Kt reads complete across the CTA; reuse Kt region for P ----
    __syncthreads();
    float* Ps = Kt;     // [64 q][AK_S=128 n]
#pragma unroll
    for (int qj = 0; qj < 4; qj++) {
        const int qi = ty * 4 + qj;
        *(float4*)(Ps + qi * AK_S + tx * 8) =
            make_float4(acc[qj][0], acc[qj][1], acc[qj][2], acc[qj][3]);
        *(float4*)(Ps + qi * AK_S + tx * 8 + 4) =
            make_float4(acc[qj][4], acc[qj][5], acc[qj][6], acc[qj][7]);
    }
    __syncthreads();

    // ---- PV GEMM: O[4q][4d] per thread ----
    float o[4][4];
#pragma unroll
    for (int qj = 0; qj < 4; qj++)
#pragma unroll
        for (int dj = 0; dj < 4; dj++) o[qj][dj] = 0.f;

#pragma unroll 4
    for (int n = 0; n < 128; n++) {
        float4 vv = *(const float4*)(Vs + n * AV_S + tx * 4);
        const float vs[4] = {vv.x, vv.y, vv.z, vv.w};
#pragma unroll
        for (int qj = 0; qj < 4; qj++) {
            const float p = Ps[(ty * 4 + qj) * AK_S + n];
#pragma unroll
            for (int dj = 0; dj < 4; dj++)
                o[qj][dj] = fmaf(p, vs[dj], o[qj][dj]);
        }
    }

    // ---- Epilogue: write fp16 [hi | lo] split ----
#pragma unroll
    for (int qj = 0; qj < 4; qj++) {
        const int i = t * 64 + ty * 4 + qj;
        const size_t rb = ((size_t)b * SEQ + i) * GK2 + h * HD + tx * 4;
        union { __half v[4]; uint2 u; } Hh, Ll;
#pragma unroll
        for (int dj = 0; dj < 4; dj++) {
            __half hb = __float2half(o[qj][dj]);
            Hh.v[dj] = hb;
            Ll.v[dj] = __float2half(o[qj][dj] - __half2float(hb));
        }
        *(uint2*)(g_att2 + rb)       = Hh.u;
        *(uint2*)(g_att2 + rb + DIM) = Ll.u;
    }
}

// ---------------------------------------------------------------------------
extern "C" void kernel_launch(void* const* d_in, const int* in_sizes, int n_in,
                              void* d_out, int out_size) {
    const float* x    = (const float*)d_in[0];
    const float* Wq   = (const float*)d_in[1];
    const float* Wk   = (const float*)d_in[2];
    const float* Wv   = (const float*)d_in[3];
    const float* Wo   = (const float*)d_in[4];
    const float* gsep = (const float*)d_in[5];
    const float* galn = (const float*)d_in[6];
    const float* gcoh = (const float*)d_in[7];
    float* out = (float*)d_out;

    cudaFuncSetAttribute(qkv_mma_kernel,
                         cudaFuncAttributeMaxDynamicSharedMemorySize, GEMM_SMEM);
    cudaFuncSetAttribute(out_mma_kernel,
                         cudaFuncAttributeMaxDynamicSharedMemorySize, GEMM_SMEM);
    cudaFuncSetAttribute(attn_kernel,
                         cudaFuncAttributeMaxDynamicSharedMemorySize, ATTN_SMEM);

    convert_kernel<<<8192, 256>>>(x, Wq, Wk, Wv, Wo);

    dim3 gqkv(DIM / TN, MTOT / TM, 3);
    qkv_mma_kernel<<<gqkv, 256, GEMM_SMEM>>>();

    kmean_kernel<<<BATCH * HEADS, 256>>>();

    dim3 gatt(SEQ / 64, BATCH * HEADS);
    attn_kernel<<<gatt, 256, ATTN_SMEM>>>(gsep, galn, gcoh);

    dim3 gout(DIM / TN, MTOT / TM);
    out_mma_kernel<<<gout, 256, GEMM_SMEM>>>(out);
}

// round 11
// speedup vs baseline: 5.9198x; 1.4956x over previous
#include <cuda_runtime.h>
#include <cuda_fp16.h>
#include <math.h>
#include <stdint.h>

// Problem constants
#define BATCH 2
#define SEQ   2048
#define DIM   1024
#define HEADS 16
#define HD    64
#define MTOT  (BATCH*SEQ)      // 4096

// GEMM tiling: plain fp16 GEMM, K = 1024.
#define TM 128
#define TN 128
#define BK 32
#define NCHUNK (DIM/BK)        // 32
#define STAGES 4
#define RS (BK+8)              // 40 elems = 80 B row stride (conflict-free)
#define STAGE_ELEMS (2*128*RS)
#define STAGE_BYTES (STAGE_ELEMS*2)        // 20480
#define GEMM_SMEM (STAGES*STAGE_BYTES)     // 81920 B -> 2 CTAs/SM

// Scratch (device globals; allocation-free contract)
__device__ __align__(256) float g_q[MTOT*DIM];
__device__ __align__(256) float g_k[MTOT*DIM];
__device__ __align__(256) float g_v[MTOT*DIM];
__device__ __align__(256) float g_kmean[BATCH*HEADS*HD];
__device__ __align__(256) __half g_x1[(size_t)MTOT*DIM];
__device__ __align__(256) __half g_att1[(size_t)MTOT*DIM];
__device__ __align__(256) __half g_wq1[(size_t)DIM*DIM];
__device__ __align__(256) __half g_wk1[(size_t)DIM*DIM];
__device__ __align__(256) __half g_wv1[(size_t)DIM*DIM];
__device__ __align__(256) __half g_wo1[(size_t)DIM*DIM];

// ---------------------------------------------------------------------------
// Non-arch-variant PTX helpers (compute_103-safe)
// ---------------------------------------------------------------------------
__device__ __forceinline__ uint32_t smem_u32(const void* p) {
    uint32_t a;
    asm("{ .reg .u64 t; cvta.to.shared.u64 t, %1; cvt.u32.u64 %0, t; }"
        : "=r"(a) : "l"(p));
    return a;
}
__device__ __forceinline__ void cp16(uint32_t dst, const void* src) {
    asm volatile("cp.async.cg.shared.global [%0], [%1], 16;"
                 :: "r"(dst), "l"(src));
}
#define CP_COMMIT() asm volatile("cp.async.commit_group;" ::: "memory")
#define CP_WAIT2()  asm volatile("cp.async.wait_group 2;" ::: "memory")

__device__ __forceinline__ void ldsm4(uint32_t* d, uint32_t addr) {
    asm volatile("ldmatrix.sync.aligned.m8n8.x4.shared.b16 {%0,%1,%2,%3}, [%4];"
                 : "=r"(d[0]), "=r"(d[1]), "=r"(d[2]), "=r"(d[3]) : "r"(addr));
}

__device__ __forceinline__ void mma_f16(float* c, const uint32_t* a,
                                        const uint32_t* b) {
    asm volatile(
        "mma.sync.aligned.m16n8k16.row.col.f32.f16.f16.f32 "
        "{%0,%1,%2,%3}, {%4,%5,%6,%7}, {%8,%9}, {%0,%1,%2,%3};"
        : "+f"(c[0]), "+f"(c[1]), "+f"(c[2]), "+f"(c[3])
        : "r"(a[0]), "r"(a[1]), "r"(a[2]), "r"(a[3]), "r"(b[0]), "r"(b[1]));
}

// ---------------------------------------------------------------------------
// fp16 conversion (no split).
// ---------------------------------------------------------------------------
__global__ __launch_bounds__(256)
void convert_kernel(const float* __restrict__ x,  const float* __restrict__ wq,
                    const float* __restrict__ wk, const float* __restrict__ wv,
                    const float* __restrict__ wo) {
    int rid = blockIdx.x;
    const float* src; __half* dst; int row;
    if      (rid < 4096) { src = x;  dst = g_x1;  row = rid;        }
    else if (rid < 5120) { src = wq; dst = g_wq1; row = rid - 4096; }
    else if (rid < 6144) { src = wk; dst = g_wk1; row = rid - 5120; }
    else if (rid < 7168) { src = wv; dst = g_wv1; row = rid - 6144; }
    else                 { src = wo; dst = g_wo1; row = rid - 7168; }
    int c = threadIdx.x * 4;
    float4 f = *(const float4*)(src + (size_t)row * DIM + c);
    union { __half b[4]; uint2 u; } H;
    H.b[0] = __float2half(f.x); H.b[1] = __float2half(f.y);
    H.b[2] = __float2half(f.z); H.b[3] = __float2half(f.w);
    *(uint2*)(dst + (size_t)row * DIM + c) = H.u;
}

// ---------------------------------------------------------------------------
// Plain fp16 HMMA GEMM: C[4096,1024] = A[4096,1024] @ B[1024,1024]^T (f32 acc)
// ---------------------------------------------------------------------------
__device__ __forceinline__ void load_stage(uint32_t stg,
                                           const __half* __restrict__ Ag,
                                           const __half* __restrict__ Bg,
                                           int chunk, int tid) {
    const __half* Ac = Ag + chunk * BK;
    const __half* Bc = Bg + chunk * BK;
#pragma unroll
    for (int i = 0; i < 2; i++) {
        int seg = tid + 256 * i;
        int r = seg >> 2, cs = seg & 3;
        cp16(stg + r * (RS*2) + cs * 16,
             (const char*)(Ac + (size_t)r * DIM) + cs * 16);
    }
#pragma unroll
    for (int i = 0; i < 2; i++) {
        int seg = tid + 256 * i;
        int r = seg >> 2, cs = seg & 3;
        cp16(stg + 128*(RS*2) + r * (RS*2) + cs * 16,
             (const char*)(Bc + (size_t)r * DIM) + cs * 16);
    }
}

__device__ __forceinline__ void mma_gemm(const __half* __restrict__ A1,
                                         const __half* __restrict__ B1,
                                         float* __restrict__ C) {
    extern __shared__ __align__(128) __half smem[];
    const uint32_t sb = smem_u32(smem);
    const int tid = threadIdx.x;
    const int lane = tid & 31, w = tid >> 5;
    const int wm = w >> 2, wn = w & 3;        // 2 x 4 warp grid
    const int g = lane >> 2, tg = lane & 3;   // epilogue mapping
    const int rowC = blockIdx.y * TM;
    const int colC = blockIdx.x * TN;
    const __half* Ag = A1 + (size_t)rowC * DIM;
    const __half* Bg = B1 + (size_t)colC * DIM;

    const int arow = wm * 64 + (lane & 15);
    const int acol = (lane >> 4) * 8;
    uint32_t a_rel[4];
#pragma unroll
    for (int mt = 0; mt < 4; mt++)
        a_rel[mt] = (uint32_t)(((arow + mt * 16) * RS + acol) * 2);
    const int brow = wn * 32 + (lane & 7) + ((lane >> 4) << 3);
    const int bcol = ((lane >> 3) & 1) * 8;
    uint32_t b_rel[2];
#pragma unroll
    for (int p = 0; p < 2; p++)
        b_rel[p] = (uint32_t)(((128 + brow + p * 16) * RS + bcol) * 2);

    float acc[4][4][4];
#pragma unroll
    for (int mt = 0; mt < 4; mt++)
#pragma unroll
        for (int nt = 0; nt < 4; nt++)
#pragma unroll
            for (int i = 0; i < 4; i++) acc[mt][nt][i] = 0.f;

#pragma unroll
    for (int s = 0; s < STAGES - 1; s++) {
        load_stage(sb + s * STAGE_BYTES, Ag, Bg, s, tid);
        CP_COMMIT();
    }

    for (int c = 0; c < NCHUNK; c++) {
        CP_WAIT2();
        __syncthreads();
        const uint32_t stg = sb + (uint32_t)(c & 3) * STAGE_BYTES;

        if (c + (STAGES - 1) < NCHUNK)
            load_stage(sb + (uint32_t)((c + STAGES - 1) & 3) * STAGE_BYTES,
                       Ag, Bg, c + STAGES - 1, tid);
        CP_COMMIT();

#pragma unroll
        for (int ks = 0; ks < 2; ks++) {
            const uint32_t ko = (uint32_t)(ks * 16 * 2);
            uint32_t a[4][4], b[2][4];
#pragma unroll
            for (int mt = 0; mt < 4; mt++) ldsm4(a[mt], stg + a_rel[mt] + ko);
#pragma unroll
            for (int p = 0; p < 2; p++)    ldsm4(b[p],  stg + b_rel[p] + ko);
#pragma unroll
            for (int mt = 0; mt < 4; mt++)
#pragma unroll
                for (int nt = 0; nt < 4; nt++)
                    mma_f16(acc[mt][nt], a[mt], &b[nt >> 1][(nt & 1) * 2]);
        }
    }

    // Epilogue: direct fp32 stores
#pragma unroll
    for (int mt = 0; mt < 4; mt++) {
        const int row = rowC + wm * 64 + mt * 16 + g;
#pragma unroll
        for (int nt = 0; nt < 4; nt++) {
            const int col = colC + wn * 32 + nt * 8 + tg * 2;
            *(float2*)(C + (size_t)row * DIM + col) =
                make_float2(acc[mt][nt][0], acc[mt][nt][1]);
            *(float2*)(C + (size_t)(row + 8) * DIM + col) =
                make_float2(acc[mt][nt][2], acc[mt][nt][3]);
        }
    }
}

__global__ __launch_bounds__(256, 2)
void qkv_mma_kernel() {
    const __half* W = (blockIdx.z == 0) ? g_wq1
                    : (blockIdx.z == 1) ? g_wk1 : g_wv1;
    float* C = (blockIdx.z == 0) ? g_q : (blockIdx.z == 1) ? g_k : g_v;
    mma_gemm(g_x1, W, C);
}

__global__ __launch_bounds__(256, 2)
void out_mma_kernel(float* __restrict__ out) {
    mma_gemm(g_att1, g_wo1, out);
}

// ---------------------------------------------------------------------------
// k_mean[b,h,d] = mean_l k[b,h,l,d]
// ---------------------------------------------------------------------------
__global__ __launch_bounds__(256)
void kmean_kernel() {
    __shared__ float red[256];
    const int bh = blockIdx.x;
    const int b = bh >> 4, h = bh & 15;
    const int d = threadIdx.x & 63, p = threadIdx.x >> 6;
    const float* base = g_k + (size_t)b * SEQ * DIM + h * HD + d;
    float s = 0.f;
    for (int l = p; l < SEQ; l += 4) s += base[(size_t)l * DIM];
    red[threadIdx.x] = s;
    __syncthreads();
    if (threadIdx.x < 64) {
        float t = red[d] + red[64 + d] + red[128 + d] + red[192 + d];
        g_kmean[bh * HD + d] = t * (1.f / (float)SEQ);
    }
}

// ---------------------------------------------------------------------------
// Fused windowed attention, register-GEMM formulation.
// Tight strides + P aliased onto dead Kt region -> 82.2 KB -> 2 CTAs/SM.
// ---------------------------------------------------------------------------
#define AQ_S 64    // Q row stride (floats)
#define AK_S 128   // Kt row stride; region reused for P after score phase
#define AV_S 64    // V row stride
#define ATTN_SMEM ((64*AQ_S + 64*AK_S + 128*AV_S + 64) * 4)   // 82176 B

__global__ void __launch_bounds__(256, 2)
attn_kernel(const float* __restrict__ gsep,
            const float* __restrict__ galign,
            const float* __restrict__ gcoh) {
    extern __shared__ float sm[];
    float* Qs = sm;                    // [64][AQ_S]  q-major
    float* Kt = Qs + 64 * AQ_S;        // [64][AK_S]  d-major; becomes P later
    float* Vs = Kt + 64 * AK_S;        // [128][AV_S] n-major
    float* km = Vs + 128 * AV_S;       // [64]

    const int t  = blockIdx.x;
    const int bh = blockIdx.y;
    const int b  = bh >> 4, h = bh & 15;
    const int tid = threadIdx.x;
    const int tx = tid & 15, ty = tid >> 4;
    const int base = t * 64 - 64;

    const float* Kg = g_k + (size_t)b * SEQ * DIM + h * HD;
    const float* Vg = g_v + (size_t)b * SEQ * DIM + h * HD;
    const float* Qg = g_q + (size_t)b * SEQ * DIM + h * HD;

    // Q: 64 rows x 16 float4 = 1024 f4, 4 per thread
#pragma unroll
    for (int it = 0; it < 4; it++) {
        int idx = tid + 256 * it;
        int r = idx >> 4, c4 = (idx & 15) * 4;
        *(float4*)(Qs + r * AQ_S + c4) =
            *(const float4*)(Qg + (size_t)(t * 64 + r) * DIM + c4);
    }
    // V: 128 rows x 16 f4 = 2048, 8 per thread
#pragma unroll
    for (int it = 0; it < 8; it++) {
        int idx = tid + 256 * it;
        int r = idx >> 4, c4 = (idx & 15) * 4;
        int j = base + r;
        float4 vv = make_float4(0.f, 0.f, 0.f, 0.f);
        if (j >= 0) vv = *(const float4*)(Vg + (size_t)j * DIM + c4);
        *(float4*)(Vs + r * AV_S + c4) = vv;
    }
    // K transposed: lane reads one row's 16B; STS.32 conflict-free
#pragma unroll
    for (int it = 0; it < 8; it++) {
        int idx = tid + 256 * it;
        int r = idx & 127, d0 = (idx >> 7) * 4;
        int j = base + r;
        float4 kv = make_float4(0.f, 0.f, 0.f, 0.f);
        if (j >= 0) kv = *(const float4*)(Kg + (size_t)j * DIM + d0);
        Kt[(d0 + 0) * AK_S + r] = kv.x;
        Kt[(d0 + 1) * AK_S + r] = kv.y;
        Kt[(d0 + 2) * AK_S + r] = kv.z;
        Kt[(d0 + 3) * AK_S + r] = kv.w;
    }
    if (tid < 64) km[tid] = g_kmean[bh * HD + tid];
    __syncthreads();

    // ---- Score GEMM: S[4q][8n] per thread, plus pm = q . kmean ----
    float acc[4][8];
    float pm[4] = {0.f, 0.f, 0.f, 0.f};
#pragma unroll
    for (int qj = 0; qj < 4; qj++)
#pragma unroll
        for (int nj = 0; nj < 8; nj++) acc[qj][nj] = 0.f;

#pragma unroll 4
    for (int d = 0; d < 64; d++) {
        float4 k0 = *(const float4*)(Kt + d * AK_S + tx * 8);
        float4 k1 = *(const float4*)(Kt + d * AK_S + tx * 8 + 4);
        const float kvs[8] = {k0.x, k0.y, k0.z, k0.w, k1.x, k1.y, k1.z, k1.w};
        const float kmd = km[d];
#pragma unroll
        for (int qj = 0; qj < 4; qj++) {
            const float qv = Qs[(ty * 4 + qj) * AQ_S + d];
            pm[qj] = fmaf(qv, kmd, pm[qj]);
#pragma unroll
            for (int nj = 0; nj < 8; nj++)
                acc[qj][nj] = fmaf(qv, kvs[nj], acc[qj][nj]);
        }
    }

    // ---- Reynolds + mask + softmax; normalized weights back into acc ----
    const float sep = *gsep, alg = *galign, coh = *gcoh;
#pragma unroll
    for (int qj = 0; qj < 4; qj++) {
        const int qi = ty * 4 + qj;
        const float mi = pm[qj] * 0.125f;
        float s2[8];
        float mx = -1e30f;
#pragma unroll
        for (int nj = 0; nj < 8; nj++) {
            const int n = tx * 8 + nj;
            const float s = acc[qj][nj] * 0.125f;
            const float sim = 1.f / (1.f + __expf(-s));
            const float v = s + alg * s - sep * sim * sim - coh * fabsf(s - mi);
            const bool ok = (n >= qi + 1) && (n <= qi + 64) && (base + n >= 0);
            s2[nj] = ok ? v : -1e30f;
            mx = fmaxf(mx, s2[nj]);
        }
#pragma unroll
        for (int o = 1; o < 16; o <<= 1)
            mx = fmaxf(mx, __shfl_xor_sync(0xffffffffu, mx, o));
        float sum = 0.f;
#pragma unroll
        for (int nj = 0; nj < 8; nj++) {
            acc[qj][nj] = (s2[nj] > -1e29f) ? __expf(s2[nj] - mx) : 0.f;
            sum += acc[qj][nj];
        }
#pragma unroll
        for (int o = 1; o < 16; o <<= 1)
            sum += __shfl_xor_sync(0xffffffffu, sum, o);
        const float inv = 1.f / sum;
#pragma unroll
        for (int nj = 0; nj < 8; nj++) acc[qj][nj] *= inv;
    }

    // ---- All Kt reads complete across the CTA; reuse Kt region for P ----
    __syncthreads();
    float* Ps = Kt;     // [64 q][AK_S=128 n]
#pragma unroll
    for (int qj = 0; qj < 4; qj++) {
        const int qi = ty * 4 + qj;
        *(float4*)(Ps + qi * AK_S + tx * 8) =
            make_float4(acc[qj][0], acc[qj][1], acc[qj][2], acc[qj][3]);
        *(float4*)(Ps + qi * AK_S + tx * 8 + 4) =
            make_float4(acc[qj][4], acc[qj][5], acc[qj][6], acc[qj][7]);
    }
    __syncthreads();

    // ---- PV GEMM: O[4q][4d] per thread ----
    float o[4][4];
#pragma unroll
    for (int qj = 0; qj < 4; qj++)
#pragma unroll
        for (int dj = 0; dj < 4; dj++) o[qj][dj] = 0.f;

#pragma unroll 4
    for (int n = 0; n < 128; n++) {
        float4 vv = *(const float4*)(Vs + n * AV_S + tx * 4);
        const float vs[4] = {vv.x, vv.y, vv.z, vv.w};
#pragma unroll
        for (int qj = 0; qj < 4; qj++) {
            const float p = Ps[(ty * 4 + qj) * AK_S + n];
#pragma unroll
            for (int dj = 0; dj < 4; dj++)
                o[qj][dj] = fmaf(p, vs[dj], o[qj][dj]);
        }
    }

    // ---- Epilogue: write single fp16 ----
#pragma unroll
    for (int qj = 0; qj < 4; qj++) {
        const int i = t * 64 + ty * 4 + qj;
        const size_t rb = ((size_t)b * SEQ + i) * DIM + h * HD + tx * 4;
        union { __half v[4]; uint2 u; } Hh;
#pragma unroll
        for (int dj = 0; dj < 4; dj++) Hh.v[dj] = __float2half(o[qj][dj]);
        *(uint2*)(g_att1 + rb) = Hh.u;
    }
}

// ---------------------------------------------------------------------------
extern "C" void kernel_launch(void* const* d_in, const int* in_sizes, int n_in,
                              void* d_out, int out_size) {
    const float* x    = (const float*)d_in[0];
    const float* Wq   = (const float*)d_in[1];
    const float* Wk   = (const float*)d_in[2];
    const float* Wv   = (const float*)d_in[3];
    const float* Wo   = (const float*)d_in[4];
    const float* gsep = (const float*)d_in[5];
    const float* galn = (const float*)d_in[6];
    const float* gcoh = (const float*)d_in[7];
    float* out = (float*)d_out;

    cudaFuncSetAttribute(qkv_mma_kernel,
                         cudaFuncAttributeMaxDynamicSharedMemorySize, GEMM_SMEM);
    cudaFuncSetAttribute(out_mma_kernel,
                         cudaFuncAttributeMaxDynamicSharedMemorySize, GEMM_SMEM);
    cudaFuncSetAttribute(attn_kernel,
                         cudaFuncAttributeMaxDynamicSharedMemorySize, ATTN_SMEM);

    convert_kernel<<<8192, 256>>>(x, Wq, Wk, Wv, Wo);

    dim3 gqkv(DIM / TN, MTOT / TM, 3);
    qkv_mma_kernel<<<gqkv, 256, GEMM_SMEM>>>();

    kmean_kernel<<<BATCH * HEADS, 256>>>();

    dim3 gatt(SEQ / 64, BATCH * HEADS);
    attn_kernel<<<gatt, 256, ATTN_SMEM>>>(gsep, galn, gcoh);

    dim3 gout(DIM / TN, MTOT / TM);
    out_mma_kernel<<<gout, 256, GEMM_SMEM>>>(out);
}

// round 12
// speedup vs baseline: 5.9691x; 1.0083x over previous
#include <cuda_runtime.h>
#include <cuda_fp16.h>
#include <math.h>
#include <stdint.h>

// Problem constants
#define BATCH 2
#define SEQ   2048
#define DIM   1024
#define HEADS 16
#define HD    64
#define MTOT  (BATCH*SEQ)      // 4096

// GEMM tiling: plain fp16 GEMM, K = 1024.
#define TM 128
#define TN 128
#define BK 32
#define NCHUNK (DIM/BK)        // 32
#define STAGES 4
#define RS (BK+8)              // 40 elems = 80 B row stride (conflict-free)
#define STAGE_ELEMS (2*128*RS)
#define STAGE_BYTES (STAGE_ELEMS*2)        // 20480
#define GEMM_SMEM (STAGES*STAGE_BYTES)     // 81920 B -> 2 CTAs/SM

// Scratch (device globals; allocation-free contract)
__device__ __align__(256) __half g_qh[(size_t)MTOT*DIM];
__device__ __align__(256) __half g_kh[(size_t)MTOT*DIM];
__device__ __align__(256) __half g_vh[(size_t)MTOT*DIM];
__device__ __align__(256) float g_kmean[BATCH*HEADS*HD];
__device__ __align__(256) __half g_x1[(size_t)MTOT*DIM];
__device__ __align__(256) __half g_att1[(size_t)MTOT*DIM];
__device__ __align__(256) __half g_wq1[(size_t)DIM*DIM];
__device__ __align__(256) __half g_wk1[(size_t)DIM*DIM];
__device__ __align__(256) __half g_wv1[(size_t)DIM*DIM];
__device__ __align__(256) __half g_wo1[(size_t)DIM*DIM];

// ---------------------------------------------------------------------------
// Non-arch-variant PTX helpers (compute_103-safe)
// ---------------------------------------------------------------------------
__device__ __forceinline__ uint32_t smem_u32(const void* p) {
    uint32_t a;
    asm("{ .reg .u64 t; cvta.to.shared.u64 t, %1; cvt.u32.u64 %0, t; }"
        : "=r"(a) : "l"(p));
    return a;
}
__device__ __forceinline__ void cp16(uint32_t dst, const void* src) {
    asm volatile("cp.async.cg.shared.global [%0], [%1], 16;"
                 :: "r"(dst), "l"(src));
}
#define CP_COMMIT() asm volatile("cp.async.commit_group;" ::: "memory")
#define CP_WAIT2()  asm volatile("cp.async.wait_group 2;" ::: "memory")

__device__ __forceinline__ void ldsm4(uint32_t* d, uint32_t addr) {
    asm volatile("ldmatrix.sync.aligned.m8n8.x4.shared.b16 {%0,%1,%2,%3}, [%4];"
                 : "=r"(d[0]), "=r"(d[1]), "=r"(d[2]), "=r"(d[3]) : "r"(addr));
}

__device__ __forceinline__ void mma_f16(float* c, const uint32_t* a,
                                        const uint32_t* b) {
    asm volatile(
        "mma.sync.aligned.m16n8k16.row.col.f32.f16.f16.f32 "
        "{%0,%1,%2,%3}, {%4,%5,%6,%7}, {%8,%9}, {%0,%1,%2,%3};"
        : "+f"(c[0]), "+f"(c[1]), "+f"(c[2]), "+f"(c[3])
        : "r"(a[0]), "r"(a[1]), "r"(a[2]), "r"(a[3]), "r"(b[0]), "r"(b[1]));
}

__device__ __forceinline__ float4 h4_to_f4(uint2 u) {
    __half2 h0 = *(__half2*)&u.x, h1 = *(__half2*)&u.y;
    float2 f0 = __half22float2(h0), f1 = __half22float2(h1);
    return make_float4(f0.x, f0.y, f1.x, f1.y);
}

// ---------------------------------------------------------------------------
// fp16 conversion (no split).
// ---------------------------------------------------------------------------
__global__ __launch_bounds__(256)
void convert_kernel(const float* __restrict__ x,  const float* __restrict__ wq,
                    const float* __restrict__ wk, const float* __restrict__ wv,
                    const float* __restrict__ wo) {
    int rid = blockIdx.x;
    const float* src; __half* dst; int row;
    if      (rid < 4096) { src = x;  dst = g_x1;  row = rid;        }
    else if (rid < 5120) { src = wq; dst = g_wq1; row = rid - 4096; }
    else if (rid < 6144) { src = wk; dst = g_wk1; row = rid - 5120; }
    else if (rid < 7168) { src = wv; dst = g_wv1; row = rid - 6144; }
    else                 { src = wo; dst = g_wo1; row = rid - 7168; }
    int c = threadIdx.x * 4;
    float4 f = *(const float4*)(src + (size_t)row * DIM + c);
    union { __half b[4]; uint2 u; } H;
    H.b[0] = __float2half(f.x); H.b[1] = __float2half(f.y);
    H.b[2] = __float2half(f.z); H.b[3] = __float2half(f.w);
    *(uint2*)(dst + (size_t)row * DIM + c) = H.u;
}

// ---------------------------------------------------------------------------
// Plain fp16 HMMA GEMM: C[4096,1024] = A[4096,1024] @ B[1024,1024]^T (f32 acc)
// Output type templated: fp32 (final out) or fp16 (q/k/v for attention).
// ---------------------------------------------------------------------------
__device__ __forceinline__ void load_stage(uint32_t stg,
                                           const __half* __restrict__ Ag,
                                           const __half* __restrict__ Bg,
                                           int chunk, int tid) {
    const __half* Ac = Ag + chunk * BK;
    const __half* Bc = Bg + chunk * BK;
#pragma unroll
    for (int i = 0; i < 2; i++) {
        int seg = tid + 256 * i;
        int r = seg >> 2, cs = seg & 3;
        cp16(stg + r * (RS*2) + cs * 16,
             (const char*)(Ac + (size_t)r * DIM) + cs * 16);
    }
#pragma unroll
    for (int i = 0; i < 2; i++) {
        int seg = tid + 256 * i;
        int r = seg >> 2, cs = seg & 3;
        cp16(stg + 128*(RS*2) + r * (RS*2) + cs * 16,
             (const char*)(Bc + (size_t)r * DIM) + cs * 16);
    }
}

template <typename OutT>
__device__ __forceinline__ void mma_gemm(const __half* __restrict__ A1,
                                         const __half* __restrict__ B1,
                                         OutT* __restrict__ C) {
    extern __shared__ __align__(128) __half smem[];
    const uint32_t sb = smem_u32(smem);
    const int tid = threadIdx.x;
    const int lane = tid & 31, w = tid >> 5;
    const int wm = w >> 2, wn = w & 3;        // 2 x 4 warp grid
    const int g = lane >> 2, tg = lane & 3;   // epilogue mapping
    const int rowC = blockIdx.y * TM;
    const int colC = blockIdx.x * TN;
    const __half* Ag = A1 + (size_t)rowC * DIM;
    const __half* Bg = B1 + (size_t)colC * DIM;

    const int arow = wm * 64 + (lane & 15);
    const int acol = (lane >> 4) * 8;
    uint32_t a_rel[4];
#pragma unroll
    for (int mt = 0; mt < 4; mt++)
        a_rel[mt] = (uint32_t)(((arow + mt * 16) * RS + acol) * 2);
    const int brow = wn * 32 + (lane & 7) + ((lane >> 4) << 3);
    const int bcol = ((lane >> 3) & 1) * 8;
    uint32_t b_rel[2];
#pragma unroll
    for (int p = 0; p < 2; p++)
        b_rel[p] = (uint32_t)(((128 + brow + p * 16) * RS + bcol) * 2);

    float acc[4][4][4];
#pragma unroll
    for (int mt = 0; mt < 4; mt++)
#pragma unroll
        for (int nt = 0; nt < 4; nt++)
#pragma unroll
            for (int i = 0; i < 4; i++) acc[mt][nt][i] = 0.f;

#pragma unroll
    for (int s = 0; s < STAGES - 1; s++) {
        load_stage(sb + s * STAGE_BYTES, Ag, Bg, s, tid);
        CP_COMMIT();
    }

    for (int c = 0; c < NCHUNK; c++) {
        CP_WAIT2();
        __syncthreads();
        const uint32_t stg = sb + (uint32_t)(c & 3) * STAGE_BYTES;

        if (c + (STAGES - 1) < NCHUNK)
            load_stage(sb + (uint32_t)((c + STAGES - 1) & 3) * STAGE_BYTES,
                       Ag, Bg, c + STAGES - 1, tid);
        CP_COMMIT();

#pragma unroll
        for (int ks = 0; ks < 2; ks++) {
            const uint32_t ko = (uint32_t)(ks * 16 * 2);
            uint32_t a[4][4], b[2][4];
#pragma unroll
            for (int mt = 0; mt < 4; mt++) ldsm4(a[mt], stg + a_rel[mt] + ko);
#pragma unroll
            for (int p = 0; p < 2; p++)    ldsm4(b[p],  stg + b_rel[p] + ko);
#pragma unroll
            for (int mt = 0; mt < 4; mt++)
#pragma unroll
                for (int nt = 0; nt < 4; nt++)
                    mma_f16(acc[mt][nt], a[mt], &b[nt >> 1][(nt & 1) * 2]);
        }
    }

    // Epilogue: fp32 float2 stores or fp16 half2 stores
#pragma unroll
    for (int mt = 0; mt < 4; mt++) {
        const int row = rowC + wm * 64 + mt * 16 + g;
#pragma unroll
        for (int nt = 0; nt < 4; nt++) {
            const int col = colC + wn * 32 + nt * 8 + tg * 2;
            if constexpr (sizeof(OutT) == 4) {
                *(float2*)((float*)C + (size_t)row * DIM + col) =
                    make_float2(acc[mt][nt][0], acc[mt][nt][1]);
                *(float2*)((float*)C + (size_t)(row + 8) * DIM + col) =
                    make_float2(acc[mt][nt][2], acc[mt][nt][3]);
            } else {
                __half2 h0 = __floats2half2_rn(acc[mt][nt][0], acc[mt][nt][1]);
                __half2 h1 = __floats2half2_rn(acc[mt][nt][2], acc[mt][nt][3]);
                *(__half2*)((__half*)C + (size_t)row * DIM + col) = h0;
                *(__half2*)((__half*)C + (size_t)(row + 8) * DIM + col) = h1;
            }
        }
    }
}

__global__ __launch_bounds__(256, 2)
void qkv_mma_kernel() {
    const __half* W = (blockIdx.z == 0) ? g_wq1
                    : (blockIdx.z == 1) ? g_wk1 : g_wv1;
    __half* C = (blockIdx.z == 0) ? g_qh : (blockIdx.z == 1) ? g_kh : g_vh;
    mma_gemm<__half>(g_x1, W, C);
}

__global__ __launch_bounds__(256, 2)
void out_mma_kernel(float* __restrict__ out) {
    mma_gemm<float>(g_att1, g_wo1, out);
}

// ---------------------------------------------------------------------------
// k_mean[b,h,d] = mean_l k[b,h,l,d]   (fp16 k input)
// ---------------------------------------------------------------------------
__global__ __launch_bounds__(256)
void kmean_kernel() {
    __shared__ float red[256];
    const int bh = blockIdx.x;
    const int b = bh >> 4, h = bh & 15;
    const int d = threadIdx.x & 63, p = threadIdx.x >> 6;
    const __half* base = g_kh + (size_t)b * SEQ * DIM + h * HD + d;
    float s = 0.f;
    for (int l = p; l < SEQ; l += 4) s += __half2float(base[(size_t)l * DIM]);
    red[threadIdx.x] = s;
    __syncthreads();
    if (threadIdx.x < 64) {
        float t = red[d] + red[64 + d] + red[128 + d] + red[192 + d];
        g_kmean[bh * HD + d] = t * (1.f / (float)SEQ);
    }
}

// ---------------------------------------------------------------------------
// Fused windowed attention, register-GEMM formulation. fp16 q/k/v inputs
// converted to fp32 in smem; compute identical to the proven kernel.
// ---------------------------------------------------------------------------
#define AQ_S 64    // Q row stride (floats)
#define AK_S 128   // Kt row stride; region reused for P after score phase
#define AV_S 64    // V row stride
#define ATTN_SMEM ((64*AQ_S + 64*AK_S + 128*AV_S + 64) * 4)   // 82176 B

__global__ void __launch_bounds__(256, 2)
attn_kernel(const float* __restrict__ gsep,
            const float* __restrict__ galign,
            const float* __restrict__ gcoh) {
    extern __shared__ float sm[];
    float* Qs = sm;                    // [64][AQ_S]  q-major
    float* Kt = Qs + 64 * AQ_S;        // [64][AK_S]  d-major; becomes P later
    float* Vs = Kt + 64 * AK_S;        // [128][AV_S] n-major
    float* km = Vs + 128 * AV_S;       // [64]

    const int t  = blockIdx.x;
    const int bh = blockIdx.y;
    const int b  = bh >> 4, h = bh & 15;
    const int tid = threadIdx.x;
    const int tx = tid & 15, ty = tid >> 4;
    const int base = t * 64 - 64;

    const __half* Kg = g_kh + (size_t)b * SEQ * DIM + h * HD;
    const __half* Vg = g_vh + (size_t)b * SEQ * DIM + h * HD;
    const __half* Qg = g_qh + (size_t)b * SEQ * DIM + h * HD;

    // Q: 64 rows x 16 half4-segments = 1024, 4 per thread
#pragma unroll
    for (int it = 0; it < 4; it++) {
        int idx = tid + 256 * it;
        int r = idx >> 4, c4 = (idx & 15) * 4;
        uint2 u = *(const uint2*)(Qg + (size_t)(t * 64 + r) * DIM + c4);
        *(float4*)(Qs + r * AQ_S + c4) = h4_to_f4(u);
    }
    // V: 128 rows x 16 segments = 2048, 8 per thread
#pragma unroll
    for (int it = 0; it < 8; it++) {
        int idx = tid + 256 * it;
        int r = idx >> 4, c4 = (idx & 15) * 4;
        int j = base + r;
        float4 vv = make_float4(0.f, 0.f, 0.f, 0.f);
        if (j >= 0) vv = h4_to_f4(*(const uint2*)(Vg + (size_t)j * DIM + c4));
        *(float4*)(Vs + r * AV_S + c4) = vv;
    }
    // K transposed: lane reads one row's 4 halves; STS.32 conflict-free
#pragma unroll
    for (int it = 0; it < 8; it++) {
        int idx = tid + 256 * it;
        int r = idx & 127, d0 = (idx >> 7) * 4;
        int j = base + r;
        float4 kv = make_float4(0.f, 0.f, 0.f, 0.f);
        if (j >= 0) kv = h4_to_f4(*(const uint2*)(Kg + (size_t)j * DIM + d0));
        Kt[(d0 + 0) * AK_S + r] = kv.x;
        Kt[(d0 + 1) * AK_S + r] = kv.y;
        Kt[(d0 + 2) * AK_S + r] = kv.z;
        Kt[(d0 + 3) * AK_S + r] = kv.w;
    }
    if (tid < 64) km[tid] = g_kmean[bh * HD + tid];
    __syncthreads();

    // ---- Score GEMM: S[4q][8n] per thread, plus pm = q . kmean ----
    float acc[4][8];
    float pm[4] = {0.f, 0.f, 0.f, 0.f};
#pragma unroll
    for (int qj = 0; qj < 4; qj++)
#pragma unroll
        for (int nj = 0; nj < 8; nj++) acc[qj][nj] = 0.f;

#pragma unroll 4
    for (int d = 0; d < 64; d++) {
        float4 k0 = *(const float4*)(Kt + d * AK_S + tx * 8);
        float4 k1 = *(const float4*)(Kt + d * AK_S + tx * 8 + 4);
        const float kvs[8] = {k0.x, k0.y, k0.z, k0.w, k1.x, k1.y, k1.z, k1.w};
        const float kmd = km[d];
#pragma unroll
        for (int qj = 0; qj < 4; qj++) {
            const float qv = Qs[(ty * 4 + qj) * AQ_S + d];
            pm[qj] = fmaf(qv, kmd, pm[qj]);
#pragma unroll
            for (int nj = 0; nj < 8; nj++)
                acc[qj][nj] = fmaf(qv, kvs[nj], acc[qj][nj]);
        }
    }

    // ---- Reynolds + mask + softmax; normalized weights back into acc ----
    const float sep = *gsep, alg = *galign, coh = *gcoh;
#pragma unroll
    for (int qj = 0; qj < 4; qj++) {
        const int qi = ty * 4 + qj;
        const float mi = pm[qj] * 0.125f;
        float s2[8];
        float mx = -1e30f;
#pragma unroll
        for (int nj = 0; nj < 8; nj++) {
            const int n = tx * 8 + nj;
            const float s = acc[qj][nj] * 0.125f;
            const float sim = 1.f / (1.f + __expf(-s));
            const float v = s + alg * s - sep * sim * sim - coh * fabsf(s - mi);
            const bool ok = (n >= qi + 1) && (n <= qi + 64) && (base + n >= 0);
            s2[nj] = ok ? v : -1e30f;
            mx = fmaxf(mx, s2[nj]);
        }
#pragma unroll
        for (int o = 1; o < 16; o <<= 1)
            mx = fmaxf(mx, __shfl_xor_sync(0xffffffffu, mx, o));
        float sum = 0.f;
#pragma unroll
        for (int nj = 0; nj < 8; nj++) {
            acc[qj][nj] = (s2[nj] > -1e29f) ? __expf(s2[nj] - mx) : 0.f;
            sum += acc[qj][nj];
        }
#pragma unroll
        for (int o = 1; o < 16; o <<= 1)
            sum += __shfl_xor_sync(0xffffffffu, sum, o);
        const float inv = 1.f / sum;
#pragma unroll
        for (int nj = 0; nj < 8; nj++) acc[qj][nj] *= inv;
    }

    // ---- All Kt reads complete across the CTA; reuse Kt region for P ----
    __syncthreads();
    float* Ps = Kt;     // [64 q][AK_S=128 n]
#pragma unroll
    for (int qj = 0; qj < 4; qj++) {
        const int qi = ty * 4 + qj;
        *(float4*)(Ps + qi * AK_S + tx * 8) =
            make_float4(acc[qj][0], acc[qj][1], acc[qj][2], acc[qj][3]);
        *(float4*)(Ps + qi * AK_S + tx * 8 + 4) =
            make_float4(acc[qj][4], acc[qj][5], acc[qj][6], acc[qj][7]);
    }
    __syncthreads();

    // ---- PV GEMM: O[4q][4d] per thread ----
    float o[4][4];
#pragma unroll
    for (int qj = 0; qj < 4; qj++)
#pragma unroll
        for (int dj = 0; dj < 4; dj++) o[qj][dj] = 0.f;

#pragma unroll 4
    for (int n = 0; n < 128; n++) {
        float4 vv = *(const float4*)(Vs + n * AV_S + tx * 4);
        const float vs[4] = {vv.x, vv.y, vv.z, vv.w};
#pragma unroll
        for (int qj = 0; qj < 4; qj++) {
            const float p = Ps[(ty * 4 + qj) * AK_S + n];
#pragma unroll
            for (int dj = 0; dj < 4; dj++)
                o[qj][dj] = fmaf(p, vs[dj], o[qj][dj]);
        }
    }

    // ---- Epilogue: write single fp16 ----
#pragma unroll
    for (int qj = 0; qj < 4; qj++) {
        const int i = t * 64 + ty * 4 + qj;
        const size_t rb = ((size_t)b * SEQ + i) * DIM + h * HD + tx * 4;
        union { __half v[4]; uint2 u; } Hh;
#pragma unroll
        for (int dj = 0; dj < 4; dj++) Hh.v[dj] = __float2half(o[qj][dj]);
        *(uint2*)(g_att1 + rb) = Hh.u;
    }
}

// ---------------------------------------------------------------------------
extern "C" void kernel_launch(void* const* d_in, const int* in_sizes, int n_in,
                              void* d_out, int out_size) {
    const float* x    = (const float*)d_in[0];
    const float* Wq   = (const float*)d_in[1];
    const float* Wk   = (const float*)d_in[2];
    const float* Wv   = (const float*)d_in[3];
    const float* Wo   = (const float*)d_in[4];
    const float* gsep = (const float*)d_in[5];
    const float* galn = (const float*)d_in[6];
    const float* gcoh = (const float*)d_in[7];
    float* out = (float*)d_out;

    cudaFuncSetAttribute(qkv_mma_kernel,
                         cudaFuncAttributeMaxDynamicSharedMemorySize, GEMM_SMEM);
    cudaFuncSetAttribute(out_mma_kernel,
                         cudaFuncAttributeMaxDynamicSharedMemorySize, GEMM_SMEM);
    cudaFuncSetAttribute(attn_kernel,
                         cudaFuncAttributeMaxDynamicSharedMemorySize, ATTN_SMEM);

    convert_kernel<<<8192, 256>>>(x, Wq, Wk, Wv, Wo);

    dim3 gqkv(DIM / TN, MTOT / TM, 3);
    qkv_mma_kernel<<<gqkv, 256, GEMM_SMEM>>>();

    kmean_kernel<<<BATCH * HEADS, 256>>>();

    dim3 gatt(SEQ / 64, BATCH * HEADS);
    attn_kernel<<<gatt, 256, ATTN_SMEM>>>(gsep, galn, gcoh);

    dim3 gout(DIM / TN, MTOT / TM);
    out_mma_kernel<<<gout, 256, GEMM_SMEM>>>(out);
}

// round 13
// speedup vs baseline: 6.0208x; 1.0087x over previous
#include <cuda_runtime.h>
#include <cuda_fp16.h>
#include <math.h>
#include <stdint.h>

// Problem constants
#define BATCH 2
#define SEQ   2048
#define DIM   1024
#define HEADS 16
#define HD    64
#define MTOT  (BATCH*SEQ)      // 4096

// GEMM tiling: plain fp16 GEMM, K = 1024.
#define TM 128
#define TN 128
#define BK 32
#define NCHUNK (DIM/BK)        // 32
#define STAGES 4
#define RS (BK+8)              // 40 elems = 80 B row stride (conflict-free)
#define STAGE_ELEMS (2*128*RS)
#define STAGE_BYTES (STAGE_ELEMS*2)        // 20480
#define GEMM_SMEM (STAGES*STAGE_BYTES)     // 81920 B -> 2 CTAs/SM

// Scratch (device globals; allocation-free contract)
__device__ __align__(256) __half g_qh[(size_t)MTOT*DIM];
__device__ __align__(256) __half g_kh[(size_t)MTOT*DIM];
__device__ __align__(256) __half g_vh[(size_t)MTOT*DIM];
__device__ __align__(256) float g_kmean[BATCH*HEADS*HD];
__device__ __align__(256) __half g_x1[(size_t)MTOT*DIM];
__device__ __align__(256) __half g_att1[(size_t)MTOT*DIM];
__device__ __align__(256) __half g_wq1[(size_t)DIM*DIM];
__device__ __align__(256) __half g_wk1[(size_t)DIM*DIM];
__device__ __align__(256) __half g_wv1[(size_t)DIM*DIM];
__device__ __align__(256) __half g_wo1[(size_t)DIM*DIM];

// ---------------------------------------------------------------------------
// Non-arch-variant PTX helpers (compute_103-safe)
// ---------------------------------------------------------------------------
__device__ __forceinline__ uint32_t smem_u32(const void* p) {
    uint32_t a;
    asm("{ .reg .u64 t; cvta.to.shared.u64 t, %1; cvt.u32.u64 %0, t; }"
        : "=r"(a) : "l"(p));
    return a;
}
__device__ __forceinline__ void cp16(uint32_t dst, const void* src) {
    asm volatile("cp.async.cg.shared.global [%0], [%1], 16;"
                 :: "r"(dst), "l"(src));
}
#define CP_COMMIT() asm volatile("cp.async.commit_group;" ::: "memory")
#define CP_WAIT2()  asm volatile("cp.async.wait_group 2;" ::: "memory")

__device__ __forceinline__ void ldsm4(uint32_t* d, uint32_t addr) {
    asm volatile("ldmatrix.sync.aligned.m8n8.x4.shared.b16 {%0,%1,%2,%3}, [%4];"
                 : "=r"(d[0]), "=r"(d[1]), "=r"(d[2]), "=r"(d[3]) : "r"(addr));
}

__device__ __forceinline__ void mma_f16(float* c, const uint32_t* a,
                                        const uint32_t* b) {
    asm volatile(
        "mma.sync.aligned.m16n8k16.row.col.f32.f16.f16.f32 "
        "{%0,%1,%2,%3}, {%4,%5,%6,%7}, {%8,%9}, {%0,%1,%2,%3};"
        : "+f"(c[0]), "+f"(c[1]), "+f"(c[2]), "+f"(c[3])
        : "r"(a[0]), "r"(a[1]), "r"(a[2]), "r"(a[3]), "r"(b[0]), "r"(b[1]));
}

__device__ __forceinline__ float4 h4_to_f4(uint2 u) {
    __half2 h0 = *(__half2*)&u.x, h1 = *(__half2*)&u.y;
    float2 f0 = __half22float2(h0), f1 = __half22float2(h1);
    return make_float4(f0.x, f0.y, f1.x, f1.y);
}

// ---------------------------------------------------------------------------
// fp16 conversion (no split).
// ---------------------------------------------------------------------------
__global__ __launch_bounds__(256)
void convert_kernel(const float* __restrict__ x,  const float* __restrict__ wq,
                    const float* __restrict__ wk, const float* __restrict__ wv,
                    const float* __restrict__ wo) {
    int rid = blockIdx.x;
    const float* src; __half* dst; int row;
    if      (rid < 4096) { src = x;  dst = g_x1;  row = rid;        }
    else if (rid < 5120) { src = wq; dst = g_wq1; row = rid - 4096; }
    else if (rid < 6144) { src = wk; dst = g_wk1; row = rid - 5120; }
    else if (rid < 7168) { src = wv; dst = g_wv1; row = rid - 6144; }
    else                 { src = wo; dst = g_wo1; row = rid - 7168; }
    int c = threadIdx.x * 4;
    float4 f = *(const float4*)(src + (size_t)row * DIM + c);
    union { __half b[4]; uint2 u; } H;
    H.b[0] = __float2half(f.x); H.b[1] = __float2half(f.y);
    H.b[2] = __float2half(f.z); H.b[3] = __float2half(f.w);
    *(uint2*)(dst + (size_t)row * DIM + c) = H.u;
}

// ---------------------------------------------------------------------------
// Plain fp16 HMMA GEMM: C[4096,1024] = A[4096,1024] @ B[1024,1024]^T (f32 acc)
// Output type templated: fp32 (final out) or fp16 (q/k/v for attention).
// ---------------------------------------------------------------------------
__device__ __forceinline__ void load_stage(uint32_t stg,
                                           const __half* __restrict__ Ag,
                                           const __half* __restrict__ Bg,
                                           int chunk, int tid) {
    const __half* Ac = Ag + chunk * BK;
    const __half* Bc = Bg + chunk * BK;
#pragma unroll
    for (int i = 0; i < 2; i++) {
        int seg = tid + 256 * i;
        int r = seg >> 2, cs = seg & 3;
        cp16(stg + r * (RS*2) + cs * 16,
             (const char*)(Ac + (size_t)r * DIM) + cs * 16);
    }
#pragma unroll
    for (int i = 0; i < 2; i++) {
        int seg = tid + 256 * i;
        int r = seg >> 2, cs = seg & 3;
        cp16(stg + 128*(RS*2) + r * (RS*2) + cs * 16,
             (const char*)(Bc + (size_t)r * DIM) + cs * 16);
    }
}

template <typename OutT>
__device__ __forceinline__ void mma_gemm(const __half* __restrict__ A1,
                                         const __half* __restrict__ B1,
                                         OutT* __restrict__ C) {
    extern __shared__ __align__(128) __half smem[];
    const uint32_t sb = smem_u32(smem);
    const int tid = threadIdx.x;
    const int lane = tid & 31, w = tid >> 5;
    const int wm = w >> 2, wn = w & 3;        // 2 x 4 warp grid
    const int g = lane >> 2, tg = lane & 3;   // epilogue mapping
    const int rowC = blockIdx.y * TM;
    const int colC = blockIdx.x * TN;
    const __half* Ag = A1 + (size_t)rowC * DIM;
    const __half* Bg = B1 + (size_t)colC * DIM;

    const int arow = wm * 64 + (lane & 15);
    const int acol = (lane >> 4) * 8;
    uint32_t a_rel[4];
#pragma unroll
    for (int mt = 0; mt < 4; mt++)
        a_rel[mt] = (uint32_t)(((arow + mt * 16) * RS + acol) * 2);
    const int brow = wn * 32 + (lane & 7) + ((lane >> 4) << 3);
    const int bcol = ((lane >> 3) & 1) * 8;
    uint32_t b_rel[2];
#pragma unroll
    for (int p = 0; p < 2; p++)
        b_rel[p] = (uint32_t)(((128 + brow + p * 16) * RS + bcol) * 2);

    float acc[4][4][4];
#pragma unroll
    for (int mt = 0; mt < 4; mt++)
#pragma unroll
        for (int nt = 0; nt < 4; nt++)
#pragma unroll
            for (int i = 0; i < 4; i++) acc[mt][nt][i] = 0.f;

#pragma unroll
    for (int s = 0; s < STAGES - 1; s++) {
        load_stage(sb + s * STAGE_BYTES, Ag, Bg, s, tid);
        CP_COMMIT();
    }

    for (int c = 0; c < NCHUNK; c++) {
        CP_WAIT2();
        __syncthreads();
        const uint32_t stg = sb + (uint32_t)(c & 3) * STAGE_BYTES;

        if (c + (STAGES - 1) < NCHUNK)
            load_stage(sb + (uint32_t)((c + STAGES - 1) & 3) * STAGE_BYTES,
                       Ag, Bg, c + STAGES - 1, tid);
        CP_COMMIT();

#pragma unroll
        for (int ks = 0; ks < 2; ks++) {
            const uint32_t ko = (uint32_t)(ks * 16 * 2);
            uint32_t a[4][4], b[2][4];
#pragma unroll
            for (int mt = 0; mt < 4; mt++) ldsm4(a[mt], stg + a_rel[mt] + ko);
#pragma unroll
            for (int p = 0; p < 2; p++)    ldsm4(b[p],  stg + b_rel[p] + ko);
#pragma unroll
            for (int mt = 0; mt < 4; mt++)
#pragma unroll
                for (int nt = 0; nt < 4; nt++)
                    mma_f16(acc[mt][nt], a[mt], &b[nt >> 1][(nt & 1) * 2]);
        }
    }

    // Epilogue: fp32 float2 stores or fp16 half2 stores
#pragma unroll
    for (int mt = 0; mt < 4; mt++) {
        const int row = rowC + wm * 64 + mt * 16 + g;
#pragma unroll
        for (int nt = 0; nt < 4; nt++) {
            const int col = colC + wn * 32 + nt * 8 + tg * 2;
            if constexpr (sizeof(OutT) == 4) {
                *(float2*)((float*)C + (size_t)row * DIM + col) =
                    make_float2(acc[mt][nt][0], acc[mt][nt][1]);
                *(float2*)((float*)C + (size_t)(row + 8) * DIM + col) =
                    make_float2(acc[mt][nt][2], acc[mt][nt][3]);
            } else {
                __half2 h0 = __floats2half2_rn(acc[mt][nt][0], acc[mt][nt][1]);
                __half2 h1 = __floats2half2_rn(acc[mt][nt][2], acc[mt][nt][3]);
                *(__half2*)((__half*)C + (size_t)row * DIM + col) = h0;
                *(__half2*)((__half*)C + (size_t)(row + 8) * DIM + col) = h1;
            }
        }
    }
}

__global__ __launch_bounds__(256, 2)
void qkv_mma_kernel() {
    const __half* W = (blockIdx.z == 0) ? g_wq1
                    : (blockIdx.z == 1) ? g_wk1 : g_wv1;
    __half* C = (blockIdx.z == 0) ? g_qh : (blockIdx.z == 1) ? g_kh : g_vh;
    mma_gemm<__half>(g_x1, W, C);
}

__global__ __launch_bounds__(256, 2)
void out_mma_kernel(float* __restrict__ out) {
    mma_gemm<float>(g_att1, g_wo1, out);
}

// ---------------------------------------------------------------------------
// k_mean[b,h,d] = mean_l k[b,h,l,d]   (fp16 k input)
// ---------------------------------------------------------------------------
__global__ __launch_bounds__(256)
void kmean_kernel() {
    __shared__ float red[256];
    const int bh = blockIdx.x;
    const int b = bh >> 4, h = bh & 15;
    const int d = threadIdx.x & 63, p = threadIdx.x >> 6;
    const __half* base = g_kh + (size_t)b * SEQ * DIM + h * HD + d;
    float s = 0.f;
    for (int l = p; l < SEQ; l += 4) s += __half2float(base[(size_t)l * DIM]);
    red[threadIdx.x] = s;
    __syncthreads();
    if (threadIdx.x < 64) {
        float t = red[d] + red[64 + d] + red[128 + d] + red[192 + d];
        g_kmean[bh * HD + d] = t * (1.f / (float)SEQ);
    }
}

// ---------------------------------------------------------------------------
// Fused windowed attention, register-GEMM formulation. Vectorized broadcast
// operands (float4 Q/km/P) to cut LDS issue pressure (~72% -> ~40% L1).
// ---------------------------------------------------------------------------
#define AQ_S 64    // Q row stride (floats)
#define AK_S 128   // Kt row stride; region reused for P after score phase
#define AV_S 64    // V row stride
#define ATTN_SMEM ((64*AQ_S + 64*AK_S + 128*AV_S + 64) * 4)   // 82176 B

__global__ void __launch_bounds__(256, 2)
attn_kernel(const float* __restrict__ gsep,
            const float* __restrict__ galign,
            const float* __restrict__ gcoh) {
    extern __shared__ float sm[];
    float* Qs = sm;                    // [64][AQ_S]  q-major
    float* Kt = Qs + 64 * AQ_S;        // [64][AK_S]  d-major; becomes P later
    float* Vs = Kt + 64 * AK_S;        // [128][AV_S] n-major
    float* km = Vs + 128 * AV_S;       // [64]

    const int t  = blockIdx.x;
    const int bh = blockIdx.y;
    const int b  = bh >> 4, h = bh & 15;
    const int tid = threadIdx.x;
    const int tx = tid & 15, ty = tid >> 4;
    const int base = t * 64 - 64;

    const __half* Kg = g_kh + (size_t)b * SEQ * DIM + h * HD;
    const __half* Vg = g_vh + (size_t)b * SEQ * DIM + h * HD;
    const __half* Qg = g_qh + (size_t)b * SEQ * DIM + h * HD;

    // Q: 64 rows x 16 half4-segments = 1024, 4 per thread
#pragma unroll
    for (int it = 0; it < 4; it++) {
        int idx = tid + 256 * it;
        int r = idx >> 4, c4 = (idx & 15) * 4;
        uint2 u = *(const uint2*)(Qg + (size_t)(t * 64 + r) * DIM + c4);
        *(float4*)(Qs + r * AQ_S + c4) = h4_to_f4(u);
    }
    // V: 128 rows x 16 segments = 2048, 8 per thread
#pragma unroll
    for (int it = 0; it < 8; it++) {
        int idx = tid + 256 * it;
        int r = idx >> 4, c4 = (idx & 15) * 4;
        int j = base + r;
        float4 vv = make_float4(0.f, 0.f, 0.f, 0.f);
        if (j >= 0) vv = h4_to_f4(*(const uint2*)(Vg + (size_t)j * DIM + c4));
        *(float4*)(Vs + r * AV_S + c4) = vv;
    }
    // K transposed: lane reads one row's 4 halves; STS.32 conflict-free
#pragma unroll
    for (int it = 0; it < 8; it++) {
        int idx = tid + 256 * it;
        int r = idx & 127, d0 = (idx >> 7) * 4;
        int j = base + r;
        float4 kv = make_float4(0.f, 0.f, 0.f, 0.f);
        if (j >= 0) kv = h4_to_f4(*(const uint2*)(Kg + (size_t)j * DIM + d0));
        Kt[(d0 + 0) * AK_S + r] = kv.x;
        Kt[(d0 + 1) * AK_S + r] = kv.y;
        Kt[(d0 + 2) * AK_S + r] = kv.z;
        Kt[(d0 + 3) * AK_S + r] = kv.w;
    }
    if (tid < 64) km[tid] = g_kmean[bh * HD + tid];
    __syncthreads();

    // ---- Score GEMM: S[4q][8n] per thread, plus pm = q . kmean ----
    // Vectorized: Q and km hoisted as float4 over 4-wide d sub-blocks.
    float acc[4][8];
    float pm[4] = {0.f, 0.f, 0.f, 0.f};
#pragma unroll
    for (int qj = 0; qj < 4; qj++)
#pragma unroll
        for (int nj = 0; nj < 8; nj++) acc[qj][nj] = 0.f;

#pragma unroll 2
    for (int d4 = 0; d4 < 64; d4 += 4) {
        const float4 km4 = *(const float4*)(km + d4);
        float4 q4[4];
#pragma unroll
        for (int qj = 0; qj < 4; qj++)
            q4[qj] = *(const float4*)(Qs + (ty * 4 + qj) * AQ_S + d4);
#pragma unroll
        for (int dd = 0; dd < 4; dd++) {
            const int d = d4 + dd;
            float4 k0 = *(const float4*)(Kt + d * AK_S + tx * 8);
            float4 k1 = *(const float4*)(Kt + d * AK_S + tx * 8 + 4);
            const float kvs[8] = {k0.x, k0.y, k0.z, k0.w,
                                  k1.x, k1.y, k1.z, k1.w};
            const float kmd = (&km4.x)[dd];
#pragma unroll
            for (int qj = 0; qj < 4; qj++) {
                const float qv = (&q4[qj].x)[dd];
                pm[qj] = fmaf(qv, kmd, pm[qj]);
#pragma unroll
                for (int nj = 0; nj < 8; nj++)
                    acc[qj][nj] = fmaf(qv, kvs[nj], acc[qj][nj]);
            }
        }
    }

    // ---- Reynolds + mask + softmax; normalized weights back into acc ----
    const float sep = *gsep, alg = *galign, coh = *gcoh;
#pragma unroll
    for (int qj = 0; qj < 4; qj++) {
        const int qi = ty * 4 + qj;
        const float mi = pm[qj] * 0.125f;
        float s2[8];
        float mx = -1e30f;
#pragma unroll
        for (int nj = 0; nj < 8; nj++) {
            const int n = tx * 8 + nj;
            const float s = acc[qj][nj] * 0.125f;
            const float sim = 1.f / (1.f + __expf(-s));
            const float v = s + alg * s - sep * sim * sim - coh * fabsf(s - mi);
            const bool ok = (n >= qi + 1) && (n <= qi + 64) && (base + n >= 0);
            s2[nj] = ok ? v : -1e30f;
            mx = fmaxf(mx, s2[nj]);
        }
#pragma unroll
        for (int o = 1; o < 16; o <<= 1)
            mx = fmaxf(mx, __shfl_xor_sync(0xffffffffu, mx, o));
        float sum = 0.f;
#pragma unroll
        for (int nj = 0; nj < 8; nj++) {
            acc[qj][nj] = (s2[nj] > -1e29f) ? __expf(s2[nj] - mx) : 0.f;
            sum += acc[qj][nj];
        }
#pragma unroll
        for (int o = 1; o < 16; o <<= 1)
            sum += __shfl_xor_sync(0xffffffffu, sum, o);
        const float inv = 1.f / sum;
#pragma unroll
        for (int nj = 0; nj < 8; nj++) acc[qj][nj] *= inv;
    }

    // ---- All Kt reads complete across the CTA; reuse Kt region for P ----
    __syncthreads();
    float* Ps = Kt;     // [64 q][AK_S=128 n]
#pragma unroll
    for (int qj = 0; qj < 4; qj++) {
        const int qi = ty * 4 + qj;
        *(float4*)(Ps + qi * AK_S + tx * 8) =
            make_float4(acc[qj][0], acc[qj][1], acc[qj][2], acc[qj][3]);
        *(float4*)(Ps + qi * AK_S + tx * 8 + 4) =
            make_float4(acc[qj][4], acc[qj][5], acc[qj][6], acc[qj][7]);
    }
    __syncthreads();

    // ---- PV GEMM: O[4q][4d] per thread; P hoisted as float4 ----
    float o[4][4];
#pragma unroll
    for (int qj = 0; qj < 4; qj++)
#pragma unroll
        for (int dj = 0; dj < 4; dj++) o[qj][dj] = 0.f;

#pragma unroll 2
    for (int n4 = 0; n4 < 128; n4 += 4) {
        float4 p4[4];
#pragma unroll
        for (int qj = 0; qj < 4; qj++)
            p4[qj] = *(const float4*)(Ps + (ty * 4 + qj) * AK_S + n4);
#pragma unroll
        for (int nn = 0; nn < 4; nn++) {
            float4 vv = *(const float4*)(Vs + (n4 + nn) * AV_S + tx * 4);
            const float vs[4] = {vv.x, vv.y, vv.z, vv.w};
#pragma unroll
            for (int qj = 0; qj < 4; qj++) {
                const float p = (&p4[qj].x)[nn];
#pragma unroll
                for (int dj = 0; dj < 4; dj++)
                    o[qj][dj] = fmaf(p, vs[dj], o[qj][dj]);
            }
        }
    }

    // ---- Epilogue: write single fp16 ----
#pragma unroll
    for (int qj = 0; qj < 4; qj++) {
        const int i = t * 64 + ty * 4 + qj;
        const size_t rb = ((size_t)b * SEQ + i) * DIM + h * HD + tx * 4;
        union { __half v[4]; uint2 u; } Hh;
#pragma unroll
        for (int dj = 0; dj < 4; dj++) Hh.v[dj] = __float2half(o[qj][dj]);
        *(uint2*)(g_att1 + rb) = Hh.u;
    }
}

// ---------------------------------------------------------------------------
extern "C" void kernel_launch(void* const* d_in, const int* in_sizes, int n_in,
                              void* d_out, int out_size) {
    const float* x    = (const float*)d_in[0];
    const float* Wq   = (const float*)d_in[1];
    const float* Wk   = (const float*)d_in[2];
    const float* Wv   = (const float*)d_in[3];
    const float* Wo   = (const float*)d_in[4];
    const float* gsep = (const float*)d_in[5];
    const float* galn = (const float*)d_in[6];
    const float* gcoh = (const float*)d_in[7];
    float* out = (float*)d_out;

    cudaFuncSetAttribute(qkv_mma_kernel,
                         cudaFuncAttributeMaxDynamicSharedMemorySize, GEMM_SMEM);
    cudaFuncSetAttribute(out_mma_kernel,
                         cudaFuncAttributeMaxDynamicSharedMemorySize, GEMM_SMEM);
    cudaFuncSetAttribute(attn_kernel,
                         cudaFuncAttributeMaxDynamicSharedMemorySize, ATTN_SMEM);

    convert_kernel<<<8192, 256>>>(x, Wq, Wk, Wv, Wo);

    dim3 gqkv(DIM / TN, MTOT / TM, 3);
    qkv_mma_kernel<<<gqkv, 256, GEMM_SMEM>>>();

    kmean_kernel<<<BATCH * HEADS, 256>>>();

    dim3 gatt(SEQ / 64, BATCH * HEADS);
    attn_kernel<<<gatt, 256, ATTN_SMEM>>>(gsep, galn, gcoh);

    dim3 gout(DIM / TN, MTOT / TM);
    out_mma_kernel<<<gout, 256, GEMM_SMEM>>>(out);
}

// round 15
// speedup vs baseline: 7.4116x; 1.2310x over previous
#include <cuda_runtime.h>
#include <cuda_fp16.h>
#include <math.h>
#include <stdint.h>

// Problem constants
#define BATCH 2
#define SEQ   2048
#define DIM   1024
#define HEADS 16
#define HD    64
#define MTOT  (BATCH*SEQ)      // 4096

// GEMM tiling: plain fp16 GEMM, K = 1024.
#define TM 128
#define TN 128
#define BK 32
#define NCHUNK (DIM/BK)        // 32
#define STAGES 4
#define RS (BK+8)              // 40 elems = 80 B row stride (conflict-free)
#define STAGE_ELEMS (2*128*RS)
#define STAGE_BYTES (STAGE_ELEMS*2)        // 20480
#define GEMM_SMEM (STAGES*STAGE_BYTES)     // 81920 B -> 2 CTAs/SM

// Scratch (device globals; allocation-free contract)
__device__ __align__(256) __half g_qh[(size_t)MTOT*DIM];
__device__ __align__(256) __half g_kh[(size_t)MTOT*DIM];
__device__ __align__(256) __half g_vh[(size_t)MTOT*DIM];
__device__ __align__(256) float g_kmean[BATCH*HEADS*HD];
__device__ __align__(256) __half g_x1[(size_t)MTOT*DIM];
__device__ __align__(256) __half g_att1[(size_t)MTOT*DIM];
__device__ __align__(256) __half g_wq1[(size_t)DIM*DIM];
__device__ __align__(256) __half g_wk1[(size_t)DIM*DIM];
__device__ __align__(256) __half g_wv1[(size_t)DIM*DIM];
__device__ __align__(256) __half g_wo1[(size_t)DIM*DIM];

// ---------------------------------------------------------------------------
// Non-arch-variant PTX helpers (compute_103-safe)
// ---------------------------------------------------------------------------
__device__ __forceinline__ uint32_t smem_u32(const void* p) {
    uint32_t a;
    asm("{ .reg .u64 t; cvta.to.shared.u64 t, %1; cvt.u32.u64 %0, t; }"
        : "=r"(a) : "l"(p));
    return a;
}
__device__ __forceinline__ void cp16(uint32_t dst, const void* src) {
    asm volatile("cp.async.cg.shared.global [%0], [%1], 16;"
                 :: "r"(dst), "l"(src));
}
#define CP_COMMIT() asm volatile("cp.async.commit_group;" ::: "memory")
#define CP_WAIT2()  asm volatile("cp.async.wait_group 2;" ::: "memory")

__device__ __forceinline__ void ldsm4(uint32_t* d, uint32_t addr) {
    asm volatile("ldmatrix.sync.aligned.m8n8.x4.shared.b16 {%0,%1,%2,%3}, [%4];"
                 : "=r"(d[0]), "=r"(d[1]), "=r"(d[2]), "=r"(d[3]) : "r"(addr));
}

__device__ __forceinline__ void mma_f16(float* c, const uint32_t* a,
                                        const uint32_t* b) {
    asm volatile(
        "mma.sync.aligned.m16n8k16.row.col.f32.f16.f16.f32 "
        "{%0,%1,%2,%3}, {%4,%5,%6,%7}, {%8,%9}, {%0,%1,%2,%3};"
        : "+f"(c[0]), "+f"(c[1]), "+f"(c[2]), "+f"(c[3])
        : "r"(a[0]), "r"(a[1]), "r"(a[2]), "r"(a[3]), "r"(b[0]), "r"(b[1]));
}

__device__ __forceinline__ float4 h4_to_f4(uint2 u) {
    __half2 h0 = *(__half2*)&u.x, h1 = *(__half2*)&u.y;
    float2 f0 = __half22float2(h0), f1 = __half22float2(h1);
    return make_float4(f0.x, f0.y, f1.x, f1.y);
}
__device__ __forceinline__ uint32_t f22h2(float a, float b) {
    __half2 h = __floats2half2_rn(a, b);
    return *(uint32_t*)&h;
}

// ---------------------------------------------------------------------------
// fp16 conversion (no split).
// ---------------------------------------------------------------------------
__global__ __launch_bounds__(256)
void convert_kernel(const float* __restrict__ x,  const float* __restrict__ wq,
                    const float* __restrict__ wk, const float* __restrict__ wv,
                    const float* __restrict__ wo) {
    int rid = blockIdx.x;
    const float* src; __half* dst; int row;
    if      (rid < 4096) { src = x;  dst = g_x1;  row = rid;        }
    else if (rid < 5120) { src = wq; dst = g_wq1; row = rid - 4096; }
    else if (rid < 6144) { src = wk; dst = g_wk1; row = rid - 5120; }
    else if (rid < 7168) { src = wv; dst = g_wv1; row = rid - 6144; }
    else                 { src = wo; dst = g_wo1; row = rid - 7168; }
    int c = threadIdx.x * 4;
    float4 f = *(const float4*)(src + (size_t)row * DIM + c);
    union { __half b[4]; uint2 u; } H;
    H.b[0] = __float2half(f.x); H.b[1] = __float2half(f.y);
    H.b[2] = __float2half(f.z); H.b[3] = __float2half(f.w);
    *(uint2*)(dst + (size_t)row * DIM + c) = H.u;
}

// ---------------------------------------------------------------------------
// Plain fp16 HMMA GEMM: C[4096,1024] = A[4096,1024] @ B[1024,1024]^T (f32 acc)
// ---------------------------------------------------------------------------
__device__ __forceinline__ void load_stage(uint32_t stg,
                                           const __half* __restrict__ Ag,
                                           const __half* __restrict__ Bg,
                                           int chunk, int tid) {
    const __half* Ac = Ag + chunk * BK;
    const __half* Bc = Bg + chunk * BK;
#pragma unroll
    for (int i = 0; i < 2; i++) {
        int seg = tid + 256 * i;
        int r = seg >> 2, cs = seg & 3;
        cp16(stg + r * (RS*2) + cs * 16,
             (const char*)(Ac + (size_t)r * DIM) + cs * 16);
    }
#pragma unroll
    for (int i = 0; i < 2; i++) {
        int seg = tid + 256 * i;
        int r = seg >> 2, cs = seg & 3;
        cp16(stg + 128*(RS*2) + r * (RS*2) + cs * 16,
             (const char*)(Bc + (size_t)r * DIM) + cs * 16);
    }
}

template <typename OutT>
__device__ __forceinline__ void mma_gemm(const __half* __restrict__ A1,
                                         const __half* __restrict__ B1,
                                         OutT* __restrict__ C) {
    extern __shared__ __align__(128) __half smem[];
    const uint32_t sb = smem_u32(smem);
    const int tid = threadIdx.x;
    const int lane = tid & 31, w = tid >> 5;
    const int wm = w >> 2, wn = w & 3;        // 2 x 4 warp grid
    const int g = lane >> 2, tg = lane & 3;   // epilogue mapping
    const int rowC = blockIdx.y * TM;
    const int colC = blockIdx.x * TN;
    const __half* Ag = A1 + (size_t)rowC * DIM;
    const __half* Bg = B1 + (size_t)colC * DIM;

    const int arow = wm * 64 + (lane & 15);
    const int acol = (lane >> 4) * 8;
    uint32_t a_rel[4];
#pragma unroll
    for (int mt = 0; mt < 4; mt++)
        a_rel[mt] = (uint32_t)(((arow + mt * 16) * RS + acol) * 2);
    const int brow = wn * 32 + (lane & 7) + ((lane >> 4) << 3);
    const int bcol = ((lane >> 3) & 1) * 8;
    uint32_t b_rel[2];
#pragma unroll
    for (int p = 0; p < 2; p++)
        b_rel[p] = (uint32_t)(((128 + brow + p * 16) * RS + bcol) * 2);

    float acc[4][4][4];
#pragma unroll
    for (int mt = 0; mt < 4; mt++)
#pragma unroll
        for (int nt = 0; nt < 4; nt++)
#pragma unroll
            for (int i = 0; i < 4; i++) acc[mt][nt][i] = 0.f;

#pragma unroll
    for (int s = 0; s < STAGES - 1; s++) {
        load_stage(sb + s * STAGE_BYTES, Ag, Bg, s, tid);
        CP_COMMIT();
    }

    for (int c = 0; c < NCHUNK; c++) {
        CP_WAIT2();
        __syncthreads();
        const uint32_t stg = sb + (uint32_t)(c & 3) * STAGE_BYTES;

        if (c + (STAGES - 1) < NCHUNK)
            load_stage(sb + (uint32_t)((c + STAGES - 1) & 3) * STAGE_BYTES,
                       Ag, Bg, c + STAGES - 1, tid);
        CP_COMMIT();

#pragma unroll
        for (int ks = 0; ks < 2; ks++) {
            const uint32_t ko = (uint32_t)(ks * 16 * 2);
            uint32_t a[4][4], b[2][4];
#pragma unroll
            for (int mt = 0; mt < 4; mt++) ldsm4(a[mt], stg + a_rel[mt] + ko);
#pragma unroll
            for (int p = 0; p < 2; p++)    ldsm4(b[p],  stg + b_rel[p] + ko);
#pragma unroll
            for (int mt = 0; mt < 4; mt++)
#pragma unroll
                for (int nt = 0; nt < 4; nt++)
                    mma_f16(acc[mt][nt], a[mt], &b[nt >> 1][(nt & 1) * 2]);
        }
    }

#pragma unroll
    for (int mt = 0; mt < 4; mt++) {
        const int row = rowC + wm * 64 + mt * 16 + g;
#pragma unroll
        for (int nt = 0; nt < 4; nt++) {
            const int col = colC + wn * 32 + nt * 8 + tg * 2;
            if constexpr (sizeof(OutT) == 4) {
                *(float2*)((float*)C + (size_t)row * DIM + col) =
                    make_float2(acc[mt][nt][0], acc[mt][nt][1]);
                *(float2*)((float*)C + (size_t)(row + 8) * DIM + col) =
                    make_float2(acc[mt][nt][2], acc[mt][nt][3]);
            } else {
                __half2 h0 = __floats2half2_rn(acc[mt][nt][0], acc[mt][nt][1]);
                __half2 h1 = __floats2half2_rn(acc[mt][nt][2], acc[mt][nt][3]);
                *(__half2*)((__half*)C + (size_t)row * DIM + col) = h0;
                *(__half2*)((__half*)C + (size_t)(row + 8) * DIM + col) = h1;
            }
        }
    }
}

__global__ __launch_bounds__(256, 2)
void qkv_mma_kernel() {
    const __half* W = (blockIdx.z == 0) ? g_wq1
                    : (blockIdx.z == 1) ? g_wk1 : g_wv1;
    __half* C = (blockIdx.z == 0) ? g_qh : (blockIdx.z == 1) ? g_kh : g_vh;
    mma_gemm<__half>(g_x1, W, C);
}

__global__ __launch_bounds__(256, 2)
void out_mma_kernel(float* __restrict__ out) {
    mma_gemm<float>(g_att1, g_wo1, out);
}

// ---------------------------------------------------------------------------
// k_mean[b,h,d] = mean_l k[b,h,l,d]   (fp16 k input)
// ---------------------------------------------------------------------------
__global__ __launch_bounds__(256)
void kmean_kernel() {
    __shared__ float red[256];
    const int bh = blockIdx.x;
    const int b = bh >> 4, h = bh & 15;
    const int d = threadIdx.x & 63, p = threadIdx.x >> 6;
    const __half* base = g_kh + (size_t)b * SEQ * DIM + h * HD + d;
    float s = 0.f;
    for (int l = p; l < SEQ; l += 4) s += __half2float(base[(size_t)l * DIM]);
    red[threadIdx.x] = s;
    __syncthreads();
    if (threadIdx.x < 64) {
        float t = red[d] + red[64 + d] + red[128 + d] + red[192 + d];
        g_kmean[bh * HD + d] = t * (1.f / (float)SEQ);
    }
}

// ---------------------------------------------------------------------------
// Fused windowed attention v3b: HMMA for S=QK^T and O=PV, with CORRECT
// cross-warp (wn pair) softmax combination via smem row stats.
// 8 warps: 4(m) x 2(n). Warp: S m16 x n64 x k64; PV m16 x d64 x k64(+reduce).
// ---------------------------------------------------------------------------
#define QH_S 72    // halves; 144 B rows (16B-aligned, conflict-free ldsm)
#define KH_S 72
#define VT_S 136   // Vt[d][seq], 272 B rows
#define OR_S 68    // f32 partial-O buffer stride
// bytes: Qh 9216 + Kh 18432 + Vt 17408 + Ored 17408 + pm 256 + rstat 1024
#define ATTN_SMEM (64*QH_S*2 + 128*KH_S*2 + 64*VT_S*2 + 64*OR_S*4 + 64*4 + 256*4)

__global__ void __launch_bounds__(256, 2)
attn_kernel(const float* __restrict__ gsep,
            const float* __restrict__ galign,
            const float* __restrict__ gcoh) {
    extern __shared__ __align__(128) char asm_[];
    __half* Qh = (__half*)asm_;                 // [64][QH_S]
    __half* Kh = Qh + 64 * QH_S;                // [128][KH_S]
    __half* Vt = Kh + 128 * KH_S;               // [64 d][VT_S seq]
    float*  Ored = (float*)(Vt + 64 * VT_S);    // [64][OR_S]
    float*  pm = Ored + 64 * OR_S;              // [64], pre-scaled by 1/8
    float*  rmx = pm + 64;                      // [2][64] local row max
    float*  rsum = rmx + 128;                   // [2][64] local row sum

    const int t  = blockIdx.x;
    const int bh = blockIdx.y;
    const int b  = bh >> 4, h = bh & 15;
    const int tid = threadIdx.x;
    const int lane = tid & 31, w = tid >> 5;
    const int wm = w >> 1, wn = w & 1;          // 4 x 2 warp grid
    const int g = lane >> 2, tg = lane & 3;
    const int base = t * 64 - 64;

    const __half* Kg = g_kh + (size_t)b * SEQ * DIM + h * HD;
    const __half* Vg = g_vh + (size_t)b * SEQ * DIM + h * HD;
    const __half* Qg = g_qh + (size_t)b * SEQ * DIM + h * HD;

    // Stage Q: 64 rows x 16 uint2 = 1024, 4 per thread
#pragma unroll
    for (int it = 0; it < 4; it++) {
        int idx = tid + 256 * it;
        int r = idx >> 4, c4 = (idx & 15) * 4;
        *(uint2*)(Qh + r * QH_S + c4) =
            *(const uint2*)(Qg + (size_t)(t * 64 + r) * DIM + c4);
    }
    // Stage K: 128 rows x 16 uint2 = 2048, 8 per thread
#pragma unroll
    for (int it = 0; it < 8; it++) {
        int idx = tid + 256 * it;
        int r = idx >> 4, c4 = (idx & 15) * 4;
        int j = base + r;
        uint2 u = make_uint2(0u, 0u);
        if (j >= 0) u = *(const uint2*)(Kg + (size_t)j * DIM + c4);
        *(uint2*)(Kh + r * KH_S + c4) = u;
    }
    // Stage V transposed: Vt[d][n]
#pragma unroll
    for (int it = 0; it < 8; it++) {
        int idx = tid + 256 * it;
        int n = idx & 127, d0 = (idx >> 7) * 4;
        int j = base + n;
        union { uint2 u; __half v[4]; } V;
        V.u = make_uint2(0u, 0u);
        if (j >= 0) V.u = *(const uint2*)(Vg + (size_t)j * DIM + d0);
        Vt[(d0 + 0) * VT_S + n] = V.v[0];
        Vt[(d0 + 1) * VT_S + n] = V.v[1];
        Vt[(d0 + 2) * VT_S + n] = V.v[2];
        Vt[(d0 + 3) * VT_S + n] = V.v[3];
    }
    __syncthreads();

    // pm[qi] = (q . k_mean) / 8
    if (tid < 64) {
        const float* kmg = g_kmean + bh * HD;
        float s = 0.f;
#pragma unroll
        for (int d4 = 0; d4 < 64; d4 += 4) {
            float4 kk = *(const float4*)(kmg + d4);
            float4 qf = h4_to_f4(*(uint2*)(Qh + tid * QH_S + d4));
            s += qf.x * kk.x + qf.y * kk.y + qf.z * kk.z + qf.w * kk.w;
        }
        pm[tid] = s * 0.125f;
    }

    const uint32_t QhA = smem_u32(Qh), KhA = smem_u32(Kh), VtA = smem_u32(Vt);

    const uint32_t a_rel = (uint32_t)(((wm * 16 + (lane & 15)) * QH_S
                                       + (lane >> 4) * 8) * 2);
    const int brow = (lane & 7) + ((lane >> 4) << 3);
    const int bcol = ((lane >> 3) & 1) * 8;
    uint32_t bS_rel[4], bV_rel[4];
#pragma unroll
    for (int p = 0; p < 4; p++) {
        bS_rel[p] = (uint32_t)(((wn * 64 + p * 16 + brow) * KH_S + bcol) * 2);
        bV_rel[p] = (uint32_t)(((p * 16 + brow) * VT_S + bcol) * 2);
    }

    __syncthreads();

    // ---- S = Q K^T : per warp m16 x n64, k=64 ----
    float acc[8][4];
#pragma unroll
    for (int nt = 0; nt < 8; nt++)
#pragma unroll
        for (int i = 0; i < 4; i++) acc[nt][i] = 0.f;

#pragma unroll
    for (int ks = 0; ks < 4; ks++) {
        uint32_t a[4], bf[4][4];
        ldsm4(a, QhA + a_rel + ks * 32);
#pragma unroll
        for (int p = 0; p < 4; p++) ldsm4(bf[p], KhA + bS_rel[p] + ks * 32);
#pragma unroll
        for (int nt = 0; nt < 8; nt++)
            mma_f16(acc[nt], a, &bf[nt >> 1][(nt & 1) * 2]);
    }

    // ---- Reynolds + mask + local softmax stats (per wn half-row) ----
    const float sep = *gsep, alg = *galign, coh = *gcoh;
    float lmx[2], lsum[2];
#pragma unroll
    for (int rh = 0; rh < 2; rh++) {
        const int qi = wm * 16 + g + rh * 8;
        const float mi = pm[qi];
        float mx = -1e30f;
#pragma unroll
        for (int nt = 0; nt < 8; nt++)
#pragma unroll
            for (int j = 0; j < 2; j++) {
                const float s = acc[nt][rh * 2 + j] * 0.125f;
                const int n = wn * 64 + nt * 8 + tg * 2 + j;
                const float sim = 1.f / (1.f + __expf(-s));
                const float v = s + alg * s - sep * sim * sim
                                - coh * fabsf(s - mi);
                const bool ok = (n >= qi + 1) && (n <= qi + 64)
                                && (base + n >= 0);
                acc[nt][rh * 2 + j] = ok ? v : -1e30f;
                mx = fmaxf(mx, acc[nt][rh * 2 + j]);
            }
        mx = fmaxf(mx, __shfl_xor_sync(0xffffffffu, mx, 1));
        mx = fmaxf(mx, __shfl_xor_sync(0xffffffffu, mx, 2));
        float sum = 0.f;
#pragma unroll
        for (int nt = 0; nt < 8; nt++)
#pragma unroll
            for (int j = 0; j < 2; j++) {
                float& e = acc[nt][rh * 2 + j];
                e = (e > -1e29f) ? __expf(e - mx) : 0.f;
                sum += e;
            }
        sum += __shfl_xor_sync(0xffffffffu, sum, 1);
        sum += __shfl_xor_sync(0xffffffffu, sum, 2);
        lmx[rh] = mx;
        lsum[rh] = sum;
        if (tg == 0) { rmx[wn * 64 + qi] = mx; rsum[wn * 64 + qi] = sum; }
    }
    __syncthreads();

    // ---- Combine with partner warp's stats; finish normalization ----
#pragma unroll
    for (int rh = 0; rh < 2; rh++) {
        const int qi = wm * 16 + g + rh * 8;
        const float omx = rmx[(1 - wn) * 64 + qi];
        const float osum = rsum[(1 - wn) * 64 + qi];
        const float gm = fmaxf(lmx[rh], omx);
        const float msc = __expf(lmx[rh] - gm);
        const float total = lsum[rh] * msc + osum * __expf(omx - gm);
        const float inv = msc / total;
#pragma unroll
        for (int nt = 0; nt < 8; nt++)
#pragma unroll
            for (int j = 0; j < 2; j++) acc[nt][rh * 2 + j] *= inv;
    }

    // ---- O_partial = P V : per warp m16 x d64 over its k=64 seq slice ----
    float o2[8][4];
#pragma unroll
    for (int dt = 0; dt < 8; dt++)
#pragma unroll
        for (int i = 0; i < 4; i++) o2[dt][i] = 0.f;

#pragma unroll
    for (int ks = 0; ks < 4; ks++) {
        const int t0 = ks * 2, t1 = ks * 2 + 1;
        uint32_t a[4];
        a[0] = f22h2(acc[t0][0], acc[t0][1]);
        a[1] = f22h2(acc[t0][2], acc[t0][3]);
        a[2] = f22h2(acc[t1][0], acc[t1][1]);
        a[3] = f22h2(acc[t1][2], acc[t1][3]);
        uint32_t bf[4][4];
        const uint32_t ko = (uint32_t)((wn * 64 + ks * 16) * 2);
#pragma unroll
        for (int p = 0; p < 4; p++) ldsm4(bf[p], VtA + bV_rel[p] + ko);
#pragma unroll
        for (int dt = 0; dt < 8; dt++)
            mma_f16(o2[dt], a, &bf[dt >> 1][(dt & 1) * 2]);
    }

    // ---- Reduce partials across wn and write fp16 output ----
    if (wn == 1) {
#pragma unroll
        for (int dt = 0; dt < 8; dt++) {
            *(float2*)(Ored + (wm * 16 + g) * OR_S + dt * 8 + tg * 2) =
                make_float2(o2[dt][0], o2[dt][1]);
            *(float2*)(Ored + (wm * 16 + g + 8) * OR_S + dt * 8 + tg * 2) =
                make_float2(o2[dt][2], o2[dt][3]);
        }
    }
    __syncthreads();
    if (wn == 0) {
        const int i0 = t * 64 + wm * 16 + g;
#pragma unroll
        for (int dt = 0; dt < 8; dt++) {
            float2 r0 = *(float2*)(Ored + (wm * 16 + g) * OR_S + dt * 8 + tg * 2);
            float2 r1 = *(float2*)(Ored + (wm * 16 + g + 8) * OR_S + dt * 8 + tg * 2);
            __half2 h0 = __floats2half2_rn(o2[dt][0] + r0.x, o2[dt][1] + r0.y);
            __half2 h1 = __floats2half2_rn(o2[dt][2] + r1.x, o2[dt][3] + r1.y);
            *(__half2*)(g_att1 + ((size_t)b * SEQ + i0) * DIM
                        + h * HD + dt * 8 + tg * 2) = h0;
            *(__half2*)(g_att1 + ((size_t)b * SEQ + i0 + 8) * DIM
                        + h * HD + dt * 8 + tg * 2) = h1;
        }
    }
}

// ---------------------------------------------------------------------------
extern "C" void kernel_launch(void* const* d_in, const int* in_sizes, int n_in,
                              void* d_out, int out_size) {
    const float* x    = (const float*)d_in[0];
    const float* Wq   = (const float*)d_in[1];
    const float* Wk   = (const float*)d_in[2];
    const float* Wv   = (const float*)d_in[3];
    const float* Wo   = (const float*)d_in[4];
    const float* gsep = (const float*)d_in[5];
    const float* galn = (const float*)d_in[6];
    const float* gcoh = (const float*)d_in[7];
    float* out = (float*)d_out;

    cudaFuncSetAttribute(qkv_mma_kernel,
                         cudaFuncAttributeMaxDynamicSharedMemorySize, GEMM_SMEM);
    cudaFuncSetAttribute(out_mma_kernel,
                         cudaFuncAttributeMaxDynamicSharedMemorySize, GEMM_SMEM);
    cudaFuncSetAttribute(attn_kernel,
                         cudaFuncAttributeMaxDynamicSharedMemorySize, ATTN_SMEM);

    convert_kernel<<<8192, 256>>>(x, Wq, Wk, Wv, Wo);

    dim3 gqkv(DIM / TN, MTOT / TM, 3);
    qkv_mma_kernel<<<gqkv, 256, GEMM_SMEM>>>();

    kmean_kernel<<<BATCH * HEADS, 256>>>();

    dim3 gatt(SEQ / 64, BATCH * HEADS);
    attn_kernel<<<gatt, 256, ATTN_SMEM>>>(gsep, galn, gcoh);

    dim3 gout(DIM / TN, MTOT / TM);
    out_mma_kernel<<<gout, 256, GEMM_SMEM>>>(out);
}